// round 2
// baseline (speedup 1.0000x reference)
#include <cuda_runtime.h>
#include <cuda_bf16.h>
#include <mma.h>
#include <cstdint>

using namespace nvcuda;

// Problem constants
constexpr int Bc  = 4;
constexpr int Nn  = 2048;
constexpr int Kc  = 48;
constexpr int Hc  = 128;
constexpr int CEc = 128;
constexpr int HCc = 256;   // H + CE
constexpr int FFc = 512;
constexpr float INV_SCALE = 1.0f / 30.0f;

// ---------------------------------------------------------------------------
// Device-global scratch (no cudaMalloc allowed)
// ---------------------------------------------------------------------------
__device__ __nv_bfloat16 g_W1bf[HCc * Hc];
__device__ __nv_bfloat16 g_W2bf[Hc * Hc];
__device__ __nv_bfloat16 g_W3bf[Hc * Hc];
__device__ __nv_bfloat16 g_WinHi[Hc * FFc];
__device__ __nv_bfloat16 g_WinLo[Hc * FFc];
__device__ __nv_bfloat16 g_WoutHi[FFc * Hc];
__device__ __nv_bfloat16 g_WoutLo[FFc * Hc];
__device__ float         g_h[Bc * Nn * Hc];   // h_V + dh (pre-FF)

// ---------------------------------------------------------------------------
// Helpers
// ---------------------------------------------------------------------------
__device__ __forceinline__ float gelu_tanh_f(float x) {
    float x3 = x * x * x;
    return 0.5f * x * (1.0f + tanhf(0.7978845608028654f * (x + 0.044715f * x3)));
}
__device__ __forceinline__ float gelu_erf_f(float x) {
    return x * normcdff(x);   // exact gelu: x * Phi(x)
}

using FragA = wmma::fragment<wmma::matrix_a, 16, 16, 16, __nv_bfloat16, wmma::row_major>;
using FragB = wmma::fragment<wmma::matrix_b, 16, 16, 16, __nv_bfloat16, wmma::row_major>;
using FragC = wmma::fragment<wmma::accumulator, 16, 16, 16, float>;

// ---------------------------------------------------------------------------
// Weight conversion / split kernel (runs every launch; deterministic)
// ---------------------------------------------------------------------------
__global__ void prep_kernel(const float* __restrict__ W1, const float* __restrict__ W2,
                            const float* __restrict__ W3, const float* __restrict__ Win,
                            const float* __restrict__ Wout) {
    int i = blockIdx.x * blockDim.x + threadIdx.x;   // 0..65535
    if (i < HCc * Hc) g_W1bf[i] = __float2bfloat16(W1[i]);
    if (i < Hc * Hc) {
        g_W2bf[i] = __float2bfloat16(W2[i]);
        g_W3bf[i] = __float2bfloat16(W3[i]);
    }
    if (i < Hc * FFc) {
        float v = Win[i];
        __nv_bfloat16 hi = __float2bfloat16(v);
        g_WinHi[i] = hi;
        g_WinLo[i] = __float2bfloat16(v - __bfloat162float(hi));
        v = Wout[i];
        hi = __float2bfloat16(v);
        g_WoutHi[i] = hi;
        g_WoutLo[i] = __float2bfloat16(v - __bfloat162float(hi));
    }
}

// ---------------------------------------------------------------------------
// Edge-MLP kernel: persistent, 2 nodes (96 edge rows) per tile iteration.
// smem layout (bytes):
// ---------------------------------------------------------------------------
constexpr int OFF_W1  = 0;                         // 256*136*2 = 69632
constexpr int OFF_W2  = OFF_W1 + 69632;            // 128*136*2 = 34816
constexpr int OFF_W3  = OFF_W2 + 34816;            // 34816
constexpr int OFF_A   = OFF_W3 + 34816;            // 96*264*2  = 50688 (also reused as M2)
constexpr int OFF_M1  = OFF_A + 50688;             // 96*136*2  = 26112
constexpr int OFF_SCR = OFF_M1 + 26112;            // 8*16*24*4 = 12288
constexpr int OFF_B1  = OFF_SCR + 12288;           // 512
constexpr int OFF_B2  = OFF_B1 + 512;              // 512
constexpr int OFF_B3  = OFF_B2 + 512;              // 512
constexpr int OFF_IDX = OFF_B3 + 512;              // 96*4 = 384
constexpr int OFF_MSK = OFF_IDX + 384;             // 384
constexpr int OFF_DH  = OFF_MSK + 384;             // 256*4 = 1024
constexpr int EDGE_SMEM = OFF_DH + 1024;           // 231680 bytes

// Generic layer: D[96x128] = act(A[96 x 16*ksteps] @ W + bias), bf16 out.
__device__ __forceinline__ void mlp_layer(const __nv_bfloat16* __restrict__ A, int lda,
                                          const __nv_bfloat16* __restrict__ W,
                                          const float* __restrict__ bias,
                                          __nv_bfloat16* __restrict__ D,
                                          float* scr, int ksteps, int warp, int lane) {
    const int ct = warp;           // 8 warps <-> 8 column tiles
    for (int rt = 0; rt < 6; rt += 2) {
        FragC acc0, acc1;
        wmma::fill_fragment(acc0, 0.0f);
        wmma::fill_fragment(acc1, 0.0f);
        for (int k = 0; k < ksteps; ++k) {
            FragB fb;
            FragA fa0, fa1;
            wmma::load_matrix_sync(fb, W + (k * 16) * 136 + ct * 16, 136);
            wmma::load_matrix_sync(fa0, A + (rt * 16) * lda + k * 16, lda);
            wmma::load_matrix_sync(fa1, A + ((rt + 1) * 16) * lda + k * 16, lda);
            wmma::mma_sync(acc0, fa0, fb, acc0);
            wmma::mma_sync(acc1, fa1, fb, acc1);
        }
        auto epi = [&](const FragC& acc, int rbase) {
            wmma::store_matrix_sync(scr, acc, 24, wmma::mem_row_major);
            __syncwarp();
#pragma unroll
            for (int i = 0; i < 8; ++i) {
                int e = lane + 32 * i;
                int r = e >> 4, c = e & 15;
                float v = scr[r * 24 + c] + bias[ct * 16 + c];
                v = gelu_tanh_f(v);
                D[(rbase + r) * 136 + ct * 16 + c] = __float2bfloat16(v);
            }
            __syncwarp();
        };
        epi(acc0, rt * 16);
        epi(acc1, (rt + 1) * 16);
    }
}

__global__ __launch_bounds__(256, 1)
void edge_mlp_kernel(const float* __restrict__ hV, const float* __restrict__ hE,
                     const int* __restrict__ eidx, const float* __restrict__ mAtt,
                     const float* __restrict__ b1, const float* __restrict__ b2,
                     const float* __restrict__ b3) {
    extern __shared__ __align__(16) char sm[];
    __nv_bfloat16* W1s  = reinterpret_cast<__nv_bfloat16*>(sm + OFF_W1);
    __nv_bfloat16* W2s  = reinterpret_cast<__nv_bfloat16*>(sm + OFF_W2);
    __nv_bfloat16* W3s  = reinterpret_cast<__nv_bfloat16*>(sm + OFF_W3);
    __nv_bfloat16* Abuf = reinterpret_cast<__nv_bfloat16*>(sm + OFF_A);   // stride 264 as A, 136 as M2
    __nv_bfloat16* M1   = reinterpret_cast<__nv_bfloat16*>(sm + OFF_M1);
    float* scrb   = reinterpret_cast<float*>(sm + OFF_SCR);
    float* b1s    = reinterpret_cast<float*>(sm + OFF_B1);
    float* b2s    = reinterpret_cast<float*>(sm + OFF_B2);
    float* b3s    = reinterpret_cast<float*>(sm + OFF_B3);
    int*   idx_s  = reinterpret_cast<int*>(sm + OFF_IDX);
    float* mask_s = reinterpret_cast<float*>(sm + OFF_MSK);
    float* dh_s   = reinterpret_cast<float*>(sm + OFF_DH);

    const int tid = threadIdx.x;
    const int warp = tid >> 5;
    const int lane = tid & 31;
    float* scr = scrb + warp * (16 * 24);

    // Load weights once per block (L2 -> smem, padded stride 136)
    for (int i = tid; i < HCc * Hc; i += 256)
        W1s[(i >> 7) * 136 + (i & 127)] = g_W1bf[i];
    for (int i = tid; i < Hc * Hc; i += 256) {
        int r = i >> 7, c = i & 127;
        W2s[r * 136 + c] = g_W2bf[i];
        W3s[r * 136 + c] = g_W3bf[i];
    }
    if (tid < Hc) { b1s[tid] = b1[tid]; b2s[tid] = b2[tid]; b3s[tid] = b3[tid]; }

    const int n_tiles = (Bc * Nn) / 2;   // 4096
    for (int t = blockIdx.x; t < n_tiles; t += gridDim.x) {
        __syncthreads();   // protect smem reuse across iterations
        const int node0 = t * 2;          // global node index of first node
        const int b = node0 >> 11;        // node0 / 2048

        if (tid < 96) {
            int rr = tid;
            int nl = (rr >= Kc) ? 1 : 0;
            int kk = rr - nl * Kc;
            int gn = node0 + nl;
            idx_s[rr]  = eidx[gn * Kc + kk];
            mask_s[rr] = mAtt[gn * Kc + kk];
        }
        dh_s[tid] = 0.0f;   // 256 entries, 256 threads
        __syncthreads();

        // Gather + concat + convert to bf16: A[96 x 256], stride 264
        for (int e = tid; e < 96 * 64; e += 256) {
            int row = e >> 6;
            int q = e & 63;
            float4 v;
            if (q < 32) {
                int nb = idx_s[row];
                v = reinterpret_cast<const float4*>(hV + (size_t)(b * Nn + nb) * Hc)[q];
            } else {
                int nl = (row >= Kc) ? 1 : 0;
                int kk = row - nl * Kc;
                int gn = node0 + nl;
                v = reinterpret_cast<const float4*>(hE + (size_t)(gn * Kc + kk) * CEc)[q - 32];
            }
            __nv_bfloat162* dst = reinterpret_cast<__nv_bfloat162*>(Abuf + row * 264 + q * 4);
            dst[0] = __floats2bfloat162_rn(v.x, v.y);
            dst[1] = __floats2bfloat162_rn(v.z, v.w);
        }
        __syncthreads();

        // Layer 1: [96x256] @ [256x128] -> M1
        mlp_layer(Abuf, 264, W1s, b1s, M1, scr, 16, warp, lane);
        __syncthreads();

        // Layer 2: M1 @ W2 -> M2 (reuses Abuf region, stride 136)
        __nv_bfloat16* M2 = Abuf;
        mlp_layer(M1, 136, W2s, b2s, M2, scr, 8, warp, lane);
        __syncthreads();

        // Layer 3: M2 @ W3 + b3, mask, column-reduce into dh_s
        {
            const int ct = warp;
            for (int rt = 0; rt < 6; rt += 2) {
                FragC acc0, acc1;
                wmma::fill_fragment(acc0, 0.0f);
                wmma::fill_fragment(acc1, 0.0f);
                for (int k = 0; k < 8; ++k) {
                    FragB fb;
                    FragA fa0, fa1;
                    wmma::load_matrix_sync(fb, W3s + (k * 16) * 136 + ct * 16, 136);
                    wmma::load_matrix_sync(fa0, M2 + (rt * 16) * 136 + k * 16, 136);
                    wmma::load_matrix_sync(fa1, M2 + ((rt + 1) * 16) * 136 + k * 16, 136);
                    wmma::mma_sync(acc0, fa0, fb, acc0);
                    wmma::mma_sync(acc1, fa1, fb, acc1);
                }
                auto epi3 = [&](const FragC& acc, int rbase) {
                    wmma::store_matrix_sync(scr, acc, 24, wmma::mem_row_major);
                    __syncwarp();
                    int node = (rbase >= Kc) ? 1 : 0;
                    float partial = 0.0f;
#pragma unroll
                    for (int i = 0; i < 8; ++i) {
                        int e = lane + 32 * i;
                        int r = e >> 4, c = e & 15;
                        float v = scr[r * 24 + c] + b3s[ct * 16 + c];
                        v *= mask_s[rbase + r];
                        partial += v;
                    }
                    partial += __shfl_xor_sync(0xffffffffu, partial, 16);
                    if (lane < 16)
                        atomicAdd(&dh_s[node * Hc + ct * 16 + (lane & 15)], partial);
                    __syncwarp();
                };
                epi3(acc0, rt * 16);
                epi3(acc1, (rt + 1) * 16);
            }
        }
        __syncthreads();

        // h = h_V + dh/SCALE  -> staging buffer
        {
            int node = tid >> 7, col = tid & 127;
            int gn = node0 + node;
            int gi = gn * Hc + col;
            g_h[gi] = hV[gi] + dh_s[tid] * INV_SCALE;
        }
    }
}

// ---------------------------------------------------------------------------
// FF kernel: 64 nodes per block, split-bf16 (hi+lo) for accuracy.
// ---------------------------------------------------------------------------
constexpr int FOFF_AHI = 0;                    // 64*136*2 = 17408
constexpr int FOFF_ALO = FOFF_AHI + 17408;
constexpr int FOFF_WIH = FOFF_ALO + 17408;     // 128*136*2 = 34816
constexpr int FOFF_WIL = FOFF_WIH + 34816;
constexpr int FOFF_HHI = FOFF_WIL + 34816;     // 17408
constexpr int FOFF_HLO = FOFF_HHI + 17408;
constexpr int FOFF_WOH = FOFF_HLO + 17408;     // 34816
constexpr int FOFF_WOL = FOFF_WOH + 34816;
constexpr int FOFF_SCR = FOFF_WOL + 34816;     // 12288
constexpr int FOFF_BIN = FOFF_SCR + 12288;     // 2048
constexpr int FOFF_BOUT= FOFF_BIN + 2048;      // 512
constexpr int FOFF_MV  = FOFF_BOUT + 512;      // 256
constexpr int FF_SMEM  = FOFF_MV + 256;        // 224000 bytes

__global__ __launch_bounds__(256, 1)
void ff_kernel(const float* __restrict__ maskV, const float* __restrict__ b_in,
               const float* __restrict__ b_out, float* __restrict__ out) {
    extern __shared__ __align__(16) char sm[];
    __nv_bfloat16* Ahi = reinterpret_cast<__nv_bfloat16*>(sm + FOFF_AHI);
    __nv_bfloat16* Alo = reinterpret_cast<__nv_bfloat16*>(sm + FOFF_ALO);
    __nv_bfloat16* WIH = reinterpret_cast<__nv_bfloat16*>(sm + FOFF_WIH);
    __nv_bfloat16* WIL = reinterpret_cast<__nv_bfloat16*>(sm + FOFF_WIL);
    __nv_bfloat16* HHI = reinterpret_cast<__nv_bfloat16*>(sm + FOFF_HHI);
    __nv_bfloat16* HLO = reinterpret_cast<__nv_bfloat16*>(sm + FOFF_HLO);
    __nv_bfloat16* WOH = reinterpret_cast<__nv_bfloat16*>(sm + FOFF_WOH);
    __nv_bfloat16* WOL = reinterpret_cast<__nv_bfloat16*>(sm + FOFF_WOL);
    float* scrb  = reinterpret_cast<float*>(sm + FOFF_SCR);
    float* bins  = reinterpret_cast<float*>(sm + FOFF_BIN);
    float* bouts = reinterpret_cast<float*>(sm + FOFF_BOUT);
    float* mvs   = reinterpret_cast<float*>(sm + FOFF_MV);

    const int tid = threadIdx.x;
    const int warp = tid >> 5;
    const int lane = tid & 31;
    const int rowbase = blockIdx.x * 64;
    float* scr = scrb + warp * (16 * 24);

    for (int i = tid; i < FFc; i += 256) bins[i] = b_in[i];
    if (tid < Hc) bouts[tid] = b_out[tid];
    if (tid < 64) mvs[tid] = maskV[rowbase + tid];

    // Load + split A = g_h rows
    for (int e = tid; e < 64 * 32; e += 256) {
        int r = e >> 5, q = e & 31;
        float4 v = reinterpret_cast<const float4*>(g_h + (size_t)(rowbase + r) * Hc)[q];
        __nv_bfloat16 hx = __float2bfloat16(v.x); float lx = v.x - __bfloat162float(hx);
        __nv_bfloat16 hy = __float2bfloat16(v.y); float ly = v.y - __bfloat162float(hy);
        __nv_bfloat16 hz = __float2bfloat16(v.z); float lz = v.z - __bfloat162float(hz);
        __nv_bfloat16 hw = __float2bfloat16(v.w); float lw = v.w - __bfloat162float(hw);
        __nv_bfloat162* dh_ = reinterpret_cast<__nv_bfloat162*>(Ahi + r * 136 + q * 4);
        dh_[0] = __halves2bfloat162(hx, hy);
        dh_[1] = __halves2bfloat162(hz, hw);
        __nv_bfloat162* dl_ = reinterpret_cast<__nv_bfloat162*>(Alo + r * 136 + q * 4);
        dl_[0] = __floats2bfloat162_rn(lx, ly);
        dl_[1] = __floats2bfloat162_rn(lz, lw);
    }

    FragC accO[4];
#pragma unroll
    for (int j = 0; j < 4; ++j) wmma::fill_fragment(accO[j], 0.0f);

    const int ct = warp;
    for (int cc = 0; cc < 4; ++cc) {      // 4 chunks of 128 over FF=512
        __syncthreads();
        // Load weight chunks
        for (int i = tid; i < Hc * 128; i += 256) {
            int r = i >> 7, c = i & 127;
            WIH[r * 136 + c] = g_WinHi[r * FFc + cc * 128 + c];
            WIL[r * 136 + c] = g_WinLo[r * FFc + cc * 128 + c];
            WOH[r * 136 + c] = g_WoutHi[(cc * 128 + r) * Hc + c];
            WOL[r * 136 + c] = g_WoutLo[(cc * 128 + r) * Hc + c];
        }
        __syncthreads();

        // GEMM1: hidden = gelu_exact(A @ Win_chunk + b_in_chunk), split hi/lo
        for (int rt = 0; rt < 4; rt += 2) {
            FragC acc0, acc1;
            wmma::fill_fragment(acc0, 0.0f);
            wmma::fill_fragment(acc1, 0.0f);
            for (int k = 0; k < 8; ++k) {
                FragB fbh, fbl;
                FragA fah0, fal0, fah1, fal1;
                wmma::load_matrix_sync(fbh, WIH + (k * 16) * 136 + ct * 16, 136);
                wmma::load_matrix_sync(fbl, WIL + (k * 16) * 136 + ct * 16, 136);
                wmma::load_matrix_sync(fah0, Ahi + (rt * 16) * 136 + k * 16, 136);
                wmma::load_matrix_sync(fal0, Alo + (rt * 16) * 136 + k * 16, 136);
                wmma::load_matrix_sync(fah1, Ahi + ((rt + 1) * 16) * 136 + k * 16, 136);
                wmma::load_matrix_sync(fal1, Alo + ((rt + 1) * 16) * 136 + k * 16, 136);
                wmma::mma_sync(acc0, fah0, fbh, acc0);
                wmma::mma_sync(acc0, fah0, fbl, acc0);
                wmma::mma_sync(acc0, fal0, fbh, acc0);
                wmma::mma_sync(acc1, fah1, fbh, acc1);
                wmma::mma_sync(acc1, fah1, fbl, acc1);
                wmma::mma_sync(acc1, fal1, fbh, acc1);
            }
            auto epiH = [&](const FragC& acc, int rbase) {
                wmma::store_matrix_sync(scr, acc, 24, wmma::mem_row_major);
                __syncwarp();
#pragma unroll
                for (int i = 0; i < 8; ++i) {
                    int e = lane + 32 * i;
                    int r = e >> 4, c = e & 15;
                    float v = scr[r * 24 + c] + bins[cc * 128 + ct * 16 + c];
                    v = gelu_erf_f(v);
                    __nv_bfloat16 hi = __float2bfloat16(v);
                    float lo = v - __bfloat162float(hi);
                    HHI[(rbase + r) * 136 + ct * 16 + c] = hi;
                    HLO[(rbase + r) * 136 + ct * 16 + c] = __float2bfloat16(lo);
                }
                __syncwarp();
            };
            epiH(acc0, rt * 16);
            epiH(acc1, (rt + 1) * 16);
        }
        __syncthreads();

        // GEMM2: out += hidden @ Wout_chunk (accumulate in registers across chunks)
#pragma unroll
        for (int rp = 0; rp < 4; rp += 2) {
            for (int k = 0; k < 8; ++k) {
                FragB fbh, fbl;
                FragA fah0, fal0, fah1, fal1;
                wmma::load_matrix_sync(fbh, WOH + (k * 16) * 136 + ct * 16, 136);
                wmma::load_matrix_sync(fbl, WOL + (k * 16) * 136 + ct * 16, 136);
                wmma::load_matrix_sync(fah0, HHI + (rp * 16) * 136 + k * 16, 136);
                wmma::load_matrix_sync(fal0, HLO + (rp * 16) * 136 + k * 16, 136);
                wmma::load_matrix_sync(fah1, HHI + ((rp + 1) * 16) * 136 + k * 16, 136);
                wmma::load_matrix_sync(fal1, HLO + ((rp + 1) * 16) * 136 + k * 16, 136);
                wmma::mma_sync(accO[rp], fah0, fbh, accO[rp]);
                wmma::mma_sync(accO[rp], fah0, fbl, accO[rp]);
                wmma::mma_sync(accO[rp], fal0, fbh, accO[rp]);
                wmma::mma_sync(accO[rp + 1], fah1, fbh, accO[rp + 1]);
                wmma::mma_sync(accO[rp + 1], fah1, fbl, accO[rp + 1]);
                wmma::mma_sync(accO[rp + 1], fal1, fbh, accO[rp + 1]);
            }
        }
    }

    // Final epilogue: out = (h + ff) * mask_V
#pragma unroll
    for (int j = 0; j < 4; ++j) {
        wmma::store_matrix_sync(scr, accO[j], 24, wmma::mem_row_major);
        __syncwarp();
        int rbase = j * 16;
#pragma unroll
        for (int i = 0; i < 8; ++i) {
            int e = lane + 32 * i;
            int r = e >> 4, c = e & 15;
            int rg = rowbase + rbase + r;
            int col = ct * 16 + c;
            float v = scr[r * 24 + c] + bouts[col];
            int gi = rg * Hc + col;
            out[gi] = (g_h[gi] + v) * mvs[rbase + r];
        }
        __syncwarp();
    }
}

// ---------------------------------------------------------------------------
// Launch
// ---------------------------------------------------------------------------
extern "C" void kernel_launch(void* const* d_in, const int* in_sizes, int n_in,
                              void* d_out, int out_size) {
    (void)in_sizes; (void)n_in; (void)out_size;
    const float* hV    = (const float*)d_in[0];
    const float* hE    = (const float*)d_in[1];
    const int*   eidx  = (const int*)d_in[2];
    const float* maskV = (const float*)d_in[3];
    const float* mAtt  = (const float*)d_in[4];
    const float* W1    = (const float*)d_in[5];
    const float* b1    = (const float*)d_in[6];
    const float* W2    = (const float*)d_in[7];
    const float* b2    = (const float*)d_in[8];
    const float* W3    = (const float*)d_in[9];
    const float* b3    = (const float*)d_in[10];
    const float* Win   = (const float*)d_in[11];
    const float* binp  = (const float*)d_in[12];
    const float* Wout  = (const float*)d_in[13];
    const float* boutp = (const float*)d_in[14];
    float* out = (float*)d_out;

    cudaFuncSetAttribute(edge_mlp_kernel, cudaFuncAttributeMaxDynamicSharedMemorySize, EDGE_SMEM);
    cudaFuncSetAttribute(ff_kernel, cudaFuncAttributeMaxDynamicSharedMemorySize, FF_SMEM);

    prep_kernel<<<128, 512>>>(W1, W2, W3, Win, Wout);
    edge_mlp_kernel<<<148, 256, EDGE_SMEM>>>(hV, hE, eidx, mAtt, b1, b2, b3);
    ff_kernel<<<(Bc * Nn) / 64, 256, FF_SMEM>>>(maskV, binp, boutp, out);
}

// round 4
// speedup vs baseline: 2.0036x; 2.0036x over previous
#include <cuda_runtime.h>
#include <cuda_bf16.h>
#include <mma.h>
#include <cstdint>

using namespace nvcuda;

constexpr int Bc=4, Nn=2048, Kc=48, Hc=128, FFc=512;
constexpr int NODES = Bc*Nn;                 // 8192
constexpr int EDGE_ROWS = NODES*Kc;          // 393216
constexpr int ROWS_T = 256;                  // edge tile rows
constexpr int N_TILES = EDGE_ROWS/ROWS_T;    // 1536
constexpr float INV_SCALE = 1.0f/30.0f;

__device__ __nv_bfloat16 g_W3hi[Hc*Hc], g_W3lo[Hc*Hc];
__device__ __nv_bfloat16 g_WinHi[Hc*FFc], g_WinLo[Hc*FFc];
__device__ __nv_bfloat16 g_WoutHi[FFc*Hc], g_WoutLo[FFc*Hc];
__device__ float g_s2[NODES*Hc];
__device__ float g_cnt[NODES];
__device__ float g_h[NODES*Hc];

// ---------------- low-level helpers ----------------
__device__ __forceinline__ uint32_t smem_u32(const void* p){
    uint32_t a; asm("{ .reg .u64 t; cvta.to.shared.u64 t, %1; cvt.u32.u64 %0, t; }":"=r"(a):"l"(p)); return a;
}
__device__ __forceinline__ void ldsm4(uint32_t* r, uint32_t addr){
    asm volatile("ldmatrix.sync.aligned.m8n8.x4.shared.b16 {%0,%1,%2,%3},[%4];"
        :"=r"(r[0]),"=r"(r[1]),"=r"(r[2]),"=r"(r[3]):"r"(addr));
}
__device__ __forceinline__ void ldsm4t(uint32_t* r, uint32_t addr){
    asm volatile("ldmatrix.sync.aligned.m8n8.x4.trans.shared.b16 {%0,%1,%2,%3},[%4];"
        :"=r"(r[0]),"=r"(r[1]),"=r"(r[2]),"=r"(r[3]):"r"(addr));
}
__device__ __forceinline__ void mma16816(float* d, const uint32_t* a, const uint32_t* b){
    asm volatile("mma.sync.aligned.m16n8k16.row.col.f32.bf16.bf16.f32 "
        "{%0,%1,%2,%3},{%4,%5,%6,%7},{%8,%9},{%0,%1,%2,%3};"
        :"+f"(d[0]),"+f"(d[1]),"+f"(d[2]),"+f"(d[3])
        :"r"(a[0]),"r"(a[1]),"r"(a[2]),"r"(a[3]),"r"(b[0]),"r"(b[1]));
}
__device__ __forceinline__ float gelu_fast(float x){
    float y = 0.7978845608028654f*x*(1.0f+0.044715f*x*x);
    float t; asm("tanh.approx.f32 %0, %1;":"=f"(t):"f"(y));
    return 0.5f*x*(1.0f+t);
}
__device__ __forceinline__ float gelu_erf_f(float x){ return x*normcdff(x); }

using FragA = wmma::fragment<wmma::matrix_a,16,16,16,__nv_bfloat16,wmma::row_major>;
using FragB = wmma::fragment<wmma::matrix_b,16,16,16,__nv_bfloat16,wmma::row_major>;
using FragC = wmma::fragment<wmma::accumulator,16,16,16,float>;

// ---------------- prep ----------------
__global__ void prep_kernel(const float* __restrict__ W3, const float* __restrict__ Win,
                            const float* __restrict__ Wout){
    int i = blockIdx.x*blockDim.x + threadIdx.x;  // 65536 threads
    if (i < Hc*FFc){
        float v=Win[i]; __nv_bfloat16 h=__float2bfloat16(v);
        g_WinHi[i]=h; g_WinLo[i]=__float2bfloat16(v-__bfloat162float(h));
        v=Wout[i]; h=__float2bfloat16(v);
        g_WoutHi[i]=h; g_WoutLo[i]=__float2bfloat16(v-__bfloat162float(h));
    }
    if (i < Hc*Hc){
        float v=W3[i]; __nv_bfloat16 h=__float2bfloat16(v);
        g_W3hi[i]=h; g_W3lo[i]=__float2bfloat16(v-__bfloat162float(h));
    }
    float4 z=make_float4(0.f,0.f,0.f,0.f);
    float4* s2=reinterpret_cast<float4*>(g_s2);
#pragma unroll
    for (int j=0;j<4;++j) s2[i*4+j]=z;
    if (i < NODES) g_cnt[i]=0.f;
}

// ---------------- edge MLP: raw mma.sync ----------------
// smem: A/M1 buf (256x136 bf16, stride 272B) | W1 (256x136) | W2 (128x136) | b1 | b2 | mask
constexpr int OFF_A   = 0;          // 69632
constexpr int OFF_W1  = 69632;      // 69632
constexpr int OFF_W2  = 139264;     // 34816
constexpr int OFF_B1  = 174080;     // 512
constexpr int OFF_B2  = 174592;     // 512
constexpr int OFF_MSK = 175104;     // 1024
constexpr int EDGE_SMEM = 176128;

__global__ __launch_bounds__(256,1)
void edge_mlp_mma(const float* __restrict__ hV, const float* __restrict__ hE,
                  const int* __restrict__ eidx, const float* __restrict__ mAtt,
                  const float* __restrict__ W1, const float* __restrict__ b1,
                  const float* __restrict__ W2, const float* __restrict__ b2){
    extern __shared__ __align__(16) char sm[];
    const int tid=threadIdx.x, wid=tid>>5, lane=tid&31;
    const int wm=wid&3, wn=wid>>2;
    const uint32_t smb=smem_u32(sm);
    float* b1s=reinterpret_cast<float*>(sm+OFF_B1);
    float* b2s=reinterpret_cast<float*>(sm+OFF_B2);
    float* mask_s=reinterpret_cast<float*>(sm+OFF_MSK);

    // weights -> smem (row-major [k][n], row stride 136 halves = 272B)
    for (int i=tid;i<256*128;i+=256){
        int k=i>>7, n=i&127;
        *reinterpret_cast<__nv_bfloat16*>(sm+OFF_W1+k*272+n*2) = __float2bfloat16(W1[i]);
    }
    for (int i=tid;i<128*128;i+=256){
        int k=i>>7, n=i&127;
        *reinterpret_cast<__nv_bfloat16*>(sm+OFF_W2+k*272+n*2) = __float2bfloat16(W2[i]);
    }
    if (tid<128){ b1s[tid]=b1[tid]; b2s[tid]=b2[tid]; }
    __syncthreads();

    // per-warp persistent bias pairs (cols wn*64 + j*8 + 2*(lane&3) + {0,1})
    float b1x[8],b1y[8],b2x[8],b2y[8];
#pragma unroll
    for (int j=0;j<8;++j){
        int c = wn*64 + j*8 + 2*(lane&3);
        b1x[j]=b1s[c]; b1y[j]=b1s[c+1];
        b2x[j]=b2s[c]; b2y[j]=b2s[c+1];
    }

    // ldmatrix lane-address bases
    const uint32_t a_base  = smb + OFF_A  + (uint32_t)((wm*64 + (lane&15))*272 + (lane>>4)*16);
    const uint32_t w1_base = smb + OFF_W1 + (uint32_t)((lane&15)*272 + (wn*64 + (lane>>4)*8)*2);
    const uint32_t w2_base = smb + OFF_W2 + (uint32_t)((lane&15)*272 + (wn*64 + (lane>>4)*8)*2);

    float acc[4][8][4];

    for (int t = blockIdx.x; t < N_TILES; t += 148){
        const int ge_base = t*ROWS_T;
        __syncthreads();   // previous tile fully consumed A/M1 + mask

        // ---- gather hV (cols 0-127) + mask ----
        {
            const int ge = ge_base + tid;
            const int node = ge / Kc;
            const int nb = eidx[ge];
            const float mk = mAtt[ge];
            mask_s[tid] = mk;
            // cnt: 16-lane (=16-row) groups are node-aligned
            float s = mk;
            s += __shfl_xor_sync(0xffffffffu,s,1);
            s += __shfl_xor_sync(0xffffffffu,s,2);
            s += __shfl_xor_sync(0xffffffffu,s,4);
            s += __shfl_xor_sync(0xffffffffu,s,8);
            if ((lane&15)==0) atomicAdd(&g_cnt[node], s);
            const float4* src = reinterpret_cast<const float4*>(hV) + ((size_t)((node>>11)<<11) + nb)*32;
            char* dst = sm + OFF_A + tid*272;
#pragma unroll 8
            for (int q=0;q<32;++q){
                float4 v = src[q];
                __nv_bfloat162 p0=__floats2bfloat162_rn(v.x,v.y), p1=__floats2bfloat162_rn(v.z,v.w);
                uint2 pk; pk.x=*reinterpret_cast<uint32_t*>(&p0); pk.y=*reinterpret_cast<uint32_t*>(&p1);
                *reinterpret_cast<uint2*>(dst + q*8) = pk;
            }
        }
#pragma unroll
        for (int s=0;s<4;++s)
#pragma unroll
            for (int j=0;j<8;++j)
#pragma unroll
                for (int c=0;c<4;++c) acc[s][j][c]=0.f;
        __syncthreads();

        // ---- GEMM1 phase 1: K cols 0-127 (hV) x W1 rows 0-127 ----
#pragma unroll
        for (int k=0;k<8;++k){
            uint32_t A[4][4];
#pragma unroll
            for (int s=0;s<4;++s) ldsm4(A[s], a_base + (uint32_t)(s*16*272 + k*32));
#pragma unroll
            for (int j2=0;j2<4;++j2){
                uint32_t B[4];
                ldsm4t(B, w1_base + (uint32_t)(k*16*272 + j2*32));
#pragma unroll
                for (int s=0;s<4;++s){
                    mma16816(acc[s][2*j2],   A[s], B);
                    mma16816(acc[s][2*j2+1], A[s], B+2);
                }
            }
        }
        __syncthreads();   // A phase-1 consumed

        // ---- load hE (cols 128-255) ----
        {
            const float4* src = reinterpret_cast<const float4*>(hE) + (size_t)(ge_base + tid)*32;
            char* dst = sm + OFF_A + tid*272;
#pragma unroll 8
            for (int q=0;q<32;++q){
                float4 v = src[q];
                __nv_bfloat162 p0=__floats2bfloat162_rn(v.x,v.y), p1=__floats2bfloat162_rn(v.z,v.w);
                uint2 pk; pk.x=*reinterpret_cast<uint32_t*>(&p0); pk.y=*reinterpret_cast<uint32_t*>(&p1);
                *reinterpret_cast<uint2*>(dst + q*8) = pk;
            }
        }
        __syncthreads();

        // ---- GEMM1 phase 2: hE x W1 rows 128-255 ----
#pragma unroll
        for (int k=0;k<8;++k){
            uint32_t A[4][4];
#pragma unroll
            for (int s=0;s<4;++s) ldsm4(A[s], a_base + (uint32_t)(s*16*272 + k*32));
#pragma unroll
            for (int j2=0;j2<4;++j2){
                uint32_t B[4];
                ldsm4t(B, w1_base + (uint32_t)((128+k*16)*272 + j2*32));
#pragma unroll
                for (int s=0;s<4;++s){
                    mma16816(acc[s][2*j2],   A[s], B);
                    mma16816(acc[s][2*j2+1], A[s], B+2);
                }
            }
        }
        __syncthreads();   // all warps done with A before M1 overwrite

        // ---- epi1: M1 = gelu(acc + b1) -> smem (reuse A buffer) ----
#pragma unroll
        for (int s=0;s<4;++s){
            int r0 = wm*64 + s*16 + (lane>>2);
#pragma unroll
            for (int j=0;j<8;++j){
                int col = wn*64 + j*8 + 2*(lane&3);
                float x0=gelu_fast(acc[s][j][0]+b1x[j]);
                float x1=gelu_fast(acc[s][j][1]+b1y[j]);
                float x2=gelu_fast(acc[s][j][2]+b1x[j]);
                float x3=gelu_fast(acc[s][j][3]+b1y[j]);
                __nv_bfloat162 p0=__floats2bfloat162_rn(x0,x1), p1=__floats2bfloat162_rn(x2,x3);
                *reinterpret_cast<uint32_t*>(sm + OFF_A + r0*272 + col*2)     = *reinterpret_cast<uint32_t*>(&p0);
                *reinterpret_cast<uint32_t*>(sm + OFF_A + (r0+8)*272 + col*2) = *reinterpret_cast<uint32_t*>(&p1);
            }
        }
#pragma unroll
        for (int s=0;s<4;++s)
#pragma unroll
            for (int j=0;j<8;++j)
#pragma unroll
                for (int c=0;c<4;++c) acc[s][j][c]=0.f;
        __syncthreads();

        // ---- GEMM2: M1 (K=128) x W2 ----
#pragma unroll
        for (int k=0;k<8;++k){
            uint32_t A[4][4];
#pragma unroll
            for (int s=0;s<4;++s) ldsm4(A[s], a_base + (uint32_t)(s*16*272 + k*32));
#pragma unroll
            for (int j2=0;j2<4;++j2){
                uint32_t B[4];
                ldsm4t(B, w2_base + (uint32_t)(k*16*272 + j2*32));
#pragma unroll
                for (int s=0;s<4;++s){
                    mma16816(acc[s][2*j2],   A[s], B);
                    mma16816(acc[s][2*j2+1], A[s], B+2);
                }
            }
        }

        // ---- epi2: gelu(acc+b2)*mask, 16-row column sums -> g_s2 ----
#pragma unroll
        for (int s=0;s<4;++s){
            const int rloc = wm*64 + s*16;
            const int node = (ge_base + rloc)/Kc;
            const float mka = mask_s[rloc + (lane>>2)];
            const float mkb = mask_s[rloc + (lane>>2) + 8];
#pragma unroll
            for (int j=0;j<8;++j){
                float v0 = gelu_fast(acc[s][j][0]+b2x[j])*mka;
                float v1 = gelu_fast(acc[s][j][1]+b2y[j])*mka;
                float v2 = gelu_fast(acc[s][j][2]+b2x[j])*mkb;
                float v3 = gelu_fast(acc[s][j][3]+b2y[j])*mkb;
                float s0 = v0+v2, s1 = v1+v3;
                s0 += __shfl_xor_sync(0xffffffffu,s0,4);
                s0 += __shfl_xor_sync(0xffffffffu,s0,8);
                s0 += __shfl_xor_sync(0xffffffffu,s0,16);
                s1 += __shfl_xor_sync(0xffffffffu,s1,4);
                s1 += __shfl_xor_sync(0xffffffffu,s1,8);
                s1 += __shfl_xor_sync(0xffffffffu,s1,16);
                if (lane<4){
                    int col = wn*64 + j*8 + 2*lane;
                    atomicAdd(&g_s2[(size_t)node*Hc + col],   s0);
                    atomicAdd(&g_s2[(size_t)node*Hc + col+1], s1);
                }
            }
        }
    }
}

// ---------------- w3h: g_h = hV + (S2@W3 + cnt*b3)/30 ----------------
constexpr int W3_AHI=0, W3_ALO=17408, W3_WHI=34816, W3_WLO=69632, W3_SCR=104448, W3_B3=116736, W3_CNT=117248;
constexpr int W3_SMEM=117504;
__global__ __launch_bounds__(256,1)
void w3h_kernel(const float* __restrict__ hV, const float* __restrict__ b3){
    extern __shared__ __align__(16) char sm[];
    __nv_bfloat16* Ahi=reinterpret_cast<__nv_bfloat16*>(sm+W3_AHI);
    __nv_bfloat16* Alo=reinterpret_cast<__nv_bfloat16*>(sm+W3_ALO);
    __nv_bfloat16* Whi=reinterpret_cast<__nv_bfloat16*>(sm+W3_WHI);
    __nv_bfloat16* Wlo=reinterpret_cast<__nv_bfloat16*>(sm+W3_WLO);
    float* scrb=reinterpret_cast<float*>(sm+W3_SCR);
    float* b3s=reinterpret_cast<float*>(sm+W3_B3);
    float* cnts=reinterpret_cast<float*>(sm+W3_CNT);
    const int tid=threadIdx.x, warp=tid>>5, lane=tid&31, rowbase=blockIdx.x*64;
    float* scr=scrb+warp*(16*24);
    if (tid<128) b3s[tid]=b3[tid];
    if (tid<64) cnts[tid]=g_cnt[rowbase+tid];
    for (int i=tid;i<Hc*128;i+=256){
        int r=i>>7,c=i&127;
        Whi[r*136+c]=g_W3hi[i]; Wlo[r*136+c]=g_W3lo[i];
    }
    for (int e=tid;e<64*32;e+=256){
        int r=e>>5,q=e&31;
        float4 v=reinterpret_cast<const float4*>(g_s2+(size_t)(rowbase+r)*Hc)[q];
        __nv_bfloat16 hx=__float2bfloat16(v.x),hy=__float2bfloat16(v.y),hz=__float2bfloat16(v.z),hw=__float2bfloat16(v.w);
        __nv_bfloat162* dh_=reinterpret_cast<__nv_bfloat162*>(Ahi+r*136+q*4);
        dh_[0]=__halves2bfloat162(hx,hy); dh_[1]=__halves2bfloat162(hz,hw);
        __nv_bfloat162* dl_=reinterpret_cast<__nv_bfloat162*>(Alo+r*136+q*4);
        dl_[0]=__floats2bfloat162_rn(v.x-__bfloat162float(hx),v.y-__bfloat162float(hy));
        dl_[1]=__floats2bfloat162_rn(v.z-__bfloat162float(hz),v.w-__bfloat162float(hw));
    }
    __syncthreads();
    const int ct=warp;
    for (int rt=0;rt<4;++rt){
        FragC acc; wmma::fill_fragment(acc,0.0f);
        for (int k=0;k<8;++k){
            FragB fbh,fbl; FragA fah,fal;
            wmma::load_matrix_sync(fbh,Whi+(k*16)*136+ct*16,136);
            wmma::load_matrix_sync(fbl,Wlo+(k*16)*136+ct*16,136);
            wmma::load_matrix_sync(fah,Ahi+(rt*16)*136+k*16,136);
            wmma::load_matrix_sync(fal,Alo+(rt*16)*136+k*16,136);
            wmma::mma_sync(acc,fah,fbh,acc);
            wmma::mma_sync(acc,fah,fbl,acc);
            wmma::mma_sync(acc,fal,fbh,acc);
        }
        wmma::store_matrix_sync(scr,acc,24,wmma::mem_row_major);
        __syncwarp();
#pragma unroll
        for (int i=0;i<8;++i){
            int e=lane+32*i, r=e>>4, c=e&15;
            int rl=rt*16+r, col=ct*16+c;
            int gi=(rowbase+rl)*Hc+col;
            g_h[gi]=hV[gi] + (scr[r*24+c] + cnts[rl]*b3s[col])*INV_SCALE;
        }
        __syncwarp();
    }
}

// ---------------- FF kernel (split-bf16 wmma, known correct) ----------------
constexpr int FOFF_AHI=0, FOFF_ALO=17408, FOFF_WIH=34816, FOFF_WIL=69632, FOFF_HHI=104448,
              FOFF_HLO=121856, FOFF_WOH=139264, FOFF_WOL=174080, FOFF_SCR=208896,
              FOFF_BIN=221184, FOFF_BOUT=223232, FOFF_MV=223744;
constexpr int FF_SMEM=224000;

__global__ __launch_bounds__(256,1)
void ff_kernel(const float* __restrict__ maskV, const float* __restrict__ b_in,
               const float* __restrict__ b_out, float* __restrict__ out){
    extern __shared__ __align__(16) char sm[];
    __nv_bfloat16* Ahi=reinterpret_cast<__nv_bfloat16*>(sm+FOFF_AHI);
    __nv_bfloat16* Alo=reinterpret_cast<__nv_bfloat16*>(sm+FOFF_ALO);
    __nv_bfloat16* WIH=reinterpret_cast<__nv_bfloat16*>(sm+FOFF_WIH);
    __nv_bfloat16* WIL=reinterpret_cast<__nv_bfloat16*>(sm+FOFF_WIL);
    __nv_bfloat16* HHI=reinterpret_cast<__nv_bfloat16*>(sm+FOFF_HHI);
    __nv_bfloat16* HLO=reinterpret_cast<__nv_bfloat16*>(sm+FOFF_HLO);
    __nv_bfloat16* WOH=reinterpret_cast<__nv_bfloat16*>(sm+FOFF_WOH);
    __nv_bfloat16* WOL=reinterpret_cast<__nv_bfloat16*>(sm+FOFF_WOL);
    float* scrb=reinterpret_cast<float*>(sm+FOFF_SCR);
    float* bins=reinterpret_cast<float*>(sm+FOFF_BIN);
    float* bouts=reinterpret_cast<float*>(sm+FOFF_BOUT);
    float* mvs=reinterpret_cast<float*>(sm+FOFF_MV);
    const int tid=threadIdx.x, warp=tid>>5, lane=tid&31, rowbase=blockIdx.x*64;
    float* scr=scrb+warp*(16*24);
    for (int i=tid;i<FFc;i+=256) bins[i]=b_in[i];
    if (tid<Hc) bouts[tid]=b_out[tid];
    if (tid<64) mvs[tid]=maskV[rowbase+tid];
    for (int e=tid;e<64*32;e+=256){
        int r=e>>5,q=e&31;
        float4 v=reinterpret_cast<const float4*>(g_h+(size_t)(rowbase+r)*Hc)[q];
        __nv_bfloat16 hx=__float2bfloat16(v.x); float lx=v.x-__bfloat162float(hx);
        __nv_bfloat16 hy=__float2bfloat16(v.y); float ly=v.y-__bfloat162float(hy);
        __nv_bfloat16 hz=__float2bfloat16(v.z); float lz=v.z-__bfloat162float(hz);
        __nv_bfloat16 hw=__float2bfloat16(v.w); float lw=v.w-__bfloat162float(hw);
        __nv_bfloat162* dh_=reinterpret_cast<__nv_bfloat162*>(Ahi+r*136+q*4);
        dh_[0]=__halves2bfloat162(hx,hy); dh_[1]=__halves2bfloat162(hz,hw);
        __nv_bfloat162* dl_=reinterpret_cast<__nv_bfloat162*>(Alo+r*136+q*4);
        dl_[0]=__floats2bfloat162_rn(lx,ly); dl_[1]=__floats2bfloat162_rn(lz,lw);
    }
    FragC accO[4];
#pragma unroll
    for (int j=0;j<4;++j) wmma::fill_fragment(accO[j],0.0f);
    const int ct=warp;
    for (int cc=0;cc<4;++cc){
        __syncthreads();
        for (int i=tid;i<Hc*128;i+=256){
            int r=i>>7,c=i&127;
            WIH[r*136+c]=g_WinHi[r*FFc+cc*128+c];
            WIL[r*136+c]=g_WinLo[r*FFc+cc*128+c];
            WOH[r*136+c]=g_WoutHi[(cc*128+r)*Hc+c];
            WOL[r*136+c]=g_WoutLo[(cc*128+r)*Hc+c];
        }
        __syncthreads();
        for (int rt=0;rt<4;rt+=2){
            FragC acc0,acc1;
            wmma::fill_fragment(acc0,0.0f); wmma::fill_fragment(acc1,0.0f);
            for (int k=0;k<8;++k){
                FragB fbh,fbl; FragA fah0,fal0,fah1,fal1;
                wmma::load_matrix_sync(fbh,WIH+(k*16)*136+ct*16,136);
                wmma::load_matrix_sync(fbl,WIL+(k*16)*136+ct*16,136);
                wmma::load_matrix_sync(fah0,Ahi+(rt*16)*136+k*16,136);
                wmma::load_matrix_sync(fal0,Alo+(rt*16)*136+k*16,136);
                wmma::load_matrix_sync(fah1,Ahi+((rt+1)*16)*136+k*16,136);
                wmma::load_matrix_sync(fal1,Alo+((rt+1)*16)*136+k*16,136);
                wmma::mma_sync(acc0,fah0,fbh,acc0); wmma::mma_sync(acc0,fah0,fbl,acc0); wmma::mma_sync(acc0,fal0,fbh,acc0);
                wmma::mma_sync(acc1,fah1,fbh,acc1); wmma::mma_sync(acc1,fah1,fbl,acc1); wmma::mma_sync(acc1,fal1,fbh,acc1);
            }
            auto epiH=[&](const FragC& acc,int rbase){
                wmma::store_matrix_sync(scr,acc,24,wmma::mem_row_major);
                __syncwarp();
#pragma unroll
                for (int i=0;i<8;++i){
                    int e=lane+32*i, r=e>>4, c=e&15;
                    float v=scr[r*24+c]+bins[cc*128+ct*16+c];
                    v=gelu_erf_f(v);
                    __nv_bfloat16 hi=__float2bfloat16(v);
                    HHI[(rbase+r)*136+ct*16+c]=hi;
                    HLO[(rbase+r)*136+ct*16+c]=__float2bfloat16(v-__bfloat162float(hi));
                }
                __syncwarp();
            };
            epiH(acc0,rt*16); epiH(acc1,(rt+1)*16);
        }
        __syncthreads();
#pragma unroll
        for (int rp=0;rp<4;rp+=2){
            for (int k=0;k<8;++k){
                FragB fbh,fbl; FragA fah0,fal0,fah1,fal1;
                wmma::load_matrix_sync(fbh,WOH+(k*16)*136+ct*16,136);
                wmma::load_matrix_sync(fbl,WOL+(k*16)*136+ct*16,136);
                wmma::load_matrix_sync(fah0,HHI+(rp*16)*136+k*16,136);
                wmma::load_matrix_sync(fal0,HLO+(rp*16)*136+k*16,136);
                wmma::load_matrix_sync(fah1,HHI+((rp+1)*16)*136+k*16,136);
                wmma::load_matrix_sync(fal1,HLO+((rp+1)*16)*136+k*16,136);
                wmma::mma_sync(accO[rp],fah0,fbh,accO[rp]); wmma::mma_sync(accO[rp],fah0,fbl,accO[rp]); wmma::mma_sync(accO[rp],fal0,fbh,accO[rp]);
                wmma::mma_sync(accO[rp+1],fah1,fbh,accO[rp+1]); wmma::mma_sync(accO[rp+1],fah1,fbl,accO[rp+1]); wmma::mma_sync(accO[rp+1],fal1,fbh,accO[rp+1]);
            }
        }
    }
#pragma unroll
    for (int j=0;j<4;++j){
        wmma::store_matrix_sync(scr,accO[j],24,wmma::mem_row_major);
        __syncwarp();
        int rbase=j*16;
#pragma unroll
        for (int i=0;i<8;++i){
            int e=lane+32*i, r=e>>4, c=e&15;
            int rg=rowbase+rbase+r, col=ct*16+c;
            int gi=rg*Hc+col;
            out[gi]=(g_h[gi]+scr[r*24+c]+bouts[col])*mvs[rbase+r];
        }
        __syncwarp();
    }
}

// ---------------- launch ----------------
extern "C" void kernel_launch(void* const* d_in, const int* in_sizes, int n_in,
                              void* d_out, int out_size){
    (void)in_sizes; (void)n_in; (void)out_size;
    const float* hV   =(const float*)d_in[0];
    const float* hE   =(const float*)d_in[1];
    const int*   eidx =(const int*)d_in[2];
    const float* maskV=(const float*)d_in[3];
    const float* mAtt =(const float*)d_in[4];
    const float* W1   =(const float*)d_in[5];
    const float* b1   =(const float*)d_in[6];
    const float* W2   =(const float*)d_in[7];
    const float* b2   =(const float*)d_in[8];
    const float* W3   =(const float*)d_in[9];
    const float* b3   =(const float*)d_in[10];
    const float* Win  =(const float*)d_in[11];
    const float* binp =(const float*)d_in[12];
    const float* Wout =(const float*)d_in[13];
    const float* boutp=(const float*)d_in[14];
    float* out=(float*)d_out;

    cudaFuncSetAttribute(edge_mlp_mma, cudaFuncAttributeMaxDynamicSharedMemorySize, EDGE_SMEM);
    cudaFuncSetAttribute(w3h_kernel, cudaFuncAttributeMaxDynamicSharedMemorySize, W3_SMEM);
    cudaFuncSetAttribute(ff_kernel, cudaFuncAttributeMaxDynamicSharedMemorySize, FF_SMEM);

    prep_kernel<<<128, 512>>>(W3, Win, Wout);
    edge_mlp_mma<<<148, 256, EDGE_SMEM>>>(hV, hE, eidx, mAtt, W1, b1, W2, b2);
    w3h_kernel<<<NODES/64, 256, W3_SMEM>>>(hV, b3);
    ff_kernel<<<NODES/64, 256, FF_SMEM>>>(maskV, binp, boutp, out);
}

// round 5
// speedup vs baseline: 2.2193x; 1.1076x over previous
#include <cuda_runtime.h>
#include <cuda_bf16.h>
#include <cstdint>

constexpr int Bc=4, Nn=2048, Kc=48, Hc=128, FFc=512;
constexpr int NODES = Bc*Nn;                 // 8192
constexpr int EDGE_ROWS = NODES*Kc;          // 393216
constexpr int ROWS_T = 128;                  // edge tile rows (per warpgroup)
constexpr int N_TILES = EDGE_ROWS/ROWS_T;    // 3072
constexpr float INV_SCALE = 1.0f/30.0f;

__device__ __nv_bfloat16 g_W3hi[Hc*Hc], g_W3lo[Hc*Hc];
__device__ __nv_bfloat16 g_WinHi[Hc*FFc], g_WinLo[Hc*FFc];
__device__ __nv_bfloat16 g_WoutHi[FFc*Hc], g_WoutLo[FFc*Hc];
__device__ float g_s2[NODES*Hc];
__device__ float g_cnt[NODES];

// ---------------- low-level helpers ----------------
__device__ __forceinline__ uint32_t smem_u32(const void* p){
    uint32_t a; asm("{ .reg .u64 t; cvta.to.shared.u64 t, %1; cvt.u32.u64 %0, t; }":"=r"(a):"l"(p)); return a;
}
__device__ __forceinline__ void ldsm4(uint32_t* r, uint32_t addr){
    asm volatile("ldmatrix.sync.aligned.m8n8.x4.shared.b16 {%0,%1,%2,%3},[%4];"
        :"=r"(r[0]),"=r"(r[1]),"=r"(r[2]),"=r"(r[3]):"r"(addr));
}
__device__ __forceinline__ void ldsm4t(uint32_t* r, uint32_t addr){
    asm volatile("ldmatrix.sync.aligned.m8n8.x4.trans.shared.b16 {%0,%1,%2,%3},[%4];"
        :"=r"(r[0]),"=r"(r[1]),"=r"(r[2]),"=r"(r[3]):"r"(addr));
}
__device__ __forceinline__ void mma16816(float* d, const uint32_t* a, const uint32_t* b){
    asm volatile("mma.sync.aligned.m16n8k16.row.col.f32.bf16.bf16.f32 "
        "{%0,%1,%2,%3},{%4,%5,%6,%7},{%8,%9},{%0,%1,%2,%3};"
        :"+f"(d[0]),"+f"(d[1]),"+f"(d[2]),"+f"(d[3])
        :"r"(a[0]),"r"(a[1]),"r"(a[2]),"r"(a[3]),"r"(b[0]),"r"(b[1]));
}
#define BAR_WG(id) asm volatile("bar.sync %0, %1;"::"r"((id)),"r"(128):"memory")

__device__ __forceinline__ float gelu_fast(float x){
    float y = 0.7978845608028654f*x*(1.0f+0.044715f*x*x);
    float t; asm("tanh.approx.f32 %0, %1;":"=f"(t):"f"(y));
    return 0.5f*x*(1.0f+t);
}
__device__ __forceinline__ float gelu_erf_f(float x){ return x*normcdff(x); }

// ---------------- prep ----------------
__global__ void prep_kernel(const float* __restrict__ W3, const float* __restrict__ Win,
                            const float* __restrict__ Wout){
    int i = blockIdx.x*blockDim.x + threadIdx.x;  // 65536 threads
    if (i < Hc*FFc){
        float v=Win[i]; __nv_bfloat16 h=__float2bfloat16(v);
        g_WinHi[i]=h; g_WinLo[i]=__float2bfloat16(v-__bfloat162float(h));
        v=Wout[i]; h=__float2bfloat16(v);
        g_WoutHi[i]=h; g_WoutLo[i]=__float2bfloat16(v-__bfloat162float(h));
    }
    if (i < Hc*Hc){
        float v=W3[i]; __nv_bfloat16 h=__float2bfloat16(v);
        g_W3hi[i]=h; g_W3lo[i]=__float2bfloat16(v-__bfloat162float(h));
    }
    float4 z=make_float4(0.f,0.f,0.f,0.f);
    float4* s2=reinterpret_cast<float4*>(g_s2);
#pragma unroll
    for (int j=0;j<4;++j) s2[i*4+j]=z;
    if (i < NODES) g_cnt[i]=0.f;
}

// ---------------- edge MLP: raw mma.sync, 2 independent warpgroups ----------------
// smem: A/M1 buf per wg (128x136 bf16, stride 272B) x2 | W1 (256x136) | W2 (128x136) | b1 | b2 | masks
constexpr int OFF_A   = 0;          // 2 x 34816 = 69632
constexpr int OFF_W1  = 69632;      // 69632
constexpr int OFF_W2  = 139264;     // 34816
constexpr int OFF_B1  = 174080;     // 512
constexpr int OFF_B2  = 174592;     // 512
constexpr int OFF_MSK = 175104;     // 2 x 512
constexpr int EDGE_SMEM = 176128;

__global__ __launch_bounds__(256,1)
void edge_mlp_mma(const float* __restrict__ hV, const float* __restrict__ hE,
                  const int* __restrict__ eidx, const float* __restrict__ mAtt,
                  const float* __restrict__ W1, const float* __restrict__ b1,
                  const float* __restrict__ W2, const float* __restrict__ b2){
    extern __shared__ __align__(16) char sm[];
    const int tid=threadIdx.x, wid=tid>>5, lane=tid&31;
    const int wg=wid>>2, wq=wid&3;
    const int wm=wq&1, wn=wq>>1;       // per-wg warp grid: 2 M-tiles(64) x 2 N-tiles(64)
    const int wg_tid=tid&127;
    const uint32_t smb=smem_u32(sm);
    float* b1s=reinterpret_cast<float*>(sm+OFF_B1);
    float* b2s=reinterpret_cast<float*>(sm+OFF_B2);
    float* mask_s=reinterpret_cast<float*>(sm+OFF_MSK+wg*512);
    const int aoff = OFF_A + wg*34816;

    // weights -> smem (row-major [k][n], row stride 136 halves = 272B)
    for (int i=tid;i<256*128;i+=256){
        int k=i>>7, n=i&127;
        *reinterpret_cast<__nv_bfloat16*>(sm+OFF_W1+k*272+n*2) = __float2bfloat16(W1[i]);
    }
    for (int i=tid;i<128*128;i+=256){
        int k=i>>7, n=i&127;
        *reinterpret_cast<__nv_bfloat16*>(sm+OFF_W2+k*272+n*2) = __float2bfloat16(W2[i]);
    }
    if (tid<128){ b1s[tid]=b1[tid]; b2s[tid]=b2[tid]; }
    __syncthreads();

    // per-warp persistent bias pairs
    float b1x[8],b1y[8],b2x[8],b2y[8];
#pragma unroll
    for (int j=0;j<8;++j){
        int c = wn*64 + j*8 + 2*(lane&3);
        b1x[j]=b1s[c]; b1y[j]=b1s[c+1];
        b2x[j]=b2s[c]; b2y[j]=b2s[c+1];
    }

    const uint32_t a_base  = smb + aoff   + (uint32_t)((wm*64 + (lane&15))*272 + (lane>>4)*16);
    const uint32_t w1_base = smb + OFF_W1 + (uint32_t)((lane&15)*272 + (wn*64 + (lane>>4)*8)*2);
    const uint32_t w2_base = smb + OFF_W2 + (uint32_t)((lane&15)*272 + (wn*64 + (lane>>4)*8)*2);

    float acc[4][8][4];

    for (int t = blockIdx.x*2+wg; t < N_TILES; t += 296){
        const int ge_base = t*ROWS_T;
        BAR_WG(wg+1);   // previous tile fully consumed A/M1 + mask

        // ---- gather hV (cols 0-127) + mask ----
        {
            const int ge = ge_base + wg_tid;
            const int node = ge / Kc;
            const int nb = eidx[ge];
            const float mk = mAtt[ge];
            mask_s[wg_tid] = mk;
            float s = mk;
            s += __shfl_xor_sync(0xffffffffu,s,1);
            s += __shfl_xor_sync(0xffffffffu,s,2);
            s += __shfl_xor_sync(0xffffffffu,s,4);
            s += __shfl_xor_sync(0xffffffffu,s,8);
            if ((lane&15)==0) atomicAdd(&g_cnt[node], s);
            const float4* src = reinterpret_cast<const float4*>(hV) + ((size_t)((node>>11)<<11) + nb)*32;
            char* dst = sm + aoff + wg_tid*272;
#pragma unroll 8
            for (int q=0;q<32;++q){
                float4 v = src[q];
                __nv_bfloat162 p0=__floats2bfloat162_rn(v.x,v.y), p1=__floats2bfloat162_rn(v.z,v.w);
                uint2 pk; pk.x=*reinterpret_cast<uint32_t*>(&p0); pk.y=*reinterpret_cast<uint32_t*>(&p1);
                *reinterpret_cast<uint2*>(dst + q*8) = pk;
            }
        }
#pragma unroll
        for (int s=0;s<4;++s)
#pragma unroll
            for (int j=0;j<8;++j)
#pragma unroll
                for (int c=0;c<4;++c) acc[s][j][c]=0.f;
        BAR_WG(wg+1);

        // ---- GEMM1 phase 1: hV cols x W1 rows 0-127 ----
#pragma unroll
        for (int k=0;k<8;++k){
            uint32_t A[4][4];
#pragma unroll
            for (int s=0;s<4;++s) ldsm4(A[s], a_base + (uint32_t)(s*16*272 + k*32));
#pragma unroll
            for (int j2=0;j2<4;++j2){
                uint32_t B[4];
                ldsm4t(B, w1_base + (uint32_t)(k*16*272 + j2*32));
#pragma unroll
                for (int s=0;s<4;++s){
                    mma16816(acc[s][2*j2],   A[s], B);
                    mma16816(acc[s][2*j2+1], A[s], B+2);
                }
            }
        }
        BAR_WG(wg+1);   // A phase-1 consumed

        // ---- load hE (cols 128-255) ----
        {
            const float4* src = reinterpret_cast<const float4*>(hE) + (size_t)(ge_base + wg_tid)*32;
            char* dst = sm + aoff + wg_tid*272;
#pragma unroll 8
            for (int q=0;q<32;++q){
                float4 v = src[q];
                __nv_bfloat162 p0=__floats2bfloat162_rn(v.x,v.y), p1=__floats2bfloat162_rn(v.z,v.w);
                uint2 pk; pk.x=*reinterpret_cast<uint32_t*>(&p0); pk.y=*reinterpret_cast<uint32_t*>(&p1);
                *reinterpret_cast<uint2*>(dst + q*8) = pk;
            }
        }
        BAR_WG(wg+1);

        // ---- GEMM1 phase 2: hE x W1 rows 128-255 ----
#pragma unroll
        for (int k=0;k<8;++k){
            uint32_t A[4][4];
#pragma unroll
            for (int s=0;s<4;++s) ldsm4(A[s], a_base + (uint32_t)(s*16*272 + k*32));
#pragma unroll
            for (int j2=0;j2<4;++j2){
                uint32_t B[4];
                ldsm4t(B, w1_base + (uint32_t)((128+k*16)*272 + j2*32));
#pragma unroll
                for (int s=0;s<4;++s){
                    mma16816(acc[s][2*j2],   A[s], B);
                    mma16816(acc[s][2*j2+1], A[s], B+2);
                }
            }
        }
        BAR_WG(wg+1);   // all wg warps done with A before M1 overwrite

        // ---- epi1: M1 = gelu(acc + b1) -> smem (reuse A buffer) ----
#pragma unroll
        for (int s=0;s<4;++s){
            int r0 = wm*64 + s*16 + (lane>>2);
#pragma unroll
            for (int j=0;j<8;++j){
                int col = wn*64 + j*8 + 2*(lane&3);
                float x0=gelu_fast(acc[s][j][0]+b1x[j]);
                float x1=gelu_fast(acc[s][j][1]+b1y[j]);
                float x2=gelu_fast(acc[s][j][2]+b1x[j]);
                float x3=gelu_fast(acc[s][j][3]+b1y[j]);
                __nv_bfloat162 p0=__floats2bfloat162_rn(x0,x1), p1=__floats2bfloat162_rn(x2,x3);
                *reinterpret_cast<uint32_t*>(sm + aoff + r0*272 + col*2)     = *reinterpret_cast<uint32_t*>(&p0);
                *reinterpret_cast<uint32_t*>(sm + aoff + (r0+8)*272 + col*2) = *reinterpret_cast<uint32_t*>(&p1);
            }
        }
#pragma unroll
        for (int s=0;s<4;++s)
#pragma unroll
            for (int j=0;j<8;++j)
#pragma unroll
                for (int c=0;c<4;++c) acc[s][j][c]=0.f;
        BAR_WG(wg+1);

        // ---- GEMM2: M1 (K=128) x W2 ----
#pragma unroll
        for (int k=0;k<8;++k){
            uint32_t A[4][4];
#pragma unroll
            for (int s=0;s<4;++s) ldsm4(A[s], a_base + (uint32_t)(s*16*272 + k*32));
#pragma unroll
            for (int j2=0;j2<4;++j2){
                uint32_t B[4];
                ldsm4t(B, w2_base + (uint32_t)(k*16*272 + j2*32));
#pragma unroll
                for (int s=0;s<4;++s){
                    mma16816(acc[s][2*j2],   A[s], B);
                    mma16816(acc[s][2*j2+1], A[s], B+2);
                }
            }
        }

        // ---- epi2: gelu(acc+b2)*mask, 16-row column sums -> g_s2 ----
#pragma unroll
        for (int s=0;s<4;++s){
            const int rloc = wm*64 + s*16;
            const int node = (ge_base + rloc)/Kc;
            const float mka = mask_s[rloc + (lane>>2)];
            const float mkb = mask_s[rloc + (lane>>2) + 8];
#pragma unroll
            for (int j=0;j<8;++j){
                float v0 = gelu_fast(acc[s][j][0]+b2x[j])*mka;
                float v1 = gelu_fast(acc[s][j][1]+b2y[j])*mka;
                float v2 = gelu_fast(acc[s][j][2]+b2x[j])*mkb;
                float v3 = gelu_fast(acc[s][j][3]+b2y[j])*mkb;
                float s0 = v0+v2, s1 = v1+v3;
                s0 += __shfl_xor_sync(0xffffffffu,s0,4);
                s0 += __shfl_xor_sync(0xffffffffu,s0,8);
                s0 += __shfl_xor_sync(0xffffffffu,s0,16);
                s1 += __shfl_xor_sync(0xffffffffu,s1,4);
                s1 += __shfl_xor_sync(0xffffffffu,s1,8);
                s1 += __shfl_xor_sync(0xffffffffu,s1,16);
                if (lane<4){
                    int col = wn*64 + j*8 + 2*lane;
                    atomicAdd(&g_s2[(size_t)node*Hc + col],   s0);
                    atomicAdd(&g_s2[(size_t)node*Hc + col+1], s1);
                }
            }
        }
    }
}

// ---------------- fused node kernel: h = hV + (S2@W3 + cnt*b3)/30, then FF ----------------
// 64 rows/block, 128 blocks, 256 threads, raw mma.sync split-bf16.
// warp grid: 2 M-tiles(32) x 4 N-tiles(32). per-warp acc [2 strips][4 n8][4].
constexpr int NOFF_S2HI = 0;         // 17408 (later: mid hi)
constexpr int NOFF_S2LO = 17408;     // 17408 (later: mid lo)
constexpr int NOFF_HHI  = 34816;     // 17408
constexpr int NOFF_HLO  = 52224;     // 17408
constexpr int NOFF_W    = 69632;     // 139264: stage0 {W3hi,W3lo}; chunks {WinHi,WinLo,WoutHi,WoutLo}
constexpr int NOFF_B3   = 208896;    // 512
constexpr int NOFF_BIN  = 209408;    // 2048
constexpr int NOFF_BOUT = 211456;    // 512
constexpr int NOFF_MV   = 211968;    // 256
constexpr int NOFF_CNT  = 212224;    // 256
constexpr int NODE_SMEM = 212480;

__global__ __launch_bounds__(256,1)
void node_kernel(const float* __restrict__ hV, const float* __restrict__ maskV,
                 const float* __restrict__ b3, const float* __restrict__ b_in,
                 const float* __restrict__ b_out, float* __restrict__ out){
    extern __shared__ __align__(16) char sm[];
    const int tid=threadIdx.x, wid=tid>>5, lane=tid&31;
    const int wm=wid&1, wn=wid>>1;          // 2 x 4 warp grid
    const int rowbase = blockIdx.x*64;
    const uint32_t smb=smem_u32(sm);
    float* b3s  = reinterpret_cast<float*>(sm+NOFF_B3);
    float* bins = reinterpret_cast<float*>(sm+NOFF_BIN);
    float* bouts= reinterpret_cast<float*>(sm+NOFF_BOUT);
    float* mvs  = reinterpret_cast<float*>(sm+NOFF_MV);
    float* cnts = reinterpret_cast<float*>(sm+NOFF_CNT);

    if (tid<128) b3s[tid]=b3[tid];
    for (int i=tid;i<FFc;i+=256) bins[i]=b_in[i];
    if (tid>=128 && tid<256) bouts[tid-128]=b_out[tid-128];
    if (tid<64){ mvs[tid]=maskV[rowbase+tid]; cnts[tid]=g_cnt[rowbase+tid]; }

    // S2 -> split bf16 hi/lo (rows 64 x 128, stride 272B)
    for (int e=tid;e<64*32;e+=256){
        int r=e>>5, q=e&31;
        float4 v = reinterpret_cast<const float4*>(g_s2 + (size_t)(rowbase+r)*Hc)[q];
        __nv_bfloat16 hx=__float2bfloat16(v.x),hy=__float2bfloat16(v.y),
                      hz=__float2bfloat16(v.z),hw=__float2bfloat16(v.w);
        __nv_bfloat162 ph0=__halves2bfloat162(hx,hy), ph1=__halves2bfloat162(hz,hw);
        __nv_bfloat162 pl0=__floats2bfloat162_rn(v.x-__bfloat162float(hx),v.y-__bfloat162float(hy));
        __nv_bfloat162 pl1=__floats2bfloat162_rn(v.z-__bfloat162float(hz),v.w-__bfloat162float(hw));
        uint2 uh; uh.x=*reinterpret_cast<uint32_t*>(&ph0); uh.y=*reinterpret_cast<uint32_t*>(&ph1);
        uint2 ul; ul.x=*reinterpret_cast<uint32_t*>(&pl0); ul.y=*reinterpret_cast<uint32_t*>(&pl1);
        *reinterpret_cast<uint2*>(sm + NOFF_S2HI + r*272 + q*8) = uh;
        *reinterpret_cast<uint2*>(sm + NOFF_S2LO + r*272 + q*8) = ul;
    }
    // W3 hi/lo -> smem [k][n] stride 272
    for (int i=tid;i<128*128;i+=256){
        int r=i>>7,c=i&127;
        *reinterpret_cast<__nv_bfloat16*>(sm+NOFF_W+r*272+c*2)        = g_W3hi[i];
        *reinterpret_cast<__nv_bfloat16*>(sm+NOFF_W+34816+r*272+c*2)  = g_W3lo[i];
    }
    __syncthreads();

    // ldsm lane bases
    const uint32_t a_row = (uint32_t)((wm*32 + (lane&15))*272 + (lane>>4)*16);
    const uint32_t b_row = (uint32_t)((lane&15)*272 + (wn*32 + (lane>>4)*8)*2);

    auto gemm3 = [&](float acc[2][4][4], uint32_t ahi, uint32_t alo, uint32_t bhi, uint32_t blo){
#pragma unroll
        for (int k=0;k<8;++k){
            uint32_t Ah[2][4], Al[2][4], Bh[2][4], Bl[2][4];
#pragma unroll
            for (int s=0;s<2;++s){
                ldsm4(Ah[s], ahi + (uint32_t)(s*16*272 + k*32));
                ldsm4(Al[s], alo + (uint32_t)(s*16*272 + k*32));
            }
#pragma unroll
            for (int j2=0;j2<2;++j2){
                ldsm4t(Bh[j2], bhi + (uint32_t)(k*16*272 + j2*32));
                ldsm4t(Bl[j2], blo + (uint32_t)(k*16*272 + j2*32));
            }
#pragma unroll
            for (int s=0;s<2;++s)
#pragma unroll
                for (int j2=0;j2<2;++j2){
                    mma16816(acc[s][2*j2],   Ah[s], Bh[j2]);
                    mma16816(acc[s][2*j2+1], Ah[s], Bh[j2]+2);
                    mma16816(acc[s][2*j2],   Ah[s], Bl[j2]);
                    mma16816(acc[s][2*j2+1], Ah[s], Bl[j2]+2);
                    mma16816(acc[s][2*j2],   Al[s], Bh[j2]);
                    mma16816(acc[s][2*j2+1], Al[s], Bh[j2]+2);
                }
        }
    };

    // ---- stage0: h = hV + (S2@W3 + cnt*b3)/30 ----
    {
        float acc[2][4][4];
#pragma unroll
        for (int s=0;s<2;++s)
#pragma unroll
            for (int j=0;j<4;++j)
#pragma unroll
                for (int c=0;c<4;++c) acc[s][j][c]=0.f;
        gemm3(acc, smb+NOFF_S2HI+a_row, smb+NOFF_S2LO+a_row,
                   smb+NOFF_W+b_row,    smb+NOFF_W+34816+b_row);
#pragma unroll
        for (int s=0;s<2;++s){
            int r0 = wm*32 + s*16 + (lane>>2);
#pragma unroll
            for (int j=0;j<4;++j){
                int c = wn*32 + j*8 + 2*(lane&3);
#pragma unroll
                for (int half=0; half<2; ++half){
                    int r = r0 + half*8;
                    size_t gi = (size_t)(rowbase+r)*Hc + c;
                    float h0 = hV[gi]   + (acc[s][j][2*half]   + cnts[r]*b3s[c])  *INV_SCALE;
                    float h1 = hV[gi+1] + (acc[s][j][2*half+1] + cnts[r]*b3s[c+1])*INV_SCALE;
                    __nv_bfloat16 x0=__float2bfloat16(h0), x1=__float2bfloat16(h1);
                    __nv_bfloat162 ph=__halves2bfloat162(x0,x1);
                    __nv_bfloat162 pl=__floats2bfloat162_rn(h0-__bfloat162float(x0),h1-__bfloat162float(x1));
                    *reinterpret_cast<uint32_t*>(sm+NOFF_HHI+r*272+c*2)=*reinterpret_cast<uint32_t*>(&ph);
                    *reinterpret_cast<uint32_t*>(sm+NOFF_HLO+r*272+c*2)=*reinterpret_cast<uint32_t*>(&pl);
                }
            }
        }
    }

    // ---- FF chunks ----
    float accO[2][4][4];
#pragma unroll
    for (int s=0;s<2;++s)
#pragma unroll
        for (int j=0;j<4;++j)
#pragma unroll
            for (int c=0;c<4;++c) accO[s][j][c]=0.f;

    for (int cc=0;cc<4;++cc){
        __syncthreads();   // prev GEMM2 done with W; stage0 epi done with h (cc=0)
        for (int i=tid;i<128*128;i+=256){
            int r=i>>7,c=i&127;
            *reinterpret_cast<__nv_bfloat16*>(sm+NOFF_W+r*272+c*2)          = g_WinHi[r*FFc+cc*128+c];
            *reinterpret_cast<__nv_bfloat16*>(sm+NOFF_W+34816+r*272+c*2)    = g_WinLo[r*FFc+cc*128+c];
            *reinterpret_cast<__nv_bfloat16*>(sm+NOFF_W+69632+r*272+c*2)    = g_WoutHi[(cc*128+r)*Hc+c];
            *reinterpret_cast<__nv_bfloat16*>(sm+NOFF_W+104448+r*272+c*2)   = g_WoutLo[(cc*128+r)*Hc+c];
        }
        __syncthreads();

        // GEMM1: mid = gelu_exact(h @ Win_cc + b_in_cc)
        float accM[2][4][4];
#pragma unroll
        for (int s=0;s<2;++s)
#pragma unroll
            for (int j=0;j<4;++j)
#pragma unroll
                for (int c=0;c<4;++c) accM[s][j][c]=0.f;
        gemm3(accM, smb+NOFF_HHI+a_row, smb+NOFF_HLO+a_row,
                    smb+NOFF_W+b_row,   smb+NOFF_W+34816+b_row);
#pragma unroll
        for (int s=0;s<2;++s){
            int r0 = wm*32 + s*16 + (lane>>2);
#pragma unroll
            for (int j=0;j<4;++j){
                int c = wn*32 + j*8 + 2*(lane&3);
#pragma unroll
                for (int half=0; half<2; ++half){
                    int r = r0 + half*8;
                    float v0 = gelu_erf_f(accM[s][j][2*half]   + bins[cc*128+c]);
                    float v1 = gelu_erf_f(accM[s][j][2*half+1] + bins[cc*128+c+1]);
                    __nv_bfloat16 x0=__float2bfloat16(v0), x1=__float2bfloat16(v1);
                    __nv_bfloat162 ph=__halves2bfloat162(x0,x1);
                    __nv_bfloat162 pl=__floats2bfloat162_rn(v0-__bfloat162float(x0),v1-__bfloat162float(x1));
                    *reinterpret_cast<uint32_t*>(sm+NOFF_S2HI+r*272+c*2)=*reinterpret_cast<uint32_t*>(&ph);
                    *reinterpret_cast<uint32_t*>(sm+NOFF_S2LO+r*272+c*2)=*reinterpret_cast<uint32_t*>(&pl);
                }
            }
        }
        __syncthreads();

        // GEMM2: accO += mid @ Wout_cc
        gemm3(accO, smb+NOFF_S2HI+a_row, smb+NOFF_S2LO+a_row,
                    smb+NOFF_W+69632+b_row, smb+NOFF_W+104448+b_row);
    }

    // ---- final: out = (h + ff + b_out) * maskV ----
#pragma unroll
    for (int s=0;s<2;++s){
        int r0 = wm*32 + s*16 + (lane>>2);
#pragma unroll
        for (int j=0;j<4;++j){
            int c = wn*32 + j*8 + 2*(lane&3);
#pragma unroll
            for (int half=0; half<2; ++half){
                int r = r0 + half*8;
                size_t gi = (size_t)(rowbase+r)*Hc + c;
                __nv_bfloat162 hh = *reinterpret_cast<__nv_bfloat162*>(sm+NOFF_HHI+r*272+c*2);
                __nv_bfloat162 hl = *reinterpret_cast<__nv_bfloat162*>(sm+NOFF_HLO+r*272+c*2);
                float h0 = __bfloat162float(hh.x)+__bfloat162float(hl.x);
                float h1 = __bfloat162float(hh.y)+__bfloat162float(hl.y);
                float mv = mvs[r];
                out[gi]   = (h0 + accO[s][j][2*half]   + bouts[c])  * mv;
                out[gi+1] = (h1 + accO[s][j][2*half+1] + bouts[c+1])* mv;
            }
        }
    }
}

// ---------------- launch ----------------
extern "C" void kernel_launch(void* const* d_in, const int* in_sizes, int n_in,
                              void* d_out, int out_size){
    (void)in_sizes; (void)n_in; (void)out_size;
    const float* hV   =(const float*)d_in[0];
    const float* hE   =(const float*)d_in[1];
    const int*   eidx =(const int*)d_in[2];
    const float* maskV=(const float*)d_in[3];
    const float* mAtt =(const float*)d_in[4];
    const float* W1   =(const float*)d_in[5];
    const float* b1   =(const float*)d_in[6];
    const float* W2   =(const float*)d_in[7];
    const float* b2   =(const float*)d_in[8];
    const float* W3   =(const float*)d_in[9];
    const float* b3   =(const float*)d_in[10];
    const float* Win  =(const float*)d_in[11];
    const float* binp =(const float*)d_in[12];
    const float* Wout =(const float*)d_in[13];
    const float* boutp=(const float*)d_in[14];
    float* out=(float*)d_out;

    cudaFuncSetAttribute(edge_mlp_mma, cudaFuncAttributeMaxDynamicSharedMemorySize, EDGE_SMEM);
    cudaFuncSetAttribute(node_kernel, cudaFuncAttributeMaxDynamicSharedMemorySize, NODE_SMEM);

    prep_kernel<<<128, 512>>>(W3, Win, Wout);
    edge_mlp_mma<<<148, 256, EDGE_SMEM>>>(hV, hE, eidx, mAtt, W1, b1, W2, b2);
    node_kernel<<<NODES/64, 256, NODE_SMEM>>>(hV, maskV, b3, binp, boutp, out);
}

// round 6
// speedup vs baseline: 2.4845x; 1.1195x over previous
#include <cuda_runtime.h>
#include <cuda_bf16.h>
#include <cstdint>

constexpr int Bc=4, Nn=2048, Kc=48, Hc=128, FFc=512;
constexpr int NODES = Bc*Nn;                 // 8192
constexpr int EDGE_ROWS = NODES*Kc;          // 393216
constexpr int ROWS_T = 128;                  // edge tile rows (per warpgroup)
constexpr int N_TILES = EDGE_ROWS/ROWS_T;    // 3072
constexpr float INV_SCALE = 1.0f/30.0f;

__device__ __nv_bfloat16 g_W3hi[Hc*Hc], g_W3lo[Hc*Hc];
__device__ __nv_bfloat16 g_WinHi[Hc*FFc], g_WinLo[Hc*FFc];
__device__ __nv_bfloat16 g_WoutHi[FFc*Hc], g_WoutLo[FFc*Hc];
__device__ __nv_bfloat16 g_P[NODES*Hc];      // hV @ W1a + b1 (bf16)
__device__ float g_s2[NODES*Hc];
__device__ float g_cnt[NODES];

// ---------------- low-level helpers ----------------
__device__ __forceinline__ uint32_t smem_u32(const void* p){
    uint32_t a; asm("{ .reg .u64 t; cvta.to.shared.u64 t, %1; cvt.u32.u64 %0, t; }":"=r"(a):"l"(p)); return a;
}
__device__ __forceinline__ void ldsm4(uint32_t* r, uint32_t addr){
    asm volatile("ldmatrix.sync.aligned.m8n8.x4.shared.b16 {%0,%1,%2,%3},[%4];"
        :"=r"(r[0]),"=r"(r[1]),"=r"(r[2]),"=r"(r[3]):"r"(addr));
}
__device__ __forceinline__ void ldsm4t(uint32_t* r, uint32_t addr){
    asm volatile("ldmatrix.sync.aligned.m8n8.x4.trans.shared.b16 {%0,%1,%2,%3},[%4];"
        :"=r"(r[0]),"=r"(r[1]),"=r"(r[2]),"=r"(r[3]):"r"(addr));
}
__device__ __forceinline__ void mma16816(float* d, const uint32_t* a, const uint32_t* b){
    asm volatile("mma.sync.aligned.m16n8k16.row.col.f32.bf16.bf16.f32 "
        "{%0,%1,%2,%3},{%4,%5,%6,%7},{%8,%9},{%0,%1,%2,%3};"
        :"+f"(d[0]),"+f"(d[1]),"+f"(d[2]),"+f"(d[3])
        :"r"(a[0]),"r"(a[1]),"r"(a[2]),"r"(a[3]),"r"(b[0]),"r"(b[1]));
}
#define BAR_WG(id) asm volatile("bar.sync %0, %1;"::"r"((id)),"r"(128):"memory")

__device__ __forceinline__ float gelu_fast(float x){
    float y = 0.7978845608028654f*x*(1.0f+0.044715f*x*x);
    float t; asm("tanh.approx.f32 %0, %1;":"=f"(t):"f"(y));
    return 0.5f*x*(1.0f+t);
}
__device__ __forceinline__ float gelu_erf_f(float x){ return x*normcdff(x); }

// ---------------- prep ----------------
__global__ void prep_kernel(const float* __restrict__ W3, const float* __restrict__ Win,
                            const float* __restrict__ Wout){
    int i = blockIdx.x*blockDim.x + threadIdx.x;  // 65536 threads
    if (i < Hc*FFc){
        float v=Win[i]; __nv_bfloat16 h=__float2bfloat16(v);
        g_WinHi[i]=h; g_WinLo[i]=__float2bfloat16(v-__bfloat162float(h));
        v=Wout[i]; h=__float2bfloat16(v);
        g_WoutHi[i]=h; g_WoutLo[i]=__float2bfloat16(v-__bfloat162float(h));
    }
    if (i < Hc*Hc){
        float v=W3[i]; __nv_bfloat16 h=__float2bfloat16(v);
        g_W3hi[i]=h; g_W3lo[i]=__float2bfloat16(v-__bfloat162float(h));
    }
    float4 z=make_float4(0.f,0.f,0.f,0.f);
    float4* s2=reinterpret_cast<float4*>(g_s2);
#pragma unroll
    for (int j=0;j<4;++j) s2[i*4+j]=z;
}

// ---------------- pre1: P = hV @ W1[0:128,:] + b1 (bf16), plus cnt ----------------
constexpr int P1_A = 0;          // 64*272 = 17408
constexpr int P1_W = 17408;      // 34816
constexpr int P1_B = 52224;      // 512
constexpr int P1_SMEM = 52736;

__global__ __launch_bounds__(256,1)
void pre1_kernel(const float* __restrict__ hV, const float* __restrict__ W1,
                 const float* __restrict__ b1, const float* __restrict__ mAtt){
    extern __shared__ __align__(16) char sm[];
    const int tid=threadIdx.x, wid=tid>>5, lane=tid&31;
    const int wm=wid&1, wn=wid>>1;          // 2 x 4 warp grid
    const int rowbase = blockIdx.x*64;
    const uint32_t smb=smem_u32(sm);
    float* b1s = reinterpret_cast<float*>(sm+P1_B);

    if (tid<128) b1s[tid]=b1[tid];
    // cnt for these 64 nodes
    if (tid<64){
        float s=0.f;
        const float* mrow = mAtt + (size_t)(rowbase+tid)*Kc;
#pragma unroll 12
        for (int k=0;k<Kc;++k) s+=mrow[k];
        g_cnt[rowbase+tid]=s;
    }
    // W1a rows 0..127 -> smem [k][n] stride 272
    for (int i=tid;i<128*128;i+=256){
        int k=i>>7, n=i&127;
        *reinterpret_cast<__nv_bfloat16*>(sm+P1_W+k*272+n*2) = __float2bfloat16(W1[k*128+n]);
    }
    // hV rows -> bf16 A stride 272
    for (int e=tid;e<64*32;e+=256){
        int r=e>>5, q=e&31;
        float4 v = reinterpret_cast<const float4*>(hV + (size_t)(rowbase+r)*Hc)[q];
        __nv_bfloat162 p0=__floats2bfloat162_rn(v.x,v.y), p1=__floats2bfloat162_rn(v.z,v.w);
        uint2 pk; pk.x=*reinterpret_cast<uint32_t*>(&p0); pk.y=*reinterpret_cast<uint32_t*>(&p1);
        *reinterpret_cast<uint2*>(sm + P1_A + r*272 + q*8) = pk;
    }
    __syncthreads();

    const uint32_t a_row = smb + P1_A + (uint32_t)((wm*32 + (lane&15))*272 + (lane>>4)*16);
    const uint32_t b_row = smb + P1_W + (uint32_t)((lane&15)*272 + (wn*32 + (lane>>4)*8)*2);

    float acc[2][4][4];
#pragma unroll
    for (int s=0;s<2;++s)
#pragma unroll
        for (int j=0;j<4;++j)
#pragma unroll
            for (int c=0;c<4;++c) acc[s][j][c]=0.f;
#pragma unroll
    for (int k=0;k<8;++k){
        uint32_t A[2][4], B[2][4];
#pragma unroll
        for (int s=0;s<2;++s) ldsm4(A[s], a_row + (uint32_t)(s*16*272 + k*32));
#pragma unroll
        for (int j2=0;j2<2;++j2) ldsm4t(B[j2], b_row + (uint32_t)(k*16*272 + j2*32));
#pragma unroll
        for (int s=0;s<2;++s)
#pragma unroll
            for (int j2=0;j2<2;++j2){
                mma16816(acc[s][2*j2],   A[s], B[j2]);
                mma16816(acc[s][2*j2+1], A[s], B[j2]+2);
            }
    }
    // P = acc + b1 -> bf16 gmem
#pragma unroll
    for (int s=0;s<2;++s){
        int r0 = wm*32 + s*16 + (lane>>2);
#pragma unroll
        for (int j=0;j<4;++j){
            int c = wn*32 + j*8 + 2*(lane&3);
#pragma unroll
            for (int half=0; half<2; ++half){
                int r = r0 + half*8;
                float v0 = acc[s][j][2*half]   + b1s[c];
                float v1 = acc[s][j][2*half+1] + b1s[c+1];
                __nv_bfloat162 p=__floats2bfloat162_rn(v0,v1);
                *reinterpret_cast<uint32_t*>(&g_P[(size_t)(rowbase+r)*Hc + c]) = *reinterpret_cast<uint32_t*>(&p);
            }
        }
    }
}

// ---------------- edge MLP: raw mma.sync, 2 warpgroups, P-precomputed ----------------
// per WG: A buf (128x136 bf16 s272) + P tile (128x136 bf16 s272); shared: W1b, W2, b2, masks
constexpr int OFF_A   = 0;          // 2 x 34816
constexpr int OFF_P   = 69632;      // 2 x 34816
constexpr int OFF_W1B = 139264;     // 34816
constexpr int OFF_W2  = 174080;     // 34816
constexpr int OFF_B2  = 208896;     // 512
constexpr int OFF_MSK = 209408;     // 2 x 512
constexpr int EDGE_SMEM = 210432;

__global__ __launch_bounds__(256,1)
void edge_mlp_mma(const float* __restrict__ hE,
                  const int* __restrict__ eidx, const float* __restrict__ mAtt,
                  const float* __restrict__ W1, const float* __restrict__ b2,
                  const float* __restrict__ W2){
    extern __shared__ __align__(16) char sm[];
    const int tid=threadIdx.x, wid=tid>>5, lane=tid&31;
    const int wg=wid>>2, wq=wid&3;
    const int wm=wq&1, wn=wq>>1;       // per-wg warp grid: 2 M-tiles(64) x 2 N-tiles(64)
    const int wg_tid=tid&127;
    const uint32_t smb=smem_u32(sm);
    float* b2s=reinterpret_cast<float*>(sm+OFF_B2);
    float* mask_s=reinterpret_cast<float*>(sm+OFF_MSK+wg*512);
    const int aoff = OFF_A + wg*34816;
    const int poff = OFF_P + wg*34816;

    // W1b = W1 rows 128..255 ([k][n], stride 272B); W2 ([k][n])
    for (int i=tid;i<128*128;i+=256){
        int k=i>>7, n=i&127;
        *reinterpret_cast<__nv_bfloat16*>(sm+OFF_W1B+k*272+n*2) = __float2bfloat16(W1[(128+k)*128+n]);
        *reinterpret_cast<__nv_bfloat16*>(sm+OFF_W2 +k*272+n*2) = __float2bfloat16(W2[k*128+n]);
    }
    if (tid<128) b2s[tid]=b2[tid];
    __syncthreads();

    float b2x[8],b2y[8];
#pragma unroll
    for (int j=0;j<8;++j){
        int c = wn*64 + j*8 + 2*(lane&3);
        b2x[j]=b2s[c]; b2y[j]=b2s[c+1];
    }

    const uint32_t a_base  = smb + aoff    + (uint32_t)((wm*64 + (lane&15))*272 + (lane>>4)*16);
    const uint32_t w1_base = smb + OFF_W1B + (uint32_t)((lane&15)*272 + (wn*64 + (lane>>4)*8)*2);
    const uint32_t w2_base = smb + OFF_W2  + (uint32_t)((lane&15)*272 + (wn*64 + (lane>>4)*8)*2);

    float acc[4][8][4];

    for (int t = blockIdx.x*2+wg; t < N_TILES; t += 296){
        const int ge_base = t*ROWS_T;
        BAR_WG(wg+1);   // previous tile fully consumed A + P + mask

        // ---- gather: hE row -> A; P[gathered node] -> Ptile; mask ----
        {
            const int ge = ge_base + wg_tid;
            const int node = ge / Kc;
            const int nb = eidx[ge];
            mask_s[wg_tid] = mAtt[ge];
            // P row (bf16, 256 B)
            const uint4* ps = reinterpret_cast<const uint4*>(g_P + ((size_t)((node>>11)<<11) + nb)*Hc);
            char* pdst = sm + poff + wg_tid*272;
#pragma unroll
            for (int q=0;q<16;++q)
                *reinterpret_cast<uint4*>(pdst + q*16) = ps[q];
            // hE row fp32 -> bf16
            const float4* src = reinterpret_cast<const float4*>(hE) + (size_t)ge*32;
            char* dst = sm + aoff + wg_tid*272;
#pragma unroll 8
            for (int q=0;q<32;++q){
                float4 v = src[q];
                __nv_bfloat162 p0=__floats2bfloat162_rn(v.x,v.y), p1=__floats2bfloat162_rn(v.z,v.w);
                uint2 pk; pk.x=*reinterpret_cast<uint32_t*>(&p0); pk.y=*reinterpret_cast<uint32_t*>(&p1);
                *reinterpret_cast<uint2*>(dst + q*8) = pk;
            }
        }
#pragma unroll
        for (int s=0;s<4;++s)
#pragma unroll
            for (int j=0;j<8;++j)
#pragma unroll
                for (int c=0;c<4;++c) acc[s][j][c]=0.f;
        BAR_WG(wg+1);

        // ---- GEMM1': hE x W1b (K=128) ----
#pragma unroll
        for (int k=0;k<8;++k){
            uint32_t A[4][4];
#pragma unroll
            for (int s=0;s<4;++s) ldsm4(A[s], a_base + (uint32_t)(s*16*272 + k*32));
#pragma unroll
            for (int j2=0;j2<4;++j2){
                uint32_t B[4];
                ldsm4t(B, w1_base + (uint32_t)(k*16*272 + j2*32));
#pragma unroll
                for (int s=0;s<4;++s){
                    mma16816(acc[s][2*j2],   A[s], B);
                    mma16816(acc[s][2*j2+1], A[s], B+2);
                }
            }
        }
        BAR_WG(wg+1);   // all wg warps done reading A before M1 overwrite

        // ---- epi1: M1 = gelu(acc + P) -> smem (reuse A buffer) ----
#pragma unroll
        for (int s=0;s<4;++s){
            int r0 = wm*64 + s*16 + (lane>>2);
#pragma unroll
            for (int j=0;j<8;++j){
                int col = wn*64 + j*8 + 2*(lane&3);
                __nv_bfloat162 pa = *reinterpret_cast<__nv_bfloat162*>(sm + poff + r0*272 + col*2);
                __nv_bfloat162 pb = *reinterpret_cast<__nv_bfloat162*>(sm + poff + (r0+8)*272 + col*2);
                float x0=gelu_fast(acc[s][j][0]+__bfloat162float(pa.x));
                float x1=gelu_fast(acc[s][j][1]+__bfloat162float(pa.y));
                float x2=gelu_fast(acc[s][j][2]+__bfloat162float(pb.x));
                float x3=gelu_fast(acc[s][j][3]+__bfloat162float(pb.y));
                __nv_bfloat162 p0=__floats2bfloat162_rn(x0,x1), p1=__floats2bfloat162_rn(x2,x3);
                *reinterpret_cast<uint32_t*>(sm + aoff + r0*272 + col*2)     = *reinterpret_cast<uint32_t*>(&p0);
                *reinterpret_cast<uint32_t*>(sm + aoff + (r0+8)*272 + col*2) = *reinterpret_cast<uint32_t*>(&p1);
            }
        }
#pragma unroll
        for (int s=0;s<4;++s)
#pragma unroll
            for (int j=0;j<8;++j)
#pragma unroll
                for (int c=0;c<4;++c) acc[s][j][c]=0.f;
        BAR_WG(wg+1);

        // ---- GEMM2: M1 (K=128) x W2 ----
#pragma unroll
        for (int k=0;k<8;++k){
            uint32_t A[4][4];
#pragma unroll
            for (int s=0;s<4;++s) ldsm4(A[s], a_base + (uint32_t)(s*16*272 + k*32));
#pragma unroll
            for (int j2=0;j2<4;++j2){
                uint32_t B[4];
                ldsm4t(B, w2_base + (uint32_t)(k*16*272 + j2*32));
#pragma unroll
                for (int s=0;s<4;++s){
                    mma16816(acc[s][2*j2],   A[s], B);
                    mma16816(acc[s][2*j2+1], A[s], B+2);
                }
            }
        }

        // ---- epi2: gelu(acc+b2)*mask, 16-row column sums -> g_s2 ----
#pragma unroll
        for (int s=0;s<4;++s){
            const int rloc = wm*64 + s*16;
            const int node = (ge_base + rloc)/Kc;
            const float mka = mask_s[rloc + (lane>>2)];
            const float mkb = mask_s[rloc + (lane>>2) + 8];
#pragma unroll
            for (int j=0;j<8;++j){
                float v0 = gelu_fast(acc[s][j][0]+b2x[j])*mka;
                float v1 = gelu_fast(acc[s][j][1]+b2y[j])*mka;
                float v2 = gelu_fast(acc[s][j][2]+b2x[j])*mkb;
                float v3 = gelu_fast(acc[s][j][3]+b2y[j])*mkb;
                float s0 = v0+v2, s1 = v1+v3;
                s0 += __shfl_xor_sync(0xffffffffu,s0,4);
                s0 += __shfl_xor_sync(0xffffffffu,s0,8);
                s0 += __shfl_xor_sync(0xffffffffu,s0,16);
                s1 += __shfl_xor_sync(0xffffffffu,s1,4);
                s1 += __shfl_xor_sync(0xffffffffu,s1,8);
                s1 += __shfl_xor_sync(0xffffffffu,s1,16);
                if (lane<4){
                    int col = wn*64 + j*8 + 2*lane;
                    atomicAdd(&g_s2[(size_t)node*Hc + col],   s0);
                    atomicAdd(&g_s2[(size_t)node*Hc + col+1], s1);
                }
            }
        }
    }
}

// ---------------- fused node kernel (unchanged from R5) ----------------
constexpr int NOFF_S2HI = 0;
constexpr int NOFF_S2LO = 17408;
constexpr int NOFF_HHI  = 34816;
constexpr int NOFF_HLO  = 52224;
constexpr int NOFF_W    = 69632;
constexpr int NOFF_B3   = 208896;
constexpr int NOFF_BIN  = 209408;
constexpr int NOFF_BOUT = 211456;
constexpr int NOFF_MV   = 211968;
constexpr int NOFF_CNT  = 212224;
constexpr int NODE_SMEM = 212480;

__global__ __launch_bounds__(256,1)
void node_kernel(const float* __restrict__ hV, const float* __restrict__ maskV,
                 const float* __restrict__ b3, const float* __restrict__ b_in,
                 const float* __restrict__ b_out, float* __restrict__ out){
    extern __shared__ __align__(16) char sm[];
    const int tid=threadIdx.x, wid=tid>>5, lane=tid&31;
    const int wm=wid&1, wn=wid>>1;
    const int rowbase = blockIdx.x*64;
    const uint32_t smb=smem_u32(sm);
    float* b3s  = reinterpret_cast<float*>(sm+NOFF_B3);
    float* bins = reinterpret_cast<float*>(sm+NOFF_BIN);
    float* bouts= reinterpret_cast<float*>(sm+NOFF_BOUT);
    float* mvs  = reinterpret_cast<float*>(sm+NOFF_MV);
    float* cnts = reinterpret_cast<float*>(sm+NOFF_CNT);

    if (tid<128) b3s[tid]=b3[tid];
    for (int i=tid;i<FFc;i+=256) bins[i]=b_in[i];
    if (tid>=128 && tid<256) bouts[tid-128]=b_out[tid-128];
    if (tid<64){ mvs[tid]=maskV[rowbase+tid]; cnts[tid]=g_cnt[rowbase+tid]; }

    for (int e=tid;e<64*32;e+=256){
        int r=e>>5, q=e&31;
        float4 v = reinterpret_cast<const float4*>(g_s2 + (size_t)(rowbase+r)*Hc)[q];
        __nv_bfloat16 hx=__float2bfloat16(v.x),hy=__float2bfloat16(v.y),
                      hz=__float2bfloat16(v.z),hw=__float2bfloat16(v.w);
        __nv_bfloat162 ph0=__halves2bfloat162(hx,hy), ph1=__halves2bfloat162(hz,hw);
        __nv_bfloat162 pl0=__floats2bfloat162_rn(v.x-__bfloat162float(hx),v.y-__bfloat162float(hy));
        __nv_bfloat162 pl1=__floats2bfloat162_rn(v.z-__bfloat162float(hz),v.w-__bfloat162float(hw));
        uint2 uh; uh.x=*reinterpret_cast<uint32_t*>(&ph0); uh.y=*reinterpret_cast<uint32_t*>(&ph1);
        uint2 ul; ul.x=*reinterpret_cast<uint32_t*>(&pl0); ul.y=*reinterpret_cast<uint32_t*>(&pl1);
        *reinterpret_cast<uint2*>(sm + NOFF_S2HI + r*272 + q*8) = uh;
        *reinterpret_cast<uint2*>(sm + NOFF_S2LO + r*272 + q*8) = ul;
    }
    for (int i=tid;i<128*128;i+=256){
        int r=i>>7,c=i&127;
        *reinterpret_cast<__nv_bfloat16*>(sm+NOFF_W+r*272+c*2)        = g_W3hi[i];
        *reinterpret_cast<__nv_bfloat16*>(sm+NOFF_W+34816+r*272+c*2)  = g_W3lo[i];
    }
    __syncthreads();

    const uint32_t a_row = (uint32_t)((wm*32 + (lane&15))*272 + (lane>>4)*16);
    const uint32_t b_row = (uint32_t)((lane&15)*272 + (wn*32 + (lane>>4)*8)*2);

    auto gemm3 = [&](float acc[2][4][4], uint32_t ahi, uint32_t alo, uint32_t bhi, uint32_t blo){
#pragma unroll
        for (int k=0;k<8;++k){
            uint32_t Ah[2][4], Al[2][4], Bh[2][4], Bl[2][4];
#pragma unroll
            for (int s=0;s<2;++s){
                ldsm4(Ah[s], ahi + (uint32_t)(s*16*272 + k*32));
                ldsm4(Al[s], alo + (uint32_t)(s*16*272 + k*32));
            }
#pragma unroll
            for (int j2=0;j2<2;++j2){
                ldsm4t(Bh[j2], bhi + (uint32_t)(k*16*272 + j2*32));
                ldsm4t(Bl[j2], blo + (uint32_t)(k*16*272 + j2*32));
            }
#pragma unroll
            for (int s=0;s<2;++s)
#pragma unroll
                for (int j2=0;j2<2;++j2){
                    mma16816(acc[s][2*j2],   Ah[s], Bh[j2]);
                    mma16816(acc[s][2*j2+1], Ah[s], Bh[j2]+2);
                    mma16816(acc[s][2*j2],   Ah[s], Bl[j2]);
                    mma16816(acc[s][2*j2+1], Ah[s], Bl[j2]+2);
                    mma16816(acc[s][2*j2],   Al[s], Bh[j2]);
                    mma16816(acc[s][2*j2+1], Al[s], Bh[j2]+2);
                }
        }
    };

    {
        float acc[2][4][4];
#pragma unroll
        for (int s=0;s<2;++s)
#pragma unroll
            for (int j=0;j<4;++j)
#pragma unroll
                for (int c=0;c<4;++c) acc[s][j][c]=0.f;
        gemm3(acc, smb+NOFF_S2HI+a_row, smb+NOFF_S2LO+a_row,
                   smb+NOFF_W+b_row,    smb+NOFF_W+34816+b_row);
#pragma unroll
        for (int s=0;s<2;++s){
            int r0 = wm*32 + s*16 + (lane>>2);
#pragma unroll
            for (int j=0;j<4;++j){
                int c = wn*32 + j*8 + 2*(lane&3);
#pragma unroll
                for (int half=0; half<2; ++half){
                    int r = r0 + half*8;
                    size_t gi = (size_t)(rowbase+r)*Hc + c;
                    float h0 = hV[gi]   + (acc[s][j][2*half]   + cnts[r]*b3s[c])  *INV_SCALE;
                    float h1 = hV[gi+1] + (acc[s][j][2*half+1] + cnts[r]*b3s[c+1])*INV_SCALE;
                    __nv_bfloat16 x0=__float2bfloat16(h0), x1=__float2bfloat16(h1);
                    __nv_bfloat162 ph=__halves2bfloat162(x0,x1);
                    __nv_bfloat162 pl=__floats2bfloat162_rn(h0-__bfloat162float(x0),h1-__bfloat162float(x1));
                    *reinterpret_cast<uint32_t*>(sm+NOFF_HHI+r*272+c*2)=*reinterpret_cast<uint32_t*>(&ph);
                    *reinterpret_cast<uint32_t*>(sm+NOFF_HLO+r*272+c*2)=*reinterpret_cast<uint32_t*>(&pl);
                }
            }
        }
    }

    float accO[2][4][4];
#pragma unroll
    for (int s=0;s<2;++s)
#pragma unroll
        for (int j=0;j<4;++j)
#pragma unroll
            for (int c=0;c<4;++c) accO[s][j][c]=0.f;

    for (int cc=0;cc<4;++cc){
        __syncthreads();
        for (int i=tid;i<128*128;i+=256){
            int r=i>>7,c=i&127;
            *reinterpret_cast<__nv_bfloat16*>(sm+NOFF_W+r*272+c*2)          = g_WinHi[r*FFc+cc*128+c];
            *reinterpret_cast<__nv_bfloat16*>(sm+NOFF_W+34816+r*272+c*2)    = g_WinLo[r*FFc+cc*128+c];
            *reinterpret_cast<__nv_bfloat16*>(sm+NOFF_W+69632+r*272+c*2)    = g_WoutHi[(cc*128+r)*Hc+c];
            *reinterpret_cast<__nv_bfloat16*>(sm+NOFF_W+104448+r*272+c*2)   = g_WoutLo[(cc*128+r)*Hc+c];
        }
        __syncthreads();

        float accM[2][4][4];
#pragma unroll
        for (int s=0;s<2;++s)
#pragma unroll
            for (int j=0;j<4;++j)
#pragma unroll
                for (int c=0;c<4;++c) accM[s][j][c]=0.f;
        gemm3(accM, smb+NOFF_HHI+a_row, smb+NOFF_HLO+a_row,
                    smb+NOFF_W+b_row,   smb+NOFF_W+34816+b_row);
#pragma unroll
        for (int s=0;s<2;++s){
            int r0 = wm*32 + s*16 + (lane>>2);
#pragma unroll
            for (int j=0;j<4;++j){
                int c = wn*32 + j*8 + 2*(lane&3);
#pragma unroll
                for (int half=0; half<2; ++half){
                    int r = r0 + half*8;
                    float v0 = gelu_erf_f(accM[s][j][2*half]   + bins[cc*128+c]);
                    float v1 = gelu_erf_f(accM[s][j][2*half+1] + bins[cc*128+c+1]);
                    __nv_bfloat16 x0=__float2bfloat16(v0), x1=__float2bfloat16(v1);
                    __nv_bfloat162 ph=__halves2bfloat162(x0,x1);
                    __nv_bfloat162 pl=__floats2bfloat162_rn(v0-__bfloat162float(x0),v1-__bfloat162float(x1));
                    *reinterpret_cast<uint32_t*>(sm+NOFF_S2HI+r*272+c*2)=*reinterpret_cast<uint32_t*>(&ph);
                    *reinterpret_cast<uint32_t*>(sm+NOFF_S2LO+r*272+c*2)=*reinterpret_cast<uint32_t*>(&pl);
                }
            }
        }
        __syncthreads();

        gemm3(accO, smb+NOFF_S2HI+a_row, smb+NOFF_S2LO+a_row,
                    smb+NOFF_W+69632+b_row, smb+NOFF_W+104448+b_row);
    }

#pragma unroll
    for (int s=0;s<2;++s){
        int r0 = wm*32 + s*16 + (lane>>2);
#pragma unroll
        for (int j=0;j<4;++j){
            int c = wn*32 + j*8 + 2*(lane&3);
#pragma unroll
            for (int half=0; half<2; ++half){
                int r = r0 + half*8;
                size_t gi = (size_t)(rowbase+r)*Hc + c;
                __nv_bfloat162 hh = *reinterpret_cast<__nv_bfloat162*>(sm+NOFF_HHI+r*272+c*2);
                __nv_bfloat162 hl = *reinterpret_cast<__nv_bfloat162*>(sm+NOFF_HLO+r*272+c*2);
                float h0 = __bfloat162float(hh.x)+__bfloat162float(hl.x);
                float h1 = __bfloat162float(hh.y)+__bfloat162float(hl.y);
                float mv = mvs[r];
                out[gi]   = (h0 + accO[s][j][2*half]   + bouts[c])  * mv;
                out[gi+1] = (h1 + accO[s][j][2*half+1] + bouts[c+1])* mv;
            }
        }
    }
}

// ---------------- launch ----------------
extern "C" void kernel_launch(void* const* d_in, const int* in_sizes, int n_in,
                              void* d_out, int out_size){
    (void)in_sizes; (void)n_in; (void)out_size;
    const float* hV   =(const float*)d_in[0];
    const float* hE   =(const float*)d_in[1];
    const int*   eidx =(const int*)d_in[2];
    const float* maskV=(const float*)d_in[3];
    const float* mAtt =(const float*)d_in[4];
    const float* W1   =(const float*)d_in[5];
    const float* b1   =(const float*)d_in[6];
    const float* W2   =(const float*)d_in[7];
    const float* b2   =(const float*)d_in[8];
    const float* W3   =(const float*)d_in[9];
    const float* b3   =(const float*)d_in[10];
    const float* Win  =(const float*)d_in[11];
    const float* binp =(const float*)d_in[12];
    const float* Wout =(const float*)d_in[13];
    const float* boutp=(const float*)d_in[14];
    float* out=(float*)d_out;

    cudaFuncSetAttribute(pre1_kernel, cudaFuncAttributeMaxDynamicSharedMemorySize, P1_SMEM);
    cudaFuncSetAttribute(edge_mlp_mma, cudaFuncAttributeMaxDynamicSharedMemorySize, EDGE_SMEM);
    cudaFuncSetAttribute(node_kernel, cudaFuncAttributeMaxDynamicSharedMemorySize, NODE_SMEM);

    prep_kernel<<<128, 512>>>(W3, Win, Wout);
    pre1_kernel<<<NODES/64, 256, P1_SMEM>>>(hV, W1, b1, mAtt);
    edge_mlp_mma<<<148, 256, EDGE_SMEM>>>(hE, eidx, mAtt, W1, b2, W2);
    node_kernel<<<NODES/64, 256, NODE_SMEM>>>(hV, maskV, b3, binp, boutp, out);
}

// round 7
// speedup vs baseline: 2.6513x; 1.0671x over previous
#include <cuda_runtime.h>
#include <cuda_bf16.h>
#include <cstdint>

constexpr int Bc=4, Nn=2048, Kc=48, Hc=128, FFc=512;
constexpr int NODES = Bc*Nn;                 // 8192
constexpr int EDGE_ROWS = NODES*Kc;          // 393216
constexpr int ROWS_T = 128;                  // edge tile rows (per warpgroup)
constexpr int N_TILES = EDGE_ROWS/ROWS_T;    // 3072
constexpr float INV_SCALE = 1.0f/30.0f;

__device__ __nv_bfloat16 g_W3hi[Hc*Hc], g_W3lo[Hc*Hc];
__device__ __nv_bfloat16 g_WinHi[Hc*FFc], g_WinLo[Hc*FFc];
__device__ __nv_bfloat16 g_WoutHi[FFc*Hc], g_WoutLo[FFc*Hc];
__device__ __nv_bfloat16 g_P[NODES*Hc];        // hV @ W1a + b1 (bf16)
__device__ __nv_bfloat16 g_hEb[EDGE_ROWS*Hc];  // hE pre-converted to bf16 (100 MB)
__device__ float g_s2[NODES*Hc];
__device__ float g_cnt[NODES];

// ---------------- low-level helpers ----------------
__device__ __forceinline__ uint32_t smem_u32(const void* p){
    uint32_t a; asm("{ .reg .u64 t; cvta.to.shared.u64 t, %1; cvt.u32.u64 %0, t; }":"=r"(a):"l"(p)); return a;
}
__device__ __forceinline__ void ldsm4(uint32_t* r, uint32_t addr){
    asm volatile("ldmatrix.sync.aligned.m8n8.x4.shared.b16 {%0,%1,%2,%3},[%4];"
        :"=r"(r[0]),"=r"(r[1]),"=r"(r[2]),"=r"(r[3]):"r"(addr));
}
__device__ __forceinline__ void ldsm4t(uint32_t* r, uint32_t addr){
    asm volatile("ldmatrix.sync.aligned.m8n8.x4.trans.shared.b16 {%0,%1,%2,%3},[%4];"
        :"=r"(r[0]),"=r"(r[1]),"=r"(r[2]),"=r"(r[3]):"r"(addr));
}
__device__ __forceinline__ void mma16816(float* d, const uint32_t* a, const uint32_t* b){
    asm volatile("mma.sync.aligned.m16n8k16.row.col.f32.bf16.bf16.f32 "
        "{%0,%1,%2,%3},{%4,%5,%6,%7},{%8,%9},{%0,%1,%2,%3};"
        :"+f"(d[0]),"+f"(d[1]),"+f"(d[2]),"+f"(d[3])
        :"r"(a[0]),"r"(a[1]),"r"(a[2]),"r"(a[3]),"r"(b[0]),"r"(b[1]));
}
__device__ __forceinline__ void cpasync16(uint32_t dst, const void* src){
    asm volatile("cp.async.cg.shared.global [%0],[%1],16;"::"r"(dst),"l"(src):"memory");
}
#define CP_COMMIT() asm volatile("cp.async.commit_group;":::"memory")
#define CP_WAIT0()  asm volatile("cp.async.wait_group 0;":::"memory")
#define BAR_WG(id) asm volatile("bar.sync %0, %1;"::"r"((id)),"r"(128):"memory")

__device__ __forceinline__ float gelu_fast(float x){
    float y = 0.7978845608028654f*x*(1.0f+0.044715f*x*x);
    float t; asm("tanh.approx.f32 %0, %1;":"=f"(t):"f"(y));
    return 0.5f*x*(1.0f+t);
}
__device__ __forceinline__ float gelu_erf_f(float x){ return x*normcdff(x); }

// ---------------- prep ----------------
__global__ void prep_kernel(const float* __restrict__ W3, const float* __restrict__ Win,
                            const float* __restrict__ Wout){
    int i = blockIdx.x*blockDim.x + threadIdx.x;  // 65536 threads
    if (i < Hc*FFc){
        float v=Win[i]; __nv_bfloat16 h=__float2bfloat16(v);
        g_WinHi[i]=h; g_WinLo[i]=__float2bfloat16(v-__bfloat162float(h));
        v=Wout[i]; h=__float2bfloat16(v);
        g_WoutHi[i]=h; g_WoutLo[i]=__float2bfloat16(v-__bfloat162float(h));
    }
    if (i < Hc*Hc){
        float v=W3[i]; __nv_bfloat16 h=__float2bfloat16(v);
        g_W3hi[i]=h; g_W3lo[i]=__float2bfloat16(v-__bfloat162float(h));
    }
    float4 z=make_float4(0.f,0.f,0.f,0.f);
    float4* s2=reinterpret_cast<float4*>(g_s2);
#pragma unroll
    for (int j=0;j<4;++j) s2[i*4+j]=z;
}

// ---------------- cvt: hE fp32 -> bf16 ----------------
__global__ __launch_bounds__(1024,2)
void cvt_hE_kernel(const float* __restrict__ hE){
    size_t i = (size_t)blockIdx.x*1024 + threadIdx.x;   // over EDGE_ROWS*Hc/4 = 12582912 float4
    float4 v = reinterpret_cast<const float4*>(hE)[i];
    __nv_bfloat162 p0=__floats2bfloat162_rn(v.x,v.y), p1=__floats2bfloat162_rn(v.z,v.w);
    uint2 pk; pk.x=*reinterpret_cast<uint32_t*>(&p0); pk.y=*reinterpret_cast<uint32_t*>(&p1);
    reinterpret_cast<uint2*>(g_hEb)[i] = pk;
}

// ---------------- pre1: P = hV @ W1[0:128,:] + b1 (bf16), plus cnt ----------------
constexpr int P1_A = 0;          // 64*272 = 17408
constexpr int P1_W = 17408;      // 34816
constexpr int P1_B = 52224;      // 512
constexpr int P1_SMEM = 52736;

__global__ __launch_bounds__(256,1)
void pre1_kernel(const float* __restrict__ hV, const float* __restrict__ W1,
                 const float* __restrict__ b1, const float* __restrict__ mAtt){
    extern __shared__ __align__(16) char sm[];
    const int tid=threadIdx.x, wid=tid>>5, lane=tid&31;
    const int wm=wid&1, wn=wid>>1;          // 2 x 4 warp grid
    const int rowbase = blockIdx.x*64;
    const uint32_t smb=smem_u32(sm);
    float* b1s = reinterpret_cast<float*>(sm+P1_B);

    if (tid<128) b1s[tid]=b1[tid];
    if (tid<64){
        float s=0.f;
        const float* mrow = mAtt + (size_t)(rowbase+tid)*Kc;
#pragma unroll 12
        for (int k=0;k<Kc;++k) s+=mrow[k];
        g_cnt[rowbase+tid]=s;
    }
    for (int i=tid;i<128*128;i+=256){
        int k=i>>7, n=i&127;
        *reinterpret_cast<__nv_bfloat16*>(sm+P1_W+k*272+n*2) = __float2bfloat16(W1[k*128+n]);
    }
    for (int e=tid;e<64*32;e+=256){
        int r=e>>5, q=e&31;
        float4 v = reinterpret_cast<const float4*>(hV + (size_t)(rowbase+r)*Hc)[q];
        __nv_bfloat162 p0=__floats2bfloat162_rn(v.x,v.y), p1=__floats2bfloat162_rn(v.z,v.w);
        uint2 pk; pk.x=*reinterpret_cast<uint32_t*>(&p0); pk.y=*reinterpret_cast<uint32_t*>(&p1);
        *reinterpret_cast<uint2*>(sm + P1_A + r*272 + q*8) = pk;
    }
    __syncthreads();

    const uint32_t a_row = smb + P1_A + (uint32_t)((wm*32 + (lane&15))*272 + (lane>>4)*16);
    const uint32_t b_row = smb + P1_W + (uint32_t)((lane&15)*272 + (wn*32 + (lane>>4)*8)*2);

    float acc[2][4][4];
#pragma unroll
    for (int s=0;s<2;++s)
#pragma unroll
        for (int j=0;j<4;++j)
#pragma unroll
            for (int c=0;c<4;++c) acc[s][j][c]=0.f;
#pragma unroll
    for (int k=0;k<8;++k){
        uint32_t A[2][4], B[2][4];
#pragma unroll
        for (int s=0;s<2;++s) ldsm4(A[s], a_row + (uint32_t)(s*16*272 + k*32));
#pragma unroll
        for (int j2=0;j2<2;++j2) ldsm4t(B[j2], b_row + (uint32_t)(k*16*272 + j2*32));
#pragma unroll
        for (int s=0;s<2;++s)
#pragma unroll
            for (int j2=0;j2<2;++j2){
                mma16816(acc[s][2*j2],   A[s], B[j2]);
                mma16816(acc[s][2*j2+1], A[s], B[j2]+2);
            }
    }
#pragma unroll
    for (int s=0;s<2;++s){
        int r0 = wm*32 + s*16 + (lane>>2);
#pragma unroll
        for (int j=0;j<4;++j){
            int c = wn*32 + j*8 + 2*(lane&3);
#pragma unroll
            for (int half=0; half<2; ++half){
                int r = r0 + half*8;
                float v0 = acc[s][j][2*half]   + b1s[c];
                float v1 = acc[s][j][2*half+1] + b1s[c+1];
                __nv_bfloat162 p=__floats2bfloat162_rn(v0,v1);
                *reinterpret_cast<uint32_t*>(&g_P[(size_t)(rowbase+r)*Hc + c]) = *reinterpret_cast<uint32_t*>(&p);
            }
        }
    }
}

// ---------------- edge MLP: raw mma.sync, 2 WGs, cp.async ping-pong pipeline ----------------
// per WG: 2 ping-pong buffers (128x136 bf16 s272 each); shared: W1b, W2, b2, masks(x2 parity)
constexpr int OFF_BUF = 0;          // 4 x 34816 = 139264 (wg*2 + parity)
constexpr int OFF_W1B = 139264;     // 34816
constexpr int OFF_W2  = 174080;     // 34816
constexpr int OFF_B2  = 208896;     // 512
constexpr int OFF_MSK = 209408;     // 2 wg x 2 parity x 512 = 2048
constexpr int EDGE_SMEM = 211456;

__global__ __launch_bounds__(256,1)
void edge_mlp_mma(const int* __restrict__ eidx, const float* __restrict__ mAtt,
                  const float* __restrict__ W1, const float* __restrict__ b2,
                  const float* __restrict__ W2){
    extern __shared__ __align__(16) char sm[];
    const int tid=threadIdx.x, wid=tid>>5, lane=tid&31;
    const int wg=wid>>2, wq=wid&3;
    const int wm=wq&1, wn=wq>>1;       // per-wg warp grid: 2 M-tiles(64) x 2 N-tiles(64)
    const int wg_tid=tid&127;
    const uint32_t smb=smem_u32(sm);
    float* b2s=reinterpret_cast<float*>(sm+OFF_B2);
    float* msk=reinterpret_cast<float*>(sm+OFF_MSK+wg*1024);   // [parity*128 + row]
    const int bufo = OFF_BUF + wg*69632;                       // + pb*34816

    // W1b = W1 rows 128..255 ([k][n], stride 272B); W2 ([k][n])
    for (int i=tid;i<128*128;i+=256){
        int k=i>>7, n=i&127;
        *reinterpret_cast<__nv_bfloat16*>(sm+OFF_W1B+k*272+n*2) = __float2bfloat16(W1[(128+k)*128+n]);
        *reinterpret_cast<__nv_bfloat16*>(sm+OFF_W2 +k*272+n*2) = __float2bfloat16(W2[k*128+n]);
    }
    if (tid<128) b2s[tid]=b2[tid];
    __syncthreads();

    float b2x[8],b2y[8];
#pragma unroll
    for (int j=0;j<8;++j){
        int c = wn*64 + j*8 + 2*(lane&3);
        b2x[j]=b2s[c]; b2y[j]=b2s[c+1];
    }

    const uint32_t a_off   = (uint32_t)((wm*64 + (lane&15))*272 + (lane>>4)*16);
    const uint32_t w1_base = smb + OFF_W1B + (uint32_t)((lane&15)*272 + (wn*64 + (lane>>4)*8)*2);
    const uint32_t w2_base = smb + OFF_W2  + (uint32_t)((lane&15)*272 + (wn*64 + (lane>>4)*8)*2);

    float acc[4][8][4];
    int pb=0, mp=0;
    const int t0 = blockIdx.x*2+wg;

    // ---- prologue: fetch tile t0 (hE -> buf0, P -> buf1, mask -> msk[0]) ----
    {
        const int ge = t0*ROWS_T + wg_tid;
        const int node = ge / Kc;
        const int nb = eidx[ge];
        msk[wg_tid] = mAtt[ge];
        const char* se = reinterpret_cast<const char*>(g_hEb) + (size_t)ge*256;
        uint32_t dE = smb + (uint32_t)(bufo + wg_tid*272);
#pragma unroll
        for (int q=0;q<16;++q) cpasync16(dE+q*16, se+q*16);
        const char* sp = reinterpret_cast<const char*>(g_P) + ((size_t)((node>>11)<<11) + nb)*256;
        uint32_t dP = smb + (uint32_t)(bufo + 34816 + wg_tid*272);
#pragma unroll
        for (int q=0;q<16;++q) cpasync16(dP+q*16, sp+q*16);
        CP_COMMIT();
        CP_WAIT0();
    }
    BAR_WG(wg+1);

    for (int t = t0; t < N_TILES; t += 296){
        const int ge_base = t*ROWS_T;
        const bool hn = (t+296) < N_TILES;
        const int aofft = bufo + pb*34816;          // A / M1 buffer
        const int pofft = bufo + (pb^1)*34816;      // P buffer
        const uint32_t a_base = smb + (uint32_t)aofft + a_off;

#pragma unroll
        for (int s=0;s<4;++s)
#pragma unroll
            for (int j=0;j<8;++j)
#pragma unroll
                for (int c=0;c<4;++c) acc[s][j][c]=0.f;

        // ---- GEMM1': hE x W1b (K=128) ----
#pragma unroll
        for (int k=0;k<8;++k){
            uint32_t A[4][4];
#pragma unroll
            for (int s=0;s<4;++s) ldsm4(A[s], a_base + (uint32_t)(s*16*272 + k*32));
#pragma unroll
            for (int j2=0;j2<4;++j2){
                uint32_t B[4];
                ldsm4t(B, w1_base + (uint32_t)(k*16*272 + j2*32));
#pragma unroll
                for (int s=0;s<4;++s){
                    mma16816(acc[s][2*j2],   A[s], B);
                    mma16816(acc[s][2*j2+1], A[s], B+2);
                }
            }
        }
        BAR_WG(wg+1);   // all wg warps done reading A before M1 overwrite

        // ---- epi1: M1 = gelu(acc + P) -> A buffer ----
#pragma unroll
        for (int s=0;s<4;++s){
            int r0 = wm*64 + s*16 + (lane>>2);
#pragma unroll
            for (int j=0;j<8;++j){
                int col = wn*64 + j*8 + 2*(lane&3);
                __nv_bfloat162 pa = *reinterpret_cast<__nv_bfloat162*>(sm + pofft + r0*272 + col*2);
                __nv_bfloat162 pb2 = *reinterpret_cast<__nv_bfloat162*>(sm + pofft + (r0+8)*272 + col*2);
                float x0=gelu_fast(acc[s][j][0]+__bfloat162float(pa.x));
                float x1=gelu_fast(acc[s][j][1]+__bfloat162float(pa.y));
                float x2=gelu_fast(acc[s][j][2]+__bfloat162float(pb2.x));
                float x3=gelu_fast(acc[s][j][3]+__bfloat162float(pb2.y));
                __nv_bfloat162 p0=__floats2bfloat162_rn(x0,x1), p1=__floats2bfloat162_rn(x2,x3);
                *reinterpret_cast<uint32_t*>(sm + aofft + r0*272 + col*2)     = *reinterpret_cast<uint32_t*>(&p0);
                *reinterpret_cast<uint32_t*>(sm + aofft + (r0+8)*272 + col*2) = *reinterpret_cast<uint32_t*>(&p1);
            }
        }
#pragma unroll
        for (int s=0;s<4;++s)
#pragma unroll
            for (int j=0;j<8;++j)
#pragma unroll
                for (int c=0;c<4;++c) acc[s][j][c]=0.f;
        BAR_WG(wg+1);   // M1 visible; P buffer free

        // ---- prefetch next tile's hE into freed P buffer ----
        int node_n=0, nb_n=0;
        if (hn){
            const int ge_n = (t+296)*ROWS_T + wg_tid;
            node_n = ge_n / Kc;
            nb_n = eidx[ge_n];
            msk[(mp^1)*128 + wg_tid] = mAtt[ge_n];
            const char* se = reinterpret_cast<const char*>(g_hEb) + (size_t)ge_n*256;
            uint32_t dE = smb + (uint32_t)(pofft + wg_tid*272);
#pragma unroll
            for (int q=0;q<16;++q) cpasync16(dE+q*16, se+q*16);
            CP_COMMIT();
        }

        // ---- GEMM2: M1 (K=128) x W2 ----
#pragma unroll
        for (int k=0;k<8;++k){
            uint32_t A[4][4];
#pragma unroll
            for (int s=0;s<4;++s) ldsm4(A[s], a_base + (uint32_t)(s*16*272 + k*32));
#pragma unroll
            for (int j2=0;j2<4;++j2){
                uint32_t B[4];
                ldsm4t(B, w2_base + (uint32_t)(k*16*272 + j2*32));
#pragma unroll
                for (int s=0;s<4;++s){
                    mma16816(acc[s][2*j2],   A[s], B);
                    mma16816(acc[s][2*j2+1], A[s], B+2);
                }
            }
        }
        BAR_WG(wg+1);   // all wg warps done with M1 buffer

        // ---- prefetch next tile's P into freed M1 buffer ----
        if (hn){
            const char* sp = reinterpret_cast<const char*>(g_P) + ((size_t)((node_n>>11)<<11) + nb_n)*256;
            uint32_t dP = smb + (uint32_t)(aofft + wg_tid*272);
#pragma unroll
            for (int q=0;q<16;++q) cpasync16(dP+q*16, sp+q*16);
            CP_COMMIT();
        }

        // ---- epi2: gelu(acc+b2)*mask, 16-row column sums -> g_s2 ----
#pragma unroll
        for (int s=0;s<4;++s){
            const int rloc = wm*64 + s*16;
            const int node = (ge_base + rloc)/Kc;
            const float mka = msk[mp*128 + rloc + (lane>>2)];
            const float mkb = msk[mp*128 + rloc + (lane>>2) + 8];
#pragma unroll
            for (int j=0;j<8;++j){
                float v0 = gelu_fast(acc[s][j][0]+b2x[j])*mka;
                float v1 = gelu_fast(acc[s][j][1]+b2y[j])*mka;
                float v2 = gelu_fast(acc[s][j][2]+b2x[j])*mkb;
                float v3 = gelu_fast(acc[s][j][3]+b2y[j])*mkb;
                float s0 = v0+v2, s1 = v1+v3;
                s0 += __shfl_xor_sync(0xffffffffu,s0,4);
                s0 += __shfl_xor_sync(0xffffffffu,s0,8);
                s0 += __shfl_xor_sync(0xffffffffu,s0,16);
                s1 += __shfl_xor_sync(0xffffffffu,s1,4);
                s1 += __shfl_xor_sync(0xffffffffu,s1,8);
                s1 += __shfl_xor_sync(0xffffffffu,s1,16);
                if (lane<4){
                    int col = wn*64 + j*8 + 2*lane;
                    atomicAdd(&g_s2[(size_t)node*Hc + col],   s0);
                    atomicAdd(&g_s2[(size_t)node*Hc + col+1], s1);
                }
            }
        }

        CP_WAIT0();
        BAR_WG(wg+1);
        pb ^= 1; mp ^= 1;
    }
}

// ---------------- fused node kernel ----------------
constexpr int NOFF_S2HI = 0;
constexpr int NOFF_S2LO = 17408;
constexpr int NOFF_HHI  = 34816;
constexpr int NOFF_HLO  = 52224;
constexpr int NOFF_W    = 69632;
constexpr int NOFF_B3   = 208896;
constexpr int NOFF_BIN  = 209408;
constexpr int NOFF_BOUT = 211456;
constexpr int NOFF_MV   = 211968;
constexpr int NOFF_CNT  = 212224;
constexpr int NODE_SMEM = 212480;

__global__ __launch_bounds__(256,1)
void node_kernel(const float* __restrict__ hV, const float* __restrict__ maskV,
                 const float* __restrict__ b3, const float* __restrict__ b_in,
                 const float* __restrict__ b_out, float* __restrict__ out){
    extern __shared__ __align__(16) char sm[];
    const int tid=threadIdx.x, wid=tid>>5, lane=tid&31;
    const int wm=wid&1, wn=wid>>1;
    const int rowbase = blockIdx.x*64;
    const uint32_t smb=smem_u32(sm);
    float* b3s  = reinterpret_cast<float*>(sm+NOFF_B3);
    float* bins = reinterpret_cast<float*>(sm+NOFF_BIN);
    float* bouts= reinterpret_cast<float*>(sm+NOFF_BOUT);
    float* mvs  = reinterpret_cast<float*>(sm+NOFF_MV);
    float* cnts = reinterpret_cast<float*>(sm+NOFF_CNT);

    if (tid<128) b3s[tid]=b3[tid];
    for (int i=tid;i<FFc;i+=256) bins[i]=b_in[i];
    if (tid>=128 && tid<256) bouts[tid-128]=b_out[tid-128];
    if (tid<64){ mvs[tid]=maskV[rowbase+tid]; cnts[tid]=g_cnt[rowbase+tid]; }

    for (int e=tid;e<64*32;e+=256){
        int r=e>>5, q=e&31;
        float4 v = reinterpret_cast<const float4*>(g_s2 + (size_t)(rowbase+r)*Hc)[q];
        __nv_bfloat16 hx=__float2bfloat16(v.x),hy=__float2bfloat16(v.y),
                      hz=__float2bfloat16(v.z),hw=__float2bfloat16(v.w);
        __nv_bfloat162 ph0=__halves2bfloat162(hx,hy), ph1=__halves2bfloat162(hz,hw);
        __nv_bfloat162 pl0=__floats2bfloat162_rn(v.x-__bfloat162float(hx),v.y-__bfloat162float(hy));
        __nv_bfloat162 pl1=__floats2bfloat162_rn(v.z-__bfloat162float(hz),v.w-__bfloat162float(hw));
        uint2 uh; uh.x=*reinterpret_cast<uint32_t*>(&ph0); uh.y=*reinterpret_cast<uint32_t*>(&ph1);
        uint2 ul; ul.x=*reinterpret_cast<uint32_t*>(&pl0); ul.y=*reinterpret_cast<uint32_t*>(&pl1);
        *reinterpret_cast<uint2*>(sm + NOFF_S2HI + r*272 + q*8) = uh;
        *reinterpret_cast<uint2*>(sm + NOFF_S2LO + r*272 + q*8) = ul;
    }
    // W3 hi/lo (vectorized: 256B rows)
    for (int i=tid;i<128*16;i+=256){
        int r=i>>4, q=i&15;
        *reinterpret_cast<uint4*>(sm+NOFF_W+r*272+q*16)       = *reinterpret_cast<const uint4*>(g_W3hi + r*Hc + q*8);
        *reinterpret_cast<uint4*>(sm+NOFF_W+34816+r*272+q*16) = *reinterpret_cast<const uint4*>(g_W3lo + r*Hc + q*8);
    }
    __syncthreads();

    const uint32_t a_row = (uint32_t)((wm*32 + (lane&15))*272 + (lane>>4)*16);
    const uint32_t b_row = (uint32_t)((lane&15)*272 + (wn*32 + (lane>>4)*8)*2);

    auto gemm3 = [&](float acc[2][4][4], uint32_t ahi, uint32_t alo, uint32_t bhi, uint32_t blo){
#pragma unroll
        for (int k=0;k<8;++k){
            uint32_t Ah[2][4], Al[2][4], Bh[2][4], Bl[2][4];
#pragma unroll
            for (int s=0;s<2;++s){
                ldsm4(Ah[s], ahi + (uint32_t)(s*16*272 + k*32));
                ldsm4(Al[s], alo + (uint32_t)(s*16*272 + k*32));
            }
#pragma unroll
            for (int j2=0;j2<2;++j2){
                ldsm4t(Bh[j2], bhi + (uint32_t)(k*16*272 + j2*32));
                ldsm4t(Bl[j2], blo + (uint32_t)(k*16*272 + j2*32));
            }
#pragma unroll
            for (int s=0;s<2;++s)
#pragma unroll
                for (int j2=0;j2<2;++j2){
                    mma16816(acc[s][2*j2],   Ah[s], Bh[j2]);
                    mma16816(acc[s][2*j2+1], Ah[s], Bh[j2]+2);
                    mma16816(acc[s][2*j2],   Ah[s], Bl[j2]);
                    mma16816(acc[s][2*j2+1], Ah[s], Bl[j2]+2);
                    mma16816(acc[s][2*j2],   Al[s], Bh[j2]);
                    mma16816(acc[s][2*j2+1], Al[s], Bh[j2]+2);
                }
        }
    };

    {
        float acc[2][4][4];
#pragma unroll
        for (int s=0;s<2;++s)
#pragma unroll
            for (int j=0;j<4;++j)
#pragma unroll
                for (int c=0;c<4;++c) acc[s][j][c]=0.f;
        gemm3(acc, smb+NOFF_S2HI+a_row, smb+NOFF_S2LO+a_row,
                   smb+NOFF_W+b_row,    smb+NOFF_W+34816+b_row);
#pragma unroll
        for (int s=0;s<2;++s){
            int r0 = wm*32 + s*16 + (lane>>2);
#pragma unroll
            for (int j=0;j<4;++j){
                int c = wn*32 + j*8 + 2*(lane&3);
#pragma unroll
                for (int half=0; half<2; ++half){
                    int r = r0 + half*8;
                    size_t gi = (size_t)(rowbase+r)*Hc + c;
                    float h0 = hV[gi]   + (acc[s][j][2*half]   + cnts[r]*b3s[c])  *INV_SCALE;
                    float h1 = hV[gi+1] + (acc[s][j][2*half+1] + cnts[r]*b3s[c+1])*INV_SCALE;
                    __nv_bfloat16 x0=__float2bfloat16(h0), x1=__float2bfloat16(h1);
                    __nv_bfloat162 ph=__halves2bfloat162(x0,x1);
                    __nv_bfloat162 pl=__floats2bfloat162_rn(h0-__bfloat162float(x0),h1-__bfloat162float(x1));
                    *reinterpret_cast<uint32_t*>(sm+NOFF_HHI+r*272+c*2)=*reinterpret_cast<uint32_t*>(&ph);
                    *reinterpret_cast<uint32_t*>(sm+NOFF_HLO+r*272+c*2)=*reinterpret_cast<uint32_t*>(&pl);
                }
            }
        }
    }

    float accO[2][4][4];
#pragma unroll
    for (int s=0;s<2;++s)
#pragma unroll
        for (int j=0;j<4;++j)
#pragma unroll
            for (int c=0;c<4;++c) accO[s][j][c]=0.f;

    for (int cc=0;cc<4;++cc){
        __syncthreads();
        // vectorized weight chunk copy (256B rows)
        for (int i=tid;i<128*16;i+=256){
            int r=i>>4, q=i&15;
            *reinterpret_cast<uint4*>(sm+NOFF_W+r*272+q*16)        = *reinterpret_cast<const uint4*>(g_WinHi + r*FFc + cc*128 + q*8);
            *reinterpret_cast<uint4*>(sm+NOFF_W+34816+r*272+q*16)  = *reinterpret_cast<const uint4*>(g_WinLo + r*FFc + cc*128 + q*8);
            *reinterpret_cast<uint4*>(sm+NOFF_W+69632+r*272+q*16)  = *reinterpret_cast<const uint4*>(g_WoutHi + (size_t)(cc*128+r)*Hc + q*8);
            *reinterpret_cast<uint4*>(sm+NOFF_W+104448+r*272+q*16) = *reinterpret_cast<const uint4*>(g_WoutLo + (size_t)(cc*128+r)*Hc + q*8);
        }
        __syncthreads();

        float accM[2][4][4];
#pragma unroll
        for (int s=0;s<2;++s)
#pragma unroll
            for (int j=0;j<4;++j)
#pragma unroll
                for (int c=0;c<4;++c) accM[s][j][c]=0.f;
        gemm3(accM, smb+NOFF_HHI+a_row, smb+NOFF_HLO+a_row,
                    smb+NOFF_W+b_row,   smb+NOFF_W+34816+b_row);
#pragma unroll
        for (int s=0;s<2;++s){
            int r0 = wm*32 + s*16 + (lane>>2);
#pragma unroll
            for (int j=0;j<4;++j){
                int c = wn*32 + j*8 + 2*(lane&3);
#pragma unroll
                for (int half=0; half<2; ++half){
                    int r = r0 + half*8;
                    float v0 = gelu_erf_f(accM[s][j][2*half]   + bins[cc*128+c]);
                    float v1 = gelu_erf_f(accM[s][j][2*half+1] + bins[cc*128+c+1]);
                    __nv_bfloat16 x0=__float2bfloat16(v0), x1=__float2bfloat16(v1);
                    __nv_bfloat162 ph=__halves2bfloat162(x0,x1);
                    __nv_bfloat162 pl=__floats2bfloat162_rn(v0-__bfloat162float(x0),v1-__bfloat162float(x1));
                    *reinterpret_cast<uint32_t*>(sm+NOFF_S2HI+r*272+c*2)=*reinterpret_cast<uint32_t*>(&ph);
                    *reinterpret_cast<uint32_t*>(sm+NOFF_S2LO+r*272+c*2)=*reinterpret_cast<uint32_t*>(&pl);
                }
            }
        }
        __syncthreads();

        gemm3(accO, smb+NOFF_S2HI+a_row, smb+NOFF_S2LO+a_row,
                    smb+NOFF_W+69632+b_row, smb+NOFF_W+104448+b_row);
    }

#pragma unroll
    for (int s=0;s<2;++s){
        int r0 = wm*32 + s*16 + (lane>>2);
#pragma unroll
        for (int j=0;j<4;++j){
            int c = wn*32 + j*8 + 2*(lane&3);
#pragma unroll
            for (int half=0; half<2; ++half){
                int r = r0 + half*8;
                size_t gi = (size_t)(rowbase+r)*Hc + c;
                __nv_bfloat162 hh = *reinterpret_cast<__nv_bfloat162*>(sm+NOFF_HHI+r*272+c*2);
                __nv_bfloat162 hl = *reinterpret_cast<__nv_bfloat162*>(sm+NOFF_HLO+r*272+c*2);
                float h0 = __bfloat162float(hh.x)+__bfloat162float(hl.x);
                float h1 = __bfloat162float(hh.y)+__bfloat162float(hl.y);
                float mv = mvs[r];
                out[gi]   = (h0 + accO[s][j][2*half]   + bouts[c])  * mv;
                out[gi+1] = (h1 + accO[s][j][2*half+1] + bouts[c+1])* mv;
            }
        }
    }
}

// ---------------- launch ----------------
extern "C" void kernel_launch(void* const* d_in, const int* in_sizes, int n_in,
                              void* d_out, int out_size){
    (void)in_sizes; (void)n_in; (void)out_size;
    const float* hV   =(const float*)d_in[0];
    const float* hE   =(const float*)d_in[1];
    const int*   eidx =(const int*)d_in[2];
    const float* maskV=(const float*)d_in[3];
    const float* mAtt =(const float*)d_in[4];
    const float* W1   =(const float*)d_in[5];
    const float* b1   =(const float*)d_in[6];
    const float* W2   =(const float*)d_in[7];
    const float* b2   =(const float*)d_in[8];
    const float* W3   =(const float*)d_in[9];
    const float* b3   =(const float*)d_in[10];
    const float* Win  =(const float*)d_in[11];
    const float* binp =(const float*)d_in[12];
    const float* Wout =(const float*)d_in[13];
    const float* boutp=(const float*)d_in[14];
    float* out=(float*)d_out;

    cudaFuncSetAttribute(pre1_kernel, cudaFuncAttributeMaxDynamicSharedMemorySize, P1_SMEM);
    cudaFuncSetAttribute(edge_mlp_mma, cudaFuncAttributeMaxDynamicSharedMemorySize, EDGE_SMEM);
    cudaFuncSetAttribute(node_kernel, cudaFuncAttributeMaxDynamicSharedMemorySize, NODE_SMEM);

    prep_kernel<<<128, 512>>>(W3, Win, Wout);
    cvt_hE_kernel<<<EDGE_ROWS*Hc/4096, 1024>>>(hE);
    pre1_kernel<<<NODES/64, 256, P1_SMEM>>>(hV, W1, b1, mAtt);
    edge_mlp_mma<<<148, 256, EDGE_SMEM>>>(eidx, mAtt, W1, b2, W2);
    node_kernel<<<NODES/64, 256, NODE_SMEM>>>(hV, maskV, b3, binp, boutp, out);
}

// round 8
// speedup vs baseline: 2.8217x; 1.0643x over previous
#include <cuda_runtime.h>
#include <cuda_bf16.h>
#include <cstdint>

constexpr int Bc=4, Nn=2048, Kc=48, Hc=128, FFc=512;
constexpr int NODES = Bc*Nn;                 // 8192
constexpr int EDGE_ROWS = NODES*Kc;          // 393216
constexpr int ROWS_T = 64;                   // edge tile rows (per warpgroup)
constexpr int N_TILES = EDGE_ROWS/ROWS_T;    // 6144
constexpr int N_STREAMS = 148*3;             // 444
constexpr float INV_SCALE = 1.0f/30.0f;

__device__ __nv_bfloat16 g_W3hi[Hc*Hc], g_W3lo[Hc*Hc];
__device__ __nv_bfloat16 g_WinHi[Hc*FFc], g_WinLo[Hc*FFc];
__device__ __nv_bfloat16 g_WoutHi[FFc*Hc], g_WoutLo[FFc*Hc];
__device__ __nv_bfloat16 g_P[NODES*Hc];        // hV @ W1a + b1 (bf16)
__device__ __nv_bfloat16 g_hEb[EDGE_ROWS*Hc];  // hE pre-converted to bf16
__device__ float g_s2[NODES*Hc];
__device__ float g_cnt[NODES];

// ---------------- low-level helpers ----------------
__device__ __forceinline__ uint32_t smem_u32(const void* p){
    uint32_t a; asm("{ .reg .u64 t; cvta.to.shared.u64 t, %1; cvt.u32.u64 %0, t; }":"=r"(a):"l"(p)); return a;
}
__device__ __forceinline__ void ldsm4(uint32_t* r, uint32_t addr){
    asm volatile("ldmatrix.sync.aligned.m8n8.x4.shared.b16 {%0,%1,%2,%3},[%4];"
        :"=r"(r[0]),"=r"(r[1]),"=r"(r[2]),"=r"(r[3]):"r"(addr));
}
__device__ __forceinline__ void ldsm4t(uint32_t* r, uint32_t addr){
    asm volatile("ldmatrix.sync.aligned.m8n8.x4.trans.shared.b16 {%0,%1,%2,%3},[%4];"
        :"=r"(r[0]),"=r"(r[1]),"=r"(r[2]),"=r"(r[3]):"r"(addr));
}
__device__ __forceinline__ void mma16816(float* d, const uint32_t* a, const uint32_t* b){
    asm volatile("mma.sync.aligned.m16n8k16.row.col.f32.bf16.bf16.f32 "
        "{%0,%1,%2,%3},{%4,%5,%6,%7},{%8,%9},{%0,%1,%2,%3};"
        :"+f"(d[0]),"+f"(d[1]),"+f"(d[2]),"+f"(d[3])
        :"r"(a[0]),"r"(a[1]),"r"(a[2]),"r"(a[3]),"r"(b[0]),"r"(b[1]));
}
__device__ __forceinline__ void cpasync16(uint32_t dst, const void* src){
    asm volatile("cp.async.cg.shared.global [%0],[%1],16;"::"r"(dst),"l"(src):"memory");
}
#define CP_COMMIT() asm volatile("cp.async.commit_group;":::"memory")
#define CP_WAIT0()  asm volatile("cp.async.wait_group 0;":::"memory")
#define BAR_WG(id) asm volatile("bar.sync %0, %1;"::"r"((id)),"r"(128):"memory")

__device__ __forceinline__ float gelu_fast(float x){
    float y = 0.7978845608028654f*x*(1.0f+0.044715f*x*x);
    float t; asm("tanh.approx.f32 %0, %1;":"=f"(t):"f"(y));
    return 0.5f*x*(1.0f+t);
}
__device__ __forceinline__ float gelu_erf_f(float x){ return x*normcdff(x); }

// ---------------- prep ----------------
__global__ void prep_kernel(const float* __restrict__ W3, const float* __restrict__ Win,
                            const float* __restrict__ Wout){
    int i = blockIdx.x*blockDim.x + threadIdx.x;  // 65536 threads
    if (i < Hc*FFc){
        float v=Win[i]; __nv_bfloat16 h=__float2bfloat16(v);
        g_WinHi[i]=h; g_WinLo[i]=__float2bfloat16(v-__bfloat162float(h));
        v=Wout[i]; h=__float2bfloat16(v);
        g_WoutHi[i]=h; g_WoutLo[i]=__float2bfloat16(v-__bfloat162float(h));
    }
    if (i < Hc*Hc){
        float v=W3[i]; __nv_bfloat16 h=__float2bfloat16(v);
        g_W3hi[i]=h; g_W3lo[i]=__float2bfloat16(v-__bfloat162float(h));
    }
    float4 z=make_float4(0.f,0.f,0.f,0.f);
    float4* s2=reinterpret_cast<float4*>(g_s2);
#pragma unroll
    for (int j=0;j<4;++j) s2[i*4+j]=z;
}

// ---------------- cvt: hE fp32 -> bf16 ----------------
__global__ __launch_bounds__(1024,2)
void cvt_hE_kernel(const float* __restrict__ hE){
    size_t i = (size_t)blockIdx.x*1024 + threadIdx.x;
    float4 v = reinterpret_cast<const float4*>(hE)[i];
    __nv_bfloat162 p0=__floats2bfloat162_rn(v.x,v.y), p1=__floats2bfloat162_rn(v.z,v.w);
    uint2 pk; pk.x=*reinterpret_cast<uint32_t*>(&p0); pk.y=*reinterpret_cast<uint32_t*>(&p1);
    reinterpret_cast<uint2*>(g_hEb)[i] = pk;
}

// ---------------- pre1: P = hV @ W1[0:128,:] + b1 (bf16), plus cnt ----------------
constexpr int P1_A = 0;
constexpr int P1_W = 17408;
constexpr int P1_B = 52224;
constexpr int P1_SMEM = 52736;

__global__ __launch_bounds__(256,1)
void pre1_kernel(const float* __restrict__ hV, const float* __restrict__ W1,
                 const float* __restrict__ b1, const float* __restrict__ mAtt){
    extern __shared__ __align__(16) char sm[];
    const int tid=threadIdx.x, wid=tid>>5, lane=tid&31;
    const int wm=wid&1, wn=wid>>1;
    const int rowbase = blockIdx.x*64;
    const uint32_t smb=smem_u32(sm);
    float* b1s = reinterpret_cast<float*>(sm+P1_B);

    if (tid<128) b1s[tid]=b1[tid];
    if (tid<64){
        float s=0.f;
        const float* mrow = mAtt + (size_t)(rowbase+tid)*Kc;
#pragma unroll 12
        for (int k=0;k<Kc;++k) s+=mrow[k];
        g_cnt[rowbase+tid]=s;
    }
    for (int i=tid;i<128*128;i+=256){
        int k=i>>7, n=i&127;
        *reinterpret_cast<__nv_bfloat16*>(sm+P1_W+k*272+n*2) = __float2bfloat16(W1[k*128+n]);
    }
    for (int e=tid;e<64*32;e+=256){
        int r=e>>5, q=e&31;
        float4 v = reinterpret_cast<const float4*>(hV + (size_t)(rowbase+r)*Hc)[q];
        __nv_bfloat162 p0=__floats2bfloat162_rn(v.x,v.y), p1=__floats2bfloat162_rn(v.z,v.w);
        uint2 pk; pk.x=*reinterpret_cast<uint32_t*>(&p0); pk.y=*reinterpret_cast<uint32_t*>(&p1);
        *reinterpret_cast<uint2*>(sm + P1_A + r*272 + q*8) = pk;
    }
    __syncthreads();

    const uint32_t a_row = smb + P1_A + (uint32_t)((wm*32 + (lane&15))*272 + (lane>>4)*16);
    const uint32_t b_row = smb + P1_W + (uint32_t)((lane&15)*272 + (wn*32 + (lane>>4)*8)*2);

    float acc[2][4][4];
#pragma unroll
    for (int s=0;s<2;++s)
#pragma unroll
        for (int j=0;j<4;++j)
#pragma unroll
            for (int c=0;c<4;++c) acc[s][j][c]=0.f;
#pragma unroll
    for (int k=0;k<8;++k){
        uint32_t A[2][4], B[2][4];
#pragma unroll
        for (int s=0;s<2;++s) ldsm4(A[s], a_row + (uint32_t)(s*16*272 + k*32));
#pragma unroll
        for (int j2=0;j2<2;++j2) ldsm4t(B[j2], b_row + (uint32_t)(k*16*272 + j2*32));
#pragma unroll
        for (int s=0;s<2;++s)
#pragma unroll
            for (int j2=0;j2<2;++j2){
                mma16816(acc[s][2*j2],   A[s], B[j2]);
                mma16816(acc[s][2*j2+1], A[s], B[j2]+2);
            }
    }
#pragma unroll
    for (int s=0;s<2;++s){
        int r0 = wm*32 + s*16 + (lane>>2);
#pragma unroll
        for (int j=0;j<4;++j){
            int c = wn*32 + j*8 + 2*(lane&3);
#pragma unroll
            for (int half=0; half<2; ++half){
                int r = r0 + half*8;
                float v0 = acc[s][j][2*half]   + b1s[c];
                float v1 = acc[s][j][2*half+1] + b1s[c+1];
                __nv_bfloat162 p=__floats2bfloat162_rn(v0,v1);
                *reinterpret_cast<uint32_t*>(&g_P[(size_t)(rowbase+r)*Hc + c]) = *reinterpret_cast<uint32_t*>(&p);
            }
        }
    }
}

// ---------------- edge MLP: 3 warpgroups x 64-row tiles, cp.async ping-pong ----------------
// per WG: 2 ping-pong buffers (64x136 bf16 s272 = 17408B each); shared: W1b, W2, b2, masks
constexpr int OFF_BUF = 0;          // 3 wg x 2 x 17408 = 104448
constexpr int OFF_W1B = 104448;     // 34816
constexpr int OFF_W2  = 139264;     // 34816
constexpr int OFF_B2  = 174080;     // 512
constexpr int OFF_MSK = 174592;     // 3 wg x 2 parity x 64 x 4 = 1536
constexpr int EDGE_SMEM = 176128;

__global__ __launch_bounds__(384,1)
void edge_mlp_mma(const int* __restrict__ eidx, const float* __restrict__ mAtt,
                  const float* __restrict__ W1, const float* __restrict__ b2,
                  const float* __restrict__ W2){
    extern __shared__ __align__(16) char sm[];
    const int tid=threadIdx.x, wid=tid>>5, lane=tid&31;
    const int wg=wid>>2, wn=wid&3;     // 3 WGs; warp tile M=64 x N=32 (wn = N tile)
    const int wg_tid=tid&127;
    const uint32_t smb=smem_u32(sm);
    float* b2s=reinterpret_cast<float*>(sm+OFF_B2);
    float* msk=reinterpret_cast<float*>(sm+OFF_MSK+wg*512);   // [parity*64 + row]
    const int bufo = OFF_BUF + wg*34816;                      // + pb*17408

    for (int i=tid;i<128*128;i+=384){
        int k=i>>7, n=i&127;
        *reinterpret_cast<__nv_bfloat16*>(sm+OFF_W1B+k*272+n*2) = __float2bfloat16(W1[(128+k)*128+n]);
        *reinterpret_cast<__nv_bfloat16*>(sm+OFF_W2 +k*272+n*2) = __float2bfloat16(W2[k*128+n]);
    }
    if (tid<128) b2s[tid]=b2[tid];
    __syncthreads();

    float b2x[4],b2y[4];
#pragma unroll
    for (int j=0;j<4;++j){
        int c = wn*32 + j*8 + 2*(lane&3);
        b2x[j]=b2s[c]; b2y[j]=b2s[c+1];
    }

    const uint32_t a_off   = (uint32_t)((lane&15)*272 + (lane>>4)*16);
    const uint32_t w1_base = smb + OFF_W1B + (uint32_t)((lane&15)*272 + (wn*32 + (lane>>4)*8)*2);
    const uint32_t w2_base = smb + OFF_W2  + (uint32_t)((lane&15)*272 + (wn*32 + (lane>>4)*8)*2);

    float acc[4][4][4];
    int pb=0, mp=0;
    const int t0 = blockIdx.x*3+wg;
    const int prow = wg_tid>>1, phalf = wg_tid&1;   // prefetch row/half split

    // ---- prologue: fetch tile t0 ----
    if (t0 < N_TILES){
        if (wg_tid<64) msk[wg_tid] = mAtt[t0*ROWS_T + wg_tid];
        const int ge = t0*ROWS_T + prow;
        const int node = ge / Kc;
        const int nb = eidx[ge];
        const char* se = reinterpret_cast<const char*>(g_hEb) + (size_t)ge*256 + phalf*128;
        uint32_t dE = smb + (uint32_t)(bufo + prow*272 + phalf*128);
#pragma unroll
        for (int q=0;q<8;++q) cpasync16(dE+q*16, se+q*16);
        const char* sp = reinterpret_cast<const char*>(g_P) + ((size_t)((node>>11)<<11) + nb)*256 + phalf*128;
        uint32_t dP = smb + (uint32_t)(bufo + 17408 + prow*272 + phalf*128);
#pragma unroll
        for (int q=0;q<8;++q) cpasync16(dP+q*16, sp+q*16);
        CP_COMMIT();
        CP_WAIT0();
    }
    BAR_WG(wg+1);

    for (int t = t0; t < N_TILES; t += N_STREAMS){
        const int ge_base = t*ROWS_T;
        const bool hn = (t+N_STREAMS) < N_TILES;
        const int aofft = bufo + pb*17408;          // A / M1 buffer
        const int pofft = bufo + (pb^1)*17408;      // P buffer
        const uint32_t a_base = smb + (uint32_t)aofft + a_off;

#pragma unroll
        for (int s=0;s<4;++s)
#pragma unroll
            for (int j=0;j<4;++j)
#pragma unroll
                for (int c=0;c<4;++c) acc[s][j][c]=0.f;

        // ---- GEMM1': hE x W1b (K=128) ----
#pragma unroll
        for (int k=0;k<8;++k){
            uint32_t A[4][4], B[2][4];
#pragma unroll
            for (int s=0;s<4;++s) ldsm4(A[s], a_base + (uint32_t)(s*16*272 + k*32));
#pragma unroll
            for (int j2=0;j2<2;++j2) ldsm4t(B[j2], w1_base + (uint32_t)(k*16*272 + j2*32));
#pragma unroll
            for (int s=0;s<4;++s)
#pragma unroll
                for (int j2=0;j2<2;++j2){
                    mma16816(acc[s][2*j2],   A[s], B[j2]);
                    mma16816(acc[s][2*j2+1], A[s], B[j2]+2);
                }
        }
        BAR_WG(wg+1);   // all wg warps done reading A before M1 overwrite

        // ---- epi1: M1 = gelu(acc + P) -> A buffer ----
#pragma unroll
        for (int s=0;s<4;++s){
            int r0 = s*16 + (lane>>2);
#pragma unroll
            for (int j=0;j<4;++j){
                int col = wn*32 + j*8 + 2*(lane&3);
                __nv_bfloat162 pa = *reinterpret_cast<__nv_bfloat162*>(sm + pofft + r0*272 + col*2);
                __nv_bfloat162 pc = *reinterpret_cast<__nv_bfloat162*>(sm + pofft + (r0+8)*272 + col*2);
                float x0=gelu_fast(acc[s][j][0]+__bfloat162float(pa.x));
                float x1=gelu_fast(acc[s][j][1]+__bfloat162float(pa.y));
                float x2=gelu_fast(acc[s][j][2]+__bfloat162float(pc.x));
                float x3=gelu_fast(acc[s][j][3]+__bfloat162float(pc.y));
                __nv_bfloat162 p0=__floats2bfloat162_rn(x0,x1), p1=__floats2bfloat162_rn(x2,x3);
                *reinterpret_cast<uint32_t*>(sm + aofft + r0*272 + col*2)     = *reinterpret_cast<uint32_t*>(&p0);
                *reinterpret_cast<uint32_t*>(sm + aofft + (r0+8)*272 + col*2) = *reinterpret_cast<uint32_t*>(&p1);
            }
        }
#pragma unroll
        for (int s=0;s<4;++s)
#pragma unroll
            for (int j=0;j<4;++j)
#pragma unroll
                for (int c=0;c<4;++c) acc[s][j][c]=0.f;
        BAR_WG(wg+1);   // M1 visible; P buffer free

        // ---- prefetch next tile's hE into freed P buffer ----
        int node_n=0, nb_n=0;
        if (hn){
            const int tn = t+N_STREAMS;
            if (wg_tid<64) msk[(mp^1)*64 + wg_tid] = mAtt[tn*ROWS_T + wg_tid];
            const int ge_n = tn*ROWS_T + prow;
            node_n = ge_n / Kc;
            nb_n = eidx[ge_n];
            const char* se = reinterpret_cast<const char*>(g_hEb) + (size_t)ge_n*256 + phalf*128;
            uint32_t dE = smb + (uint32_t)(pofft + prow*272 + phalf*128);
#pragma unroll
            for (int q=0;q<8;++q) cpasync16(dE+q*16, se+q*16);
            CP_COMMIT();
        }

        // ---- GEMM2: M1 (K=128) x W2 ----
#pragma unroll
        for (int k=0;k<8;++k){
            uint32_t A[4][4], B[2][4];
#pragma unroll
            for (int s=0;s<4;++s) ldsm4(A[s], a_base + (uint32_t)(s*16*272 + k*32));
#pragma unroll
            for (int j2=0;j2<2;++j2) ldsm4t(B[j2], w2_base + (uint32_t)(k*16*272 + j2*32));
#pragma unroll
            for (int s=0;s<4;++s)
#pragma unroll
                for (int j2=0;j2<2;++j2){
                    mma16816(acc[s][2*j2],   A[s], B[j2]);
                    mma16816(acc[s][2*j2+1], A[s], B[j2]+2);
                }
        }
        BAR_WG(wg+1);   // all wg warps done with M1 buffer

        // ---- prefetch next tile's P into freed M1 buffer ----
        if (hn){
            const char* sp = reinterpret_cast<const char*>(g_P) + ((size_t)((node_n>>11)<<11) + nb_n)*256 + phalf*128;
            uint32_t dP = smb + (uint32_t)(aofft + prow*272 + phalf*128);
#pragma unroll
            for (int q=0;q<8;++q) cpasync16(dP+q*16, sp+q*16);
            CP_COMMIT();
        }

        // ---- epi2: gelu(acc+b2)*mask, 16-row column sums -> g_s2 ----
#pragma unroll
        for (int s=0;s<4;++s){
            const int node = (ge_base + s*16)/Kc;
            const float mka = msk[mp*64 + s*16 + (lane>>2)];
            const float mkb = msk[mp*64 + s*16 + (lane>>2) + 8];
#pragma unroll
            for (int j=0;j<4;++j){
                float v0 = gelu_fast(acc[s][j][0]+b2x[j])*mka;
                float v1 = gelu_fast(acc[s][j][1]+b2y[j])*mka;
                float v2 = gelu_fast(acc[s][j][2]+b2x[j])*mkb;
                float v3 = gelu_fast(acc[s][j][3]+b2y[j])*mkb;
                float s0 = v0+v2, s1 = v1+v3;
                s0 += __shfl_xor_sync(0xffffffffu,s0,4);
                s0 += __shfl_xor_sync(0xffffffffu,s0,8);
                s0 += __shfl_xor_sync(0xffffffffu,s0,16);
                s1 += __shfl_xor_sync(0xffffffffu,s1,4);
                s1 += __shfl_xor_sync(0xffffffffu,s1,8);
                s1 += __shfl_xor_sync(0xffffffffu,s1,16);
                if (lane<4){
                    int col = wn*32 + j*8 + 2*lane;
                    atomicAdd(&g_s2[(size_t)node*Hc + col],   s0);
                    atomicAdd(&g_s2[(size_t)node*Hc + col+1], s1);
                }
            }
        }

        CP_WAIT0();
        BAR_WG(wg+1);
        pb ^= 1; mp ^= 1;
    }
}

// ---------------- fused node kernel (unchanged from R7) ----------------
constexpr int NOFF_S2HI = 0;
constexpr int NOFF_S2LO = 17408;
constexpr int NOFF_HHI  = 34816;
constexpr int NOFF_HLO  = 52224;
constexpr int NOFF_W    = 69632;
constexpr int NOFF_B3   = 208896;
constexpr int NOFF_BIN  = 209408;
constexpr int NOFF_BOUT = 211456;
constexpr int NOFF_MV   = 211968;
constexpr int NOFF_CNT  = 212224;
constexpr int NODE_SMEM = 212480;

__global__ __launch_bounds__(256,1)
void node_kernel(const float* __restrict__ hV, const float* __restrict__ maskV,
                 const float* __restrict__ b3, const float* __restrict__ b_in,
                 const float* __restrict__ b_out, float* __restrict__ out){
    extern __shared__ __align__(16) char sm[];
    const int tid=threadIdx.x, wid=tid>>5, lane=tid&31;
    const int wm=wid&1, wn=wid>>1;
    const int rowbase = blockIdx.x*64;
    const uint32_t smb=smem_u32(sm);
    float* b3s  = reinterpret_cast<float*>(sm+NOFF_B3);
    float* bins = reinterpret_cast<float*>(sm+NOFF_BIN);
    float* bouts= reinterpret_cast<float*>(sm+NOFF_BOUT);
    float* mvs  = reinterpret_cast<float*>(sm+NOFF_MV);
    float* cnts = reinterpret_cast<float*>(sm+NOFF_CNT);

    if (tid<128) b3s[tid]=b3[tid];
    for (int i=tid;i<FFc;i+=256) bins[i]=b_in[i];
    if (tid>=128 && tid<256) bouts[tid-128]=b_out[tid-128];
    if (tid<64){ mvs[tid]=maskV[rowbase+tid]; cnts[tid]=g_cnt[rowbase+tid]; }

    for (int e=tid;e<64*32;e+=256){
        int r=e>>5, q=e&31;
        float4 v = reinterpret_cast<const float4*>(g_s2 + (size_t)(rowbase+r)*Hc)[q];
        __nv_bfloat16 hx=__float2bfloat16(v.x),hy=__float2bfloat16(v.y),
                      hz=__float2bfloat16(v.z),hw=__float2bfloat16(v.w);
        __nv_bfloat162 ph0=__halves2bfloat162(hx,hy), ph1=__halves2bfloat162(hz,hw);
        __nv_bfloat162 pl0=__floats2bfloat162_rn(v.x-__bfloat162float(hx),v.y-__bfloat162float(hy));
        __nv_bfloat162 pl1=__floats2bfloat162_rn(v.z-__bfloat162float(hz),v.w-__bfloat162float(hw));
        uint2 uh; uh.x=*reinterpret_cast<uint32_t*>(&ph0); uh.y=*reinterpret_cast<uint32_t*>(&ph1);
        uint2 ul; ul.x=*reinterpret_cast<uint32_t*>(&pl0); ul.y=*reinterpret_cast<uint32_t*>(&pl1);
        *reinterpret_cast<uint2*>(sm + NOFF_S2HI + r*272 + q*8) = uh;
        *reinterpret_cast<uint2*>(sm + NOFF_S2LO + r*272 + q*8) = ul;
    }
    for (int i=tid;i<128*16;i+=256){
        int r=i>>4, q=i&15;
        *reinterpret_cast<uint4*>(sm+NOFF_W+r*272+q*16)       = *reinterpret_cast<const uint4*>(g_W3hi + r*Hc + q*8);
        *reinterpret_cast<uint4*>(sm+NOFF_W+34816+r*272+q*16) = *reinterpret_cast<const uint4*>(g_W3lo + r*Hc + q*8);
    }
    __syncthreads();

    const uint32_t a_row = (uint32_t)((wm*32 + (lane&15))*272 + (lane>>4)*16);
    const uint32_t b_row = (uint32_t)((lane&15)*272 + (wn*32 + (lane>>4)*8)*2);

    auto gemm3 = [&](float acc[2][4][4], uint32_t ahi, uint32_t alo, uint32_t bhi, uint32_t blo){
#pragma unroll
        for (int k=0;k<8;++k){
            uint32_t Ah[2][4], Al[2][4], Bh[2][4], Bl[2][4];
#pragma unroll
            for (int s=0;s<2;++s){
                ldsm4(Ah[s], ahi + (uint32_t)(s*16*272 + k*32));
                ldsm4(Al[s], alo + (uint32_t)(s*16*272 + k*32));
            }
#pragma unroll
            for (int j2=0;j2<2;++j2){
                ldsm4t(Bh[j2], bhi + (uint32_t)(k*16*272 + j2*32));
                ldsm4t(Bl[j2], blo + (uint32_t)(k*16*272 + j2*32));
            }
#pragma unroll
            for (int s=0;s<2;++s)
#pragma unroll
                for (int j2=0;j2<2;++j2){
                    mma16816(acc[s][2*j2],   Ah[s], Bh[j2]);
                    mma16816(acc[s][2*j2+1], Ah[s], Bh[j2]+2);
                    mma16816(acc[s][2*j2],   Ah[s], Bl[j2]);
                    mma16816(acc[s][2*j2+1], Ah[s], Bl[j2]+2);
                    mma16816(acc[s][2*j2],   Al[s], Bh[j2]);
                    mma16816(acc[s][2*j2+1], Al[s], Bh[j2]+2);
                }
        }
    };

    {
        float acc[2][4][4];
#pragma unroll
        for (int s=0;s<2;++s)
#pragma unroll
            for (int j=0;j<4;++j)
#pragma unroll
                for (int c=0;c<4;++c) acc[s][j][c]=0.f;
        gemm3(acc, smb+NOFF_S2HI+a_row, smb+NOFF_S2LO+a_row,
                   smb+NOFF_W+b_row,    smb+NOFF_W+34816+b_row);
#pragma unroll
        for (int s=0;s<2;++s){
            int r0 = wm*32 + s*16 + (lane>>2);
#pragma unroll
            for (int j=0;j<4;++j){
                int c = wn*32 + j*8 + 2*(lane&3);
#pragma unroll
                for (int half=0; half<2; ++half){
                    int r = r0 + half*8;
                    size_t gi = (size_t)(rowbase+r)*Hc + c;
                    float h0 = hV[gi]   + (acc[s][j][2*half]   + cnts[r]*b3s[c])  *INV_SCALE;
                    float h1 = hV[gi+1] + (acc[s][j][2*half+1] + cnts[r]*b3s[c+1])*INV_SCALE;
                    __nv_bfloat16 x0=__float2bfloat16(h0), x1=__float2bfloat16(h1);
                    __nv_bfloat162 ph=__halves2bfloat162(x0,x1);
                    __nv_bfloat162 pl=__floats2bfloat162_rn(h0-__bfloat162float(x0),h1-__bfloat162float(x1));
                    *reinterpret_cast<uint32_t*>(sm+NOFF_HHI+r*272+c*2)=*reinterpret_cast<uint32_t*>(&ph);
                    *reinterpret_cast<uint32_t*>(sm+NOFF_HLO+r*272+c*2)=*reinterpret_cast<uint32_t*>(&pl);
                }
            }
        }
    }

    float accO[2][4][4];
#pragma unroll
    for (int s=0;s<2;++s)
#pragma unroll
        for (int j=0;j<4;++j)
#pragma unroll
            for (int c=0;c<4;++c) accO[s][j][c]=0.f;

    for (int cc=0;cc<4;++cc){
        __syncthreads();
        for (int i=tid;i<128*16;i+=256){
            int r=i>>4, q=i&15;
            *reinterpret_cast<uint4*>(sm+NOFF_W+r*272+q*16)        = *reinterpret_cast<const uint4*>(g_WinHi + r*FFc + cc*128 + q*8);
            *reinterpret_cast<uint4*>(sm+NOFF_W+34816+r*272+q*16)  = *reinterpret_cast<const uint4*>(g_WinLo + r*FFc + cc*128 + q*8);
            *reinterpret_cast<uint4*>(sm+NOFF_W+69632+r*272+q*16)  = *reinterpret_cast<const uint4*>(g_WoutHi + (size_t)(cc*128+r)*Hc + q*8);
            *reinterpret_cast<uint4*>(sm+NOFF_W+104448+r*272+q*16) = *reinterpret_cast<const uint4*>(g_WoutLo + (size_t)(cc*128+r)*Hc + q*8);
        }
        __syncthreads();

        float accM[2][4][4];
#pragma unroll
        for (int s=0;s<2;++s)
#pragma unroll
            for (int j=0;j<4;++j)
#pragma unroll
                for (int c=0;c<4;++c) accM[s][j][c]=0.f;
        gemm3(accM, smb+NOFF_HHI+a_row, smb+NOFF_HLO+a_row,
                    smb+NOFF_W+b_row,   smb+NOFF_W+34816+b_row);
#pragma unroll
        for (int s=0;s<2;++s){
            int r0 = wm*32 + s*16 + (lane>>2);
#pragma unroll
            for (int j=0;j<4;++j){
                int c = wn*32 + j*8 + 2*(lane&3);
#pragma unroll
                for (int half=0; half<2; ++half){
                    int r = r0 + half*8;
                    float v0 = gelu_erf_f(accM[s][j][2*half]   + bins[cc*128+c]);
                    float v1 = gelu_erf_f(accM[s][j][2*half+1] + bins[cc*128+c+1]);
                    __nv_bfloat16 x0=__float2bfloat16(v0), x1=__float2bfloat16(v1);
                    __nv_bfloat162 ph=__halves2bfloat162(x0,x1);
                    __nv_bfloat162 pl=__floats2bfloat162_rn(v0-__bfloat162float(x0),v1-__bfloat162float(x1));
                    *reinterpret_cast<uint32_t*>(sm+NOFF_S2HI+r*272+c*2)=*reinterpret_cast<uint32_t*>(&ph);
                    *reinterpret_cast<uint32_t*>(sm+NOFF_S2LO+r*272+c*2)=*reinterpret_cast<uint32_t*>(&pl);
                }
            }
        }
        __syncthreads();

        gemm3(accO, smb+NOFF_S2HI+a_row, smb+NOFF_S2LO+a_row,
                    smb+NOFF_W+69632+b_row, smb+NOFF_W+104448+b_row);
    }

#pragma unroll
    for (int s=0;s<2;++s){
        int r0 = wm*32 + s*16 + (lane>>2);
#pragma unroll
        for (int j=0;j<4;++j){
            int c = wn*32 + j*8 + 2*(lane&3);
#pragma unroll
            for (int half=0; half<2; ++half){
                int r = r0 + half*8;
                size_t gi = (size_t)(rowbase+r)*Hc + c;
                __nv_bfloat162 hh = *reinterpret_cast<__nv_bfloat162*>(sm+NOFF_HHI+r*272+c*2);
                __nv_bfloat162 hl = *reinterpret_cast<__nv_bfloat162*>(sm+NOFF_HLO+r*272+c*2);
                float h0 = __bfloat162float(hh.x)+__bfloat162float(hl.x);
                float h1 = __bfloat162float(hh.y)+__bfloat162float(hl.y);
                float mv = mvs[r];
                out[gi]   = (h0 + accO[s][j][2*half]   + bouts[c])  * mv;
                out[gi+1] = (h1 + accO[s][j][2*half+1] + bouts[c+1])* mv;
            }
        }
    }
}

// ---------------- launch ----------------
extern "C" void kernel_launch(void* const* d_in, const int* in_sizes, int n_in,
                              void* d_out, int out_size){
    (void)in_sizes; (void)n_in; (void)out_size;
    const float* hV   =(const float*)d_in[0];
    const float* hE   =(const float*)d_in[1];
    const int*   eidx =(const int*)d_in[2];
    const float* maskV=(const float*)d_in[3];
    const float* mAtt =(const float*)d_in[4];
    const float* W1   =(const float*)d_in[5];
    const float* b1   =(const float*)d_in[6];
    const float* W2   =(const float*)d_in[7];
    const float* b2   =(const float*)d_in[8];
    const float* W3   =(const float*)d_in[9];
    const float* b3   =(const float*)d_in[10];
    const float* Win  =(const float*)d_in[11];
    const float* binp =(const float*)d_in[12];
    const float* Wout =(const float*)d_in[13];
    const float* boutp=(const float*)d_in[14];
    float* out=(float*)d_out;

    cudaFuncSetAttribute(pre1_kernel, cudaFuncAttributeMaxDynamicSharedMemorySize, P1_SMEM);
    cudaFuncSetAttribute(edge_mlp_mma, cudaFuncAttributeMaxDynamicSharedMemorySize, EDGE_SMEM);
    cudaFuncSetAttribute(node_kernel, cudaFuncAttributeMaxDynamicSharedMemorySize, NODE_SMEM);

    prep_kernel<<<128, 512>>>(W3, Win, Wout);
    cvt_hE_kernel<<<EDGE_ROWS*Hc/4096, 1024>>>(hE);
    pre1_kernel<<<NODES/64, 256, P1_SMEM>>>(hV, W1, b1, mAtt);
    edge_mlp_mma<<<148, 384, EDGE_SMEM>>>(eidx, mAtt, W1, b2, W2);
    node_kernel<<<NODES/64, 256, NODE_SMEM>>>(hV, maskV, b3, binp, boutp, out);
}

// round 9
// speedup vs baseline: 3.1980x; 1.1333x over previous
#include <cuda_runtime.h>
#include <cuda_bf16.h>
#include <cstdint>

constexpr int Bc=4, Nn=2048, Kc=48, Hc=128, FFc=512;
constexpr int NODES = Bc*Nn;                 // 8192
constexpr int EDGE_ROWS = NODES*Kc;          // 393216
constexpr int ROWS_T = 64;                   // edge tile rows (per warpgroup)
constexpr int N_TILES = EDGE_ROWS/ROWS_T;    // 6144
constexpr int N_STREAMS = 148*4;             // 592
constexpr float INV_SCALE = 1.0f/30.0f;

__device__ __nv_bfloat16 g_W3hi[Hc*Hc], g_W3lo[Hc*Hc];
__device__ __nv_bfloat16 g_WinHi[Hc*FFc], g_WinLo[Hc*FFc];
__device__ __nv_bfloat16 g_WoutHi[FFc*Hc], g_WoutLo[FFc*Hc];
__device__ __nv_bfloat16 g_P[NODES*Hc];        // hV @ W1a + b1 (bf16)
__device__ __nv_bfloat16 g_hEb[EDGE_ROWS*Hc];  // hE pre-converted to bf16
__device__ float g_s2[NODES*Hc];
__device__ float g_cnt[NODES];

// ---------------- low-level helpers ----------------
__device__ __forceinline__ uint32_t smem_u32(const void* p){
    uint32_t a; asm("{ .reg .u64 t; cvta.to.shared.u64 t, %1; cvt.u32.u64 %0, t; }":"=r"(a):"l"(p)); return a;
}
__device__ __forceinline__ void ldsm4(uint32_t* r, uint32_t addr){
    asm volatile("ldmatrix.sync.aligned.m8n8.x4.shared.b16 {%0,%1,%2,%3},[%4];"
        :"=r"(r[0]),"=r"(r[1]),"=r"(r[2]),"=r"(r[3]):"r"(addr));
}
__device__ __forceinline__ void ldsm4t(uint32_t* r, uint32_t addr){
    asm volatile("ldmatrix.sync.aligned.m8n8.x4.trans.shared.b16 {%0,%1,%2,%3},[%4];"
        :"=r"(r[0]),"=r"(r[1]),"=r"(r[2]),"=r"(r[3]):"r"(addr));
}
__device__ __forceinline__ void mma16816(float* d, const uint32_t* a, const uint32_t* b){
    asm volatile("mma.sync.aligned.m16n8k16.row.col.f32.bf16.bf16.f32 "
        "{%0,%1,%2,%3},{%4,%5,%6,%7},{%8,%9},{%0,%1,%2,%3};"
        :"+f"(d[0]),"+f"(d[1]),"+f"(d[2]),"+f"(d[3])
        :"r"(a[0]),"r"(a[1]),"r"(a[2]),"r"(a[3]),"r"(b[0]),"r"(b[1]));
}
__device__ __forceinline__ void cpasync16(uint32_t dst, const void* src){
    asm volatile("cp.async.cg.shared.global [%0],[%1],16;"::"r"(dst),"l"(src):"memory");
}
#define CP_COMMIT() asm volatile("cp.async.commit_group;":::"memory")
#define CP_WAIT0()  asm volatile("cp.async.wait_group 0;":::"memory")
#define BAR_WG(id) asm volatile("bar.sync %0, %1;"::"r"((id)),"r"(128):"memory")

__device__ __forceinline__ float gelu_fast(float x){
    float t1 = x*x;
    float y  = x*__fmaf_rn(0.0356774081f, t1, 0.7978845608f);
    float t; asm("tanh.approx.f32 %0, %1;":"=f"(t):"f"(y));
    float h = 0.5f*x;
    return __fmaf_rn(h, t, h);
}
__device__ __forceinline__ float gelu_erf_f(float x){ return x*normcdff(x); }

// ---------------- fused setup kernel: pre1 (blocks 0-127) | prep (128-383) | cvt (384+) ----------------
constexpr int P1_A = 0;
constexpr int P1_W = 17408;
constexpr int P1_B = 52224;
constexpr int P1_SMEM = 52736;
constexpr int CVT_BLOCKS = (EDGE_ROWS*Hc/4)/1024;   // 12288
constexpr int SETUP_GRID = 384 + CVT_BLOCKS;

__global__ __launch_bounds__(256,1)
void setup_kernel(const float* __restrict__ hV, const float* __restrict__ hE,
                  const float* __restrict__ W1, const float* __restrict__ b1,
                  const float* __restrict__ W3, const float* __restrict__ Win,
                  const float* __restrict__ Wout, const float* __restrict__ mAtt){
    const int blk = blockIdx.x;
    const int tid = threadIdx.x;

    if (blk >= 384){
        // ---- cvt: hE fp32 -> bf16 (1024 float4 per block) ----
        size_t base = (size_t)(blk-384)*1024;
#pragma unroll
        for (int q=0;q<4;++q){
            size_t i = base + q*256 + tid;
            float4 v = reinterpret_cast<const float4*>(hE)[i];
            __nv_bfloat162 p0=__floats2bfloat162_rn(v.x,v.y), p1=__floats2bfloat162_rn(v.z,v.w);
            uint2 pk; pk.x=*reinterpret_cast<uint32_t*>(&p0); pk.y=*reinterpret_cast<uint32_t*>(&p1);
            reinterpret_cast<uint2*>(g_hEb)[i] = pk;
        }
        return;
    }
    if (blk >= 128){
        // ---- prep: split weights, zero s2 ----
        int i = (blk-128)*256 + tid;   // 0..65535
        if (i < Hc*FFc){
            float v=Win[i]; __nv_bfloat16 h=__float2bfloat16(v);
            g_WinHi[i]=h; g_WinLo[i]=__float2bfloat16(v-__bfloat162float(h));
            v=Wout[i]; h=__float2bfloat16(v);
            g_WoutHi[i]=h; g_WoutLo[i]=__float2bfloat16(v-__bfloat162float(h));
        }
        if (i < Hc*Hc){
            float v=W3[i]; __nv_bfloat16 h=__float2bfloat16(v);
            g_W3hi[i]=h; g_W3lo[i]=__float2bfloat16(v-__bfloat162float(h));
        }
        float4 z=make_float4(0.f,0.f,0.f,0.f);
        float4* s2=reinterpret_cast<float4*>(g_s2);
#pragma unroll
        for (int j=0;j<4;++j) s2[i*4+j]=z;
        return;
    }

    // ---- pre1: P = hV @ W1[0:128,:] + b1 (bf16), plus cnt ----
    extern __shared__ __align__(16) char sm[];
    const int wid=tid>>5, lane=tid&31;
    const int wm=wid&1, wn=wid>>1;
    const int rowbase = blk*64;
    const uint32_t smb=smem_u32(sm);
    float* b1s = reinterpret_cast<float*>(sm+P1_B);

    if (tid<128) b1s[tid]=b1[tid];
    if (tid<64){
        float s=0.f;
        const float* mrow = mAtt + (size_t)(rowbase+tid)*Kc;
#pragma unroll 12
        for (int k=0;k<Kc;++k) s+=mrow[k];
        g_cnt[rowbase+tid]=s;
    }
    for (int i=tid;i<128*128;i+=256){
        int k=i>>7, n=i&127;
        *reinterpret_cast<__nv_bfloat16*>(sm+P1_W+k*272+n*2) = __float2bfloat16(W1[k*128+n]);
    }
    for (int e=tid;e<64*32;e+=256){
        int r=e>>5, q=e&31;
        float4 v = reinterpret_cast<const float4*>(hV + (size_t)(rowbase+r)*Hc)[q];
        __nv_bfloat162 p0=__floats2bfloat162_rn(v.x,v.y), p1=__floats2bfloat162_rn(v.z,v.w);
        uint2 pk; pk.x=*reinterpret_cast<uint32_t*>(&p0); pk.y=*reinterpret_cast<uint32_t*>(&p1);
        *reinterpret_cast<uint2*>(sm + P1_A + r*272 + q*8) = pk;
    }
    __syncthreads();

    const uint32_t a_row = smb + P1_A + (uint32_t)((wm*32 + (lane&15))*272 + (lane>>4)*16);
    const uint32_t b_row = smb + P1_W + (uint32_t)((lane&15)*272 + (wn*32 + (lane>>4)*8)*2);

    float acc[2][4][4];
#pragma unroll
    for (int s=0;s<2;++s)
#pragma unroll
        for (int j=0;j<4;++j)
#pragma unroll
            for (int c=0;c<4;++c) acc[s][j][c]=0.f;
#pragma unroll
    for (int k=0;k<8;++k){
        uint32_t A[2][4], B[2][4];
#pragma unroll
        for (int s=0;s<2;++s) ldsm4(A[s], a_row + (uint32_t)(s*16*272 + k*32));
#pragma unroll
        for (int j2=0;j2<2;++j2) ldsm4t(B[j2], b_row + (uint32_t)(k*16*272 + j2*32));
#pragma unroll
        for (int s=0;s<2;++s)
#pragma unroll
            for (int j2=0;j2<2;++j2){
                mma16816(acc[s][2*j2],   A[s], B[j2]);
                mma16816(acc[s][2*j2+1], A[s], B[j2]+2);
            }
    }
#pragma unroll
    for (int s=0;s<2;++s){
        int r0 = wm*32 + s*16 + (lane>>2);
#pragma unroll
        for (int j=0;j<4;++j){
            int c = wn*32 + j*8 + 2*(lane&3);
#pragma unroll
            for (int half=0; half<2; ++half){
                int r = r0 + half*8;
                float v0 = acc[s][j][2*half]   + b1s[c];
                float v1 = acc[s][j][2*half+1] + b1s[c+1];
                __nv_bfloat162 p=__floats2bfloat162_rn(v0,v1);
                *reinterpret_cast<uint32_t*>(&g_P[(size_t)(rowbase+r)*Hc + c]) = *reinterpret_cast<uint32_t*>(&p);
            }
        }
    }
}

// ---------------- edge MLP: 4 warpgroups x 64-row tiles, cp.async ping-pong ----------------
constexpr int OFF_BUF = 0;          // 4 wg x 2 x 17408 = 139264
constexpr int OFF_W1B = 139264;     // 34816
constexpr int OFF_W2  = 174080;     // 34816
constexpr int OFF_B2  = 208896;     // 512
constexpr int OFF_MSK = 209408;     // 4 wg x 2 parity x 64 x 4 = 2048
constexpr int EDGE_SMEM = 211456;

__global__ __launch_bounds__(512,1)
void edge_mlp_mma(const int* __restrict__ eidx, const float* __restrict__ mAtt,
                  const float* __restrict__ W1, const float* __restrict__ b2,
                  const float* __restrict__ W2){
    extern __shared__ __align__(16) char sm[];
    const int tid=threadIdx.x, wid=tid>>5, lane=tid&31;
    const int wg=wid>>2, wn=wid&3;     // 4 WGs; warp tile M=64 x N=32
    const int wg_tid=tid&127;
    const uint32_t smb=smem_u32(sm);
    float* b2s=reinterpret_cast<float*>(sm+OFF_B2);
    float* msk=reinterpret_cast<float*>(sm+OFF_MSK+wg*512);   // [parity*64 + row]
    const int bufo = OFF_BUF + wg*34816;                      // + pb*17408

    for (int i=tid;i<128*128;i+=512){
        int k=i>>7, n=i&127;
        *reinterpret_cast<__nv_bfloat16*>(sm+OFF_W1B+k*272+n*2) = __float2bfloat16(W1[(128+k)*128+n]);
        *reinterpret_cast<__nv_bfloat16*>(sm+OFF_W2 +k*272+n*2) = __float2bfloat16(W2[k*128+n]);
    }
    if (tid<128) b2s[tid]=b2[tid];
    __syncthreads();

    const uint32_t a_off   = (uint32_t)((lane&15)*272 + (lane>>4)*16);
    const uint32_t w1_base = smb + OFF_W1B + (uint32_t)((lane&15)*272 + (wn*32 + (lane>>4)*8)*2);
    const uint32_t w2_base = smb + OFF_W2  + (uint32_t)((lane&15)*272 + (wn*32 + (lane>>4)*8)*2);

    float acc[4][4][4];
    int pb=0, mp=0;
    const int t0 = blockIdx.x*4+wg;
    const int prow = wg_tid>>1, phalf = wg_tid&1;   // prefetch row/half split

    // ---- prologue: fetch tile t0 ----
    if (t0 < N_TILES){
        if (wg_tid<64) msk[wg_tid] = mAtt[t0*ROWS_T + wg_tid];
        const int ge = t0*ROWS_T + prow;
        const int node = ge / Kc;
        const int nb = eidx[ge];
        const char* se = reinterpret_cast<const char*>(g_hEb) + (size_t)ge*256 + phalf*128;
        uint32_t dE = smb + (uint32_t)(bufo + prow*272 + phalf*128);
#pragma unroll
        for (int q=0;q<8;++q) cpasync16(dE+q*16, se+q*16);
        const char* sp = reinterpret_cast<const char*>(g_P) + ((size_t)((node>>11)<<11) + nb)*256 + phalf*128;
        uint32_t dP = smb + (uint32_t)(bufo + 17408 + prow*272 + phalf*128);
#pragma unroll
        for (int q=0;q<8;++q) cpasync16(dP+q*16, sp+q*16);
        CP_COMMIT();
        CP_WAIT0();
    }
    BAR_WG(wg+1);

    for (int t = t0; t < N_TILES; t += N_STREAMS){
        const int ge_base = t*ROWS_T;
        const bool hn = (t+N_STREAMS) < N_TILES;
        const int aofft = bufo + pb*17408;          // A / M1 buffer
        const int pofft = bufo + (pb^1)*17408;      // P buffer
        const uint32_t a_base = smb + (uint32_t)aofft + a_off;

#pragma unroll
        for (int s=0;s<4;++s)
#pragma unroll
            for (int j=0;j<4;++j)
#pragma unroll
                for (int c=0;c<4;++c) acc[s][j][c]=0.f;

        // ---- GEMM1': hE x W1b (K=128) ----
#pragma unroll
        for (int k=0;k<8;++k){
            uint32_t A[4][4], B[2][4];
#pragma unroll
            for (int s=0;s<4;++s) ldsm4(A[s], a_base + (uint32_t)(s*16*272 + k*32));
#pragma unroll
            for (int j2=0;j2<2;++j2) ldsm4t(B[j2], w1_base + (uint32_t)(k*16*272 + j2*32));
#pragma unroll
            for (int s=0;s<4;++s)
#pragma unroll
                for (int j2=0;j2<2;++j2){
                    mma16816(acc[s][2*j2],   A[s], B[j2]);
                    mma16816(acc[s][2*j2+1], A[s], B[j2]+2);
                }
        }
        BAR_WG(wg+1);   // all wg warps done reading A before M1 overwrite

        // ---- epi1: M1 = gelu(acc + P) -> A buffer ----
#pragma unroll
        for (int s=0;s<4;++s){
            int r0 = s*16 + (lane>>2);
#pragma unroll
            for (int j=0;j<4;++j){
                int col = wn*32 + j*8 + 2*(lane&3);
                __nv_bfloat162 pa = *reinterpret_cast<__nv_bfloat162*>(sm + pofft + r0*272 + col*2);
                __nv_bfloat162 pc = *reinterpret_cast<__nv_bfloat162*>(sm + pofft + (r0+8)*272 + col*2);
                float x0=gelu_fast(acc[s][j][0]+__bfloat162float(pa.x));
                float x1=gelu_fast(acc[s][j][1]+__bfloat162float(pa.y));
                float x2=gelu_fast(acc[s][j][2]+__bfloat162float(pc.x));
                float x3=gelu_fast(acc[s][j][3]+__bfloat162float(pc.y));
                __nv_bfloat162 p0=__floats2bfloat162_rn(x0,x1), p1=__floats2bfloat162_rn(x2,x3);
                *reinterpret_cast<uint32_t*>(sm + aofft + r0*272 + col*2)     = *reinterpret_cast<uint32_t*>(&p0);
                *reinterpret_cast<uint32_t*>(sm + aofft + (r0+8)*272 + col*2) = *reinterpret_cast<uint32_t*>(&p1);
            }
        }
#pragma unroll
        for (int s=0;s<4;++s)
#pragma unroll
            for (int j=0;j<4;++j)
#pragma unroll
                for (int c=0;c<4;++c) acc[s][j][c]=0.f;
        BAR_WG(wg+1);   // M1 visible; P buffer free

        // ---- prefetch next tile's hE into freed P buffer ----
        int node_n=0, nb_n=0;
        if (hn){
            const int tn = t+N_STREAMS;
            if (wg_tid<64) msk[(mp^1)*64 + wg_tid] = mAtt[tn*ROWS_T + wg_tid];
            const int ge_n = tn*ROWS_T + prow;
            node_n = ge_n / Kc;
            nb_n = eidx[ge_n];
            const char* se = reinterpret_cast<const char*>(g_hEb) + (size_t)ge_n*256 + phalf*128;
            uint32_t dE = smb + (uint32_t)(pofft + prow*272 + phalf*128);
#pragma unroll
            for (int q=0;q<8;++q) cpasync16(dE+q*16, se+q*16);
            CP_COMMIT();
        }

        // ---- GEMM2: M1 (K=128) x W2 ----
#pragma unroll
        for (int k=0;k<8;++k){
            uint32_t A[4][4], B[2][4];
#pragma unroll
            for (int s=0;s<4;++s) ldsm4(A[s], a_base + (uint32_t)(s*16*272 + k*32));
#pragma unroll
            for (int j2=0;j2<2;++j2) ldsm4t(B[j2], w2_base + (uint32_t)(k*16*272 + j2*32));
#pragma unroll
            for (int s=0;s<4;++s)
#pragma unroll
                for (int j2=0;j2<2;++j2){
                    mma16816(acc[s][2*j2],   A[s], B[j2]);
                    mma16816(acc[s][2*j2+1], A[s], B[j2]+2);
                }
        }
        BAR_WG(wg+1);   // all wg warps done with M1 buffer

        // ---- prefetch next tile's P into freed M1 buffer ----
        if (hn){
            const char* sp = reinterpret_cast<const char*>(g_P) + ((size_t)((node_n>>11)<<11) + nb_n)*256 + phalf*128;
            uint32_t dP = smb + (uint32_t)(aofft + prow*272 + phalf*128);
#pragma unroll
            for (int q=0;q<8;++q) cpasync16(dP+q*16, sp+q*16);
            CP_COMMIT();
        }

        // ---- epi2: gelu(acc+b2)*mask, 16-row column sums -> g_s2 ----
#pragma unroll
        for (int s=0;s<4;++s){
            const int node = (ge_base + s*16)/Kc;
            const float mka = msk[mp*64 + s*16 + (lane>>2)];
            const float mkb = msk[mp*64 + s*16 + (lane>>2) + 8];
#pragma unroll
            for (int j=0;j<4;++j){
                int c = wn*32 + j*8 + 2*(lane&3);
                float2 bb = *reinterpret_cast<float2*>(&b2s[c]);
                float v0 = gelu_fast(acc[s][j][0]+bb.x)*mka;
                float v1 = gelu_fast(acc[s][j][1]+bb.y)*mka;
                float v2 = gelu_fast(acc[s][j][2]+bb.x)*mkb;
                float v3 = gelu_fast(acc[s][j][3]+bb.y)*mkb;
                float s0 = v0+v2, s1 = v1+v3;
                s0 += __shfl_xor_sync(0xffffffffu,s0,4);
                s0 += __shfl_xor_sync(0xffffffffu,s0,8);
                s0 += __shfl_xor_sync(0xffffffffu,s0,16);
                s1 += __shfl_xor_sync(0xffffffffu,s1,4);
                s1 += __shfl_xor_sync(0xffffffffu,s1,8);
                s1 += __shfl_xor_sync(0xffffffffu,s1,16);
                if (lane<4){
                    int col = wn*32 + j*8 + 2*lane;
                    atomicAdd(&g_s2[(size_t)node*Hc + col],   s0);
                    atomicAdd(&g_s2[(size_t)node*Hc + col+1], s1);
                }
            }
        }

        CP_WAIT0();
        BAR_WG(wg+1);
        pb ^= 1; mp ^= 1;
    }
}

// ---------------- fused node kernel (unchanged) ----------------
constexpr int NOFF_S2HI = 0;
constexpr int NOFF_S2LO = 17408;
constexpr int NOFF_HHI  = 34816;
constexpr int NOFF_HLO  = 52224;
constexpr int NOFF_W    = 69632;
constexpr int NOFF_B3   = 208896;
constexpr int NOFF_BIN  = 209408;
constexpr int NOFF_BOUT = 211456;
constexpr int NOFF_MV   = 211968;
constexpr int NOFF_CNT  = 212224;
constexpr int NODE_SMEM = 212480;

__global__ __launch_bounds__(256,1)
void node_kernel(const float* __restrict__ hV, const float* __restrict__ maskV,
                 const float* __restrict__ b3, const float* __restrict__ b_in,
                 const float* __restrict__ b_out, float* __restrict__ out){
    extern __shared__ __align__(16) char sm[];
    const int tid=threadIdx.x, wid=tid>>5, lane=tid&31;
    const int wm=wid&1, wn=wid>>1;
    const int rowbase = blockIdx.x*64;
    const uint32_t smb=smem_u32(sm);
    float* b3s  = reinterpret_cast<float*>(sm+NOFF_B3);
    float* bins = reinterpret_cast<float*>(sm+NOFF_BIN);
    float* bouts= reinterpret_cast<float*>(sm+NOFF_BOUT);
    float* mvs  = reinterpret_cast<float*>(sm+NOFF_MV);
    float* cnts = reinterpret_cast<float*>(sm+NOFF_CNT);

    if (tid<128) b3s[tid]=b3[tid];
    for (int i=tid;i<FFc;i+=256) bins[i]=b_in[i];
    if (tid>=128 && tid<256) bouts[tid-128]=b_out[tid-128];
    if (tid<64){ mvs[tid]=maskV[rowbase+tid]; cnts[tid]=g_cnt[rowbase+tid]; }

    for (int e=tid;e<64*32;e+=256){
        int r=e>>5, q=e&31;
        float4 v = reinterpret_cast<const float4*>(g_s2 + (size_t)(rowbase+r)*Hc)[q];
        __nv_bfloat16 hx=__float2bfloat16(v.x),hy=__float2bfloat16(v.y),
                      hz=__float2bfloat16(v.z),hw=__float2bfloat16(v.w);
        __nv_bfloat162 ph0=__halves2bfloat162(hx,hy), ph1=__halves2bfloat162(hz,hw);
        __nv_bfloat162 pl0=__floats2bfloat162_rn(v.x-__bfloat162float(hx),v.y-__bfloat162float(hy));
        __nv_bfloat162 pl1=__floats2bfloat162_rn(v.z-__bfloat162float(hz),v.w-__bfloat162float(hw));
        uint2 uh; uh.x=*reinterpret_cast<uint32_t*>(&ph0); uh.y=*reinterpret_cast<uint32_t*>(&ph1);
        uint2 ul; ul.x=*reinterpret_cast<uint32_t*>(&pl0); ul.y=*reinterpret_cast<uint32_t*>(&pl1);
        *reinterpret_cast<uint2*>(sm + NOFF_S2HI + r*272 + q*8) = uh;
        *reinterpret_cast<uint2*>(sm + NOFF_S2LO + r*272 + q*8) = ul;
    }
    for (int i=tid;i<128*16;i+=256){
        int r=i>>4, q=i&15;
        *reinterpret_cast<uint4*>(sm+NOFF_W+r*272+q*16)       = *reinterpret_cast<const uint4*>(g_W3hi + r*Hc + q*8);
        *reinterpret_cast<uint4*>(sm+NOFF_W+34816+r*272+q*16) = *reinterpret_cast<const uint4*>(g_W3lo + r*Hc + q*8);
    }
    __syncthreads();

    const uint32_t a_row = (uint32_t)((wm*32 + (lane&15))*272 + (lane>>4)*16);
    const uint32_t b_row = (uint32_t)((lane&15)*272 + (wn*32 + (lane>>4)*8)*2);

    auto gemm3 = [&](float acc[2][4][4], uint32_t ahi, uint32_t alo, uint32_t bhi, uint32_t blo){
#pragma unroll
        for (int k=0;k<8;++k){
            uint32_t Ah[2][4], Al[2][4], Bh[2][4], Bl[2][4];
#pragma unroll
            for (int s=0;s<2;++s){
                ldsm4(Ah[s], ahi + (uint32_t)(s*16*272 + k*32));
                ldsm4(Al[s], alo + (uint32_t)(s*16*272 + k*32));
            }
#pragma unroll
            for (int j2=0;j2<2;++j2){
                ldsm4t(Bh[j2], bhi + (uint32_t)(k*16*272 + j2*32));
                ldsm4t(Bl[j2], blo + (uint32_t)(k*16*272 + j2*32));
            }
#pragma unroll
            for (int s=0;s<2;++s)
#pragma unroll
                for (int j2=0;j2<2;++j2){
                    mma16816(acc[s][2*j2],   Ah[s], Bh[j2]);
                    mma16816(acc[s][2*j2+1], Ah[s], Bh[j2]+2);
                    mma16816(acc[s][2*j2],   Ah[s], Bl[j2]);
                    mma16816(acc[s][2*j2+1], Ah[s], Bl[j2]+2);
                    mma16816(acc[s][2*j2],   Al[s], Bh[j2]);
                    mma16816(acc[s][2*j2+1], Al[s], Bh[j2]+2);
                }
        }
    };

    {
        float acc[2][4][4];
#pragma unroll
        for (int s=0;s<2;++s)
#pragma unroll
            for (int j=0;j<4;++j)
#pragma unroll
                for (int c=0;c<4;++c) acc[s][j][c]=0.f;
        gemm3(acc, smb+NOFF_S2HI+a_row, smb+NOFF_S2LO+a_row,
                   smb+NOFF_W+b_row,    smb+NOFF_W+34816+b_row);
#pragma unroll
        for (int s=0;s<2;++s){
            int r0 = wm*32 + s*16 + (lane>>2);
#pragma unroll
            for (int j=0;j<4;++j){
                int c = wn*32 + j*8 + 2*(lane&3);
#pragma unroll
                for (int half=0; half<2; ++half){
                    int r = r0 + half*8;
                    size_t gi = (size_t)(rowbase+r)*Hc + c;
                    float h0 = hV[gi]   + (acc[s][j][2*half]   + cnts[r]*b3s[c])  *INV_SCALE;
                    float h1 = hV[gi+1] + (acc[s][j][2*half+1] + cnts[r]*b3s[c+1])*INV_SCALE;
                    __nv_bfloat16 x0=__float2bfloat16(h0), x1=__float2bfloat16(h1);
                    __nv_bfloat162 ph=__halves2bfloat162(x0,x1);
                    __nv_bfloat162 pl=__floats2bfloat162_rn(h0-__bfloat162float(x0),h1-__bfloat162float(x1));
                    *reinterpret_cast<uint32_t*>(sm+NOFF_HHI+r*272+c*2)=*reinterpret_cast<uint32_t*>(&ph);
                    *reinterpret_cast<uint32_t*>(sm+NOFF_HLO+r*272+c*2)=*reinterpret_cast<uint32_t*>(&pl);
                }
            }
        }
    }

    float accO[2][4][4];
#pragma unroll
    for (int s=0;s<2;++s)
#pragma unroll
        for (int j=0;j<4;++j)
#pragma unroll
            for (int c=0;c<4;++c) accO[s][j][c]=0.f;

    for (int cc=0;cc<4;++cc){
        __syncthreads();
        for (int i=tid;i<128*16;i+=256){
            int r=i>>4, q=i&15;
            *reinterpret_cast<uint4*>(sm+NOFF_W+r*272+q*16)        = *reinterpret_cast<const uint4*>(g_WinHi + r*FFc + cc*128 + q*8);
            *reinterpret_cast<uint4*>(sm+NOFF_W+34816+r*272+q*16)  = *reinterpret_cast<const uint4*>(g_WinLo + r*FFc + cc*128 + q*8);
            *reinterpret_cast<uint4*>(sm+NOFF_W+69632+r*272+q*16)  = *reinterpret_cast<const uint4*>(g_WoutHi + (size_t)(cc*128+r)*Hc + q*8);
            *reinterpret_cast<uint4*>(sm+NOFF_W+104448+r*272+q*16) = *reinterpret_cast<const uint4*>(g_WoutLo + (size_t)(cc*128+r)*Hc + q*8);
        }
        __syncthreads();

        float accM[2][4][4];
#pragma unroll
        for (int s=0;s<2;++s)
#pragma unroll
            for (int j=0;j<4;++j)
#pragma unroll
                for (int c=0;c<4;++c) accM[s][j][c]=0.f;
        gemm3(accM, smb+NOFF_HHI+a_row, smb+NOFF_HLO+a_row,
                    smb+NOFF_W+b_row,   smb+NOFF_W+34816+b_row);
#pragma unroll
        for (int s=0;s<2;++s){
            int r0 = wm*32 + s*16 + (lane>>2);
#pragma unroll
            for (int j=0;j<4;++j){
                int c = wn*32 + j*8 + 2*(lane&3);
#pragma unroll
                for (int half=0; half<2; ++half){
                    int r = r0 + half*8;
                    float v0 = gelu_erf_f(accM[s][j][2*half]   + bins[cc*128+c]);
                    float v1 = gelu_erf_f(accM[s][j][2*half+1] + bins[cc*128+c+1]);
                    __nv_bfloat16 x0=__float2bfloat16(v0), x1=__float2bfloat16(v1);
                    __nv_bfloat162 ph=__halves2bfloat162(x0,x1);
                    __nv_bfloat162 pl=__floats2bfloat162_rn(v0-__bfloat162float(x0),v1-__bfloat162float(x1));
                    *reinterpret_cast<uint32_t*>(sm+NOFF_S2HI+r*272+c*2)=*reinterpret_cast<uint32_t*>(&ph);
                    *reinterpret_cast<uint32_t*>(sm+NOFF_S2LO+r*272+c*2)=*reinterpret_cast<uint32_t*>(&pl);
                }
            }
        }
        __syncthreads();

        gemm3(accO, smb+NOFF_S2HI+a_row, smb+NOFF_S2LO+a_row,
                    smb+NOFF_W+69632+b_row, smb+NOFF_W+104448+b_row);
    }

#pragma unroll
    for (int s=0;s<2;++s){
        int r0 = wm*32 + s*16 + (lane>>2);
#pragma unroll
        for (int j=0;j<4;++j){
            int c = wn*32 + j*8 + 2*(lane&3);
#pragma unroll
            for (int half=0; half<2; ++half){
                int r = r0 + half*8;
                size_t gi = (size_t)(rowbase+r)*Hc + c;
                __nv_bfloat162 hh = *reinterpret_cast<__nv_bfloat162*>(sm+NOFF_HHI+r*272+c*2);
                __nv_bfloat162 hl = *reinterpret_cast<__nv_bfloat162*>(sm+NOFF_HLO+r*272+c*2);
                float h0 = __bfloat162float(hh.x)+__bfloat162float(hl.x);
                float h1 = __bfloat162float(hh.y)+__bfloat162float(hl.y);
                float mv = mvs[r];
                out[gi]   = (h0 + accO[s][j][2*half]   + bouts[c])  * mv;
                out[gi+1] = (h1 + accO[s][j][2*half+1] + bouts[c+1])* mv;
            }
        }
    }
}

// ---------------- launch ----------------
extern "C" void kernel_launch(void* const* d_in, const int* in_sizes, int n_in,
                              void* d_out, int out_size){
    (void)in_sizes; (void)n_in; (void)out_size;
    const float* hV   =(const float*)d_in[0];
    const float* hE   =(const float*)d_in[1];
    const int*   eidx =(const int*)d_in[2];
    const float* maskV=(const float*)d_in[3];
    const float* mAtt =(const float*)d_in[4];
    const float* W1   =(const float*)d_in[5];
    const float* b1   =(const float*)d_in[6];
    const float* W2   =(const float*)d_in[7];
    const float* b2   =(const float*)d_in[8];
    const float* W3   =(const float*)d_in[9];
    const float* b3   =(const float*)d_in[10];
    const float* Win  =(const float*)d_in[11];
    const float* binp =(const float*)d_in[12];
    const float* Wout =(const float*)d_in[13];
    const float* boutp=(const float*)d_in[14];
    float* out=(float*)d_out;

    cudaFuncSetAttribute(setup_kernel, cudaFuncAttributeMaxDynamicSharedMemorySize, P1_SMEM);
    cudaFuncSetAttribute(edge_mlp_mma, cudaFuncAttributeMaxDynamicSharedMemorySize, EDGE_SMEM);
    cudaFuncSetAttribute(node_kernel, cudaFuncAttributeMaxDynamicSharedMemorySize, NODE_SMEM);

    setup_kernel<<<SETUP_GRID, 256, P1_SMEM>>>(hV, hE, W1, b1, W3, Win, Wout, mAtt);
    edge_mlp_mma<<<148, 512, EDGE_SMEM>>>(eidx, mAtt, W1, b2, W2);
    node_kernel<<<NODES/64, 256, NODE_SMEM>>>(hV, maskV, b3, binp, boutp, out);
}